// round 2
// baseline (speedup 1.0000x reference)
#include <cuda_runtime.h>
#include <math.h>

// Problem dims
#define NB   2
#define TT   4096
#define NHD  16      // heads
#define DH   64      // head dim
#define HID  1024
#define SELC 64
#define TOPK 16
#define LOCC 128

// Scratch (device globals: allocation-free rule)
__device__ float g_q[(size_t)NB*NHD*TT*DH];
__device__ float g_k[(size_t)NB*NHD*TT*DH];
__device__ float g_v[(size_t)NB*NHD*TT*DH];
__device__ float g_ctxg[(size_t)NB*NHD*TT*DH];
__device__ float g_lseg[NB*NHD*TT];
__device__ float g_norm[NB*NHD*TT];
__device__ int   g_gidx[NB*NHD*1024];
__device__ int   g_lidx[NB*NHD*3072];

// ---------------------------------------------------------------------------
// SGEMM: out[n,h,t,d] = hidden[n*T+t, :] . W[h*64+d, :] + bias[h*64+d]
// M=8192, N=1024, K=1024. 128x128x16 tiles, 8x8 microtile, 256 threads.
// z selects (Wq,bq,g_q) / (Wk,bk,g_k) / (Wv,bv,g_v).
// ---------------------------------------------------------------------------
#define BM 128
#define BN 128
#define BK 16
#define TM 8
#define TN 8

__global__ __launch_bounds__(256) void qkv_gemm(
    const float* __restrict__ A,
    const float* __restrict__ Wq, const float* __restrict__ bq,
    const float* __restrict__ Wk, const float* __restrict__ bk,
    const float* __restrict__ Wv, const float* __restrict__ bv)
{
    const float* W; const float* bias; float* out;
    int z = blockIdx.z;
    if (z == 0)      { W = Wq; bias = bq; out = g_q; }
    else if (z == 1) { W = Wk; bias = bk; out = g_k; }
    else             { W = Wv; bias = bv; out = g_v; }

    __shared__ float As[BK][BM];
    __shared__ float Bs[BK][BN];

    int tid = threadIdx.x;
    int tx = tid & 15;       // 0..15 -> N
    int ty = tid >> 4;       // 0..15 -> M
    int row0 = blockIdx.y * BM;
    int col0 = blockIdx.x * BN;

    int lr = tid >> 2;           // 0..63
    int lc = (tid & 3) * 4;      // 0,4,8,12

    float acc[TM][TN];
    #pragma unroll
    for (int i = 0; i < TM; i++)
        #pragma unroll
        for (int j = 0; j < TN; j++) acc[i][j] = 0.f;

    for (int k0 = 0; k0 < 1024; k0 += BK) {
        #pragma unroll
        for (int p = 0; p < 2; p++) {
            int r = lr + p * 64;
            float4 va = *(const float4*)&A[(size_t)(row0 + r) * 1024 + k0 + lc];
            As[lc+0][r] = va.x; As[lc+1][r] = va.y;
            As[lc+2][r] = va.z; As[lc+3][r] = va.w;
        }
        #pragma unroll
        for (int p = 0; p < 2; p++) {
            int c = lr + p * 64;
            float4 vb = *(const float4*)&W[(size_t)(col0 + c) * 1024 + k0 + lc];
            Bs[lc+0][c] = vb.x; Bs[lc+1][c] = vb.y;
            Bs[lc+2][c] = vb.z; Bs[lc+3][c] = vb.w;
        }
        __syncthreads();
        #pragma unroll
        for (int kk = 0; kk < BK; kk++) {
            float4 a0 = *(const float4*)&As[kk][ty * TM];
            float4 a1 = *(const float4*)&As[kk][ty * TM + 4];
            float4 b0 = *(const float4*)&Bs[kk][tx * TN];
            float4 b1 = *(const float4*)&Bs[kk][tx * TN + 4];
            float af[TM] = {a0.x, a0.y, a0.z, a0.w, a1.x, a1.y, a1.z, a1.w};
            float bf[TN] = {b0.x, b0.y, b0.z, b0.w, b1.x, b1.y, b1.z, b1.w};
            #pragma unroll
            for (int i = 0; i < TM; i++)
                #pragma unroll
                for (int j = 0; j < TN; j++)
                    acc[i][j] += af[i] * bf[j];
        }
        __syncthreads();
    }

    #pragma unroll
    for (int i = 0; i < TM; i++) {
        int row = row0 + ty * TM + i;
        int nn = row >> 12, t = row & 4095;
        #pragma unroll
        for (int j = 0; j < TN; j++) {
            int col = col0 + tx * TN + j;
            int h = col >> 6, d = col & 63;
            out[(((size_t)(nn * NHD + h)) * TT + t) * DH + d] = acc[i][j] + bias[col];
        }
    }
}

// ---------------------------------------------------------------------------
// norms: ||k[n,h,t,:] + bq[h*64:]||^2 * (mask[n,t]==0)
// ---------------------------------------------------------------------------
__global__ void norm_kernel(const float* __restrict__ bq, const float* __restrict__ mask)
{
    int g = blockIdx.x * 256 + threadIdx.x;
    if (g >= NB * NHD * TT) return;
    int t = g & (TT - 1);
    int h = (g >> 12) & (NHD - 1);
    int n = g >> 16;
    const float* kp = &g_k[(size_t)g * DH];
    const float* bh = &bq[h * DH];
    float s = 0.f;
    #pragma unroll
    for (int d = 0; d < DH; d += 4) {
        float4 kv = *(const float4*)&kp[d];
        float x0 = kv.x + bh[d+0];
        float x1 = kv.y + bh[d+1];
        float x2 = kv.z + bh[d+2];
        float x3 = kv.w + bh[d+3];
        s += x0*x0 + x1*x1 + x2*x2 + x3*x3;
    }
    float valid = (mask[n * TT + t] == 0.0f) ? 1.0f : 0.0f;
    g_norm[g] = s * valid;
}

// ---------------------------------------------------------------------------
// selection: per (n,h, 64-token chunk): stable-ascending rank; top-16 -> gidx,
// bottom-48 -> lidx, both ordered by token index.
// ---------------------------------------------------------------------------
__global__ void select_kernel()
{
    int b  = blockIdx.x;     // (n*16+h)*64 + c
    int c  = b & 63;
    int nh = b >> 6;
    int i  = threadIdx.x;    // 0..63
    __shared__ float nrm[64];
    __shared__ int   sel[64];
    nrm[i] = g_norm[(size_t)nh * TT + c * SELC + i];
    __syncthreads();
    float mine = nrm[i];
    int rank = 0;
    #pragma unroll 8
    for (int j = 0; j < 64; j++) {
        float oj = nrm[j];
        rank += (oj < mine) || (oj == mine && j < i);
    }
    sel[i] = (rank >= SELC - TOPK) ? 1 : 0;
    __syncthreads();
    int gcnt = 0;
    for (int j = 0; j < i; j++) gcnt += sel[j];
    if (sel[i]) g_gidx[nh * 1024 + c * TOPK + gcnt] = c * SELC + i;
    else        g_lidx[nh * 3072 + c * (SELC - TOPK) + (i - gcnt)] = c * SELC + i;
}

// ---------------------------------------------------------------------------
// Global pass: 64-query blocks, window of up to 48 gathered keys (ck=16).
// Writes softmaxed ctx_g and lse_g.
// ---------------------------------------------------------------------------
__global__ __launch_bounds__(64) void attn_global(const float* __restrict__ mask)
{
    int qb = blockIdx.x;      // 0..63
    int h  = blockIdx.y, n = blockIdx.z;
    int nh = n * NHD + h;
    __shared__ float ks[48][DH];
    __shared__ float vs[48][DH];
    __shared__ float am[48];
    __shared__ float sc[48][DH];     // [slot][thread] score buffer
    int tid = threadIdx.x;           // 0..63 (= d for loads, = query for compute)

    for (int s = 0; s < 48; s++) {
        int gs = qb * 16 - 16 + s;
        if (gs >= 0 && gs < 1024) {
            int tok = g_gidx[nh * 1024 + gs];
            ks[s][tid] = g_k[((size_t)nh * TT + tok) * DH + tid];
            vs[s][tid] = g_v[((size_t)nh * TT + tok) * DH + tid];
            if (tid == 0) am[s] = mask[n * TT + tok];
        } else {
            ks[s][tid] = 0.f; vs[s][tid] = 0.f;
            if (tid == 0) am[s] = -1e30f;
        }
    }
    __syncthreads();

    int qt = qb * SELC + tid;
    float qreg[DH];
    const float* qp = &g_q[((size_t)nh * TT + qt) * DH];
    #pragma unroll
    for (int d = 0; d < DH; d++) qreg[d] = qp[d];

    float m = -1e30f;
    for (int s = 0; s < 48; s++) {
        float dot = 0.f;
        #pragma unroll
        for (int d = 0; d < DH; d += 4) {
            float4 kv = *(const float4*)&ks[s][d];
            dot += qreg[d]*kv.x + qreg[d+1]*kv.y + qreg[d+2]*kv.z + qreg[d+3]*kv.w;
        }
        float a = am[s];
        float v = (a > -1e29f) ? dot * 0.125f + a : -1e30f;
        sc[s][tid] = v;
        m = fmaxf(m, v);
    }

    float l = 0.f;
    float acc[DH];
    #pragma unroll
    for (int d = 0; d < DH; d++) acc[d] = 0.f;
    for (int s = 0; s < 48; s++) {
        float v = sc[s][tid];
        float p = (v > -1e29f) ? expf(v - m) : 0.f;
        l += p;
        #pragma unroll
        for (int d = 0; d < DH; d += 4) {
            float4 vv = *(const float4*)&vs[s][d];
            acc[d]   += p * vv.x; acc[d+1] += p * vv.y;
            acc[d+2] += p * vv.z; acc[d+3] += p * vv.w;
        }
    }
    float inv = 1.f / l;
    float* cg = &g_ctxg[((size_t)nh * TT + qt) * DH];
    #pragma unroll
    for (int d = 0; d < DH; d++) cg[d] = acc[d] * inv;
    g_lseg[nh * TT + qt] = m + logf(l);
}

// ---------------------------------------------------------------------------
// Local pass + merge: 128-query blocks, window of up to 288 gathered keys
// (ck=96) + global key (token 0, additive mask 0). Online softmax, then
// merges with (ctx_g, lse_g) and writes final output (n,t,hid).
// ---------------------------------------------------------------------------
__global__ __launch_bounds__(128) void attn_local(const float* __restrict__ mask,
                                                  float* __restrict__ out)
{
    int qb = blockIdx.x;      // 0..31
    int h  = blockIdx.y, n = blockIdx.z;
    int nh = n * NHD + h;
    __shared__ float ks[32][DH];
    __shared__ float vs[32][DH];
    __shared__ float am[32];
    __shared__ int   toks[32];
    __shared__ float sc[32][128];    // [slot][thread]

    int tid = threadIdx.x;
    int qt = qb * LOCC + tid;
    float qreg[DH];
    const float* qp = &g_q[((size_t)nh * TT + qt) * DH];
    #pragma unroll
    for (int d = 0; d < DH; d++) qreg[d] = qp[d];

    float acc[DH];
    #pragma unroll
    for (int d = 0; d < DH; d++) acc[d] = 0.f;
    float m = -1e30f, l = 0.f;
    int base = qb * 96 - 96;

    for (int t0 = 0; t0 < 288; t0 += 32) {
        if (tid < 32) {
            int gs = base + t0 + tid;
            int tok = (gs >= 0 && gs < 3072) ? g_lidx[nh * 3072 + gs] : -1;
            toks[tid] = tok;
            am[tid] = (tok >= 0) ? mask[n * TT + tok] : -1e30f;
        }
        __syncthreads();
        for (int idx = tid; idx < 32 * DH; idx += 128) {
            int s = idx >> 6, d = idx & 63;
            int tok = toks[s];
            if (tok >= 0) {
                ks[s][d] = g_k[((size_t)nh * TT + tok) * DH + d];
                vs[s][d] = g_v[((size_t)nh * TT + tok) * DH + d];
            } else { ks[s][d] = 0.f; vs[s][d] = 0.f; }
        }
        __syncthreads();

        float tmax = -1e30f;
        for (int s = 0; s < 32; s++) {
            float dot = 0.f;
            #pragma unroll
            for (int d = 0; d < DH; d += 4) {
                float4 kv = *(const float4*)&ks[s][d];
                dot += qreg[d]*kv.x + qreg[d+1]*kv.y + qreg[d+2]*kv.z + qreg[d+3]*kv.w;
            }
            float a = am[s];
            float v = (a > -1e29f) ? dot * 0.125f + a : -1e30f;
            sc[s][tid] = v;
            tmax = fmaxf(tmax, v);
        }
        if (tmax > -1e29f) {
            float newm = fmaxf(m, tmax);
            float scale = expf(m - newm);
            l *= scale;
            #pragma unroll
            for (int d = 0; d < DH; d++) acc[d] *= scale;
            for (int s = 0; s < 32; s++) {
                float v = sc[s][tid];
                float p = (v > -1e29f) ? expf(v - newm) : 0.f;
                l += p;
                #pragma unroll
                for (int d = 0; d < DH; d += 4) {
                    float4 vv = *(const float4*)&vs[s][d];
                    acc[d]   += p * vv.x; acc[d+1] += p * vv.y;
                    acc[d+2] += p * vv.z; acc[d+3] += p * vv.w;
                }
            }
            m = newm;
        }
        __syncthreads();
    }

    // appended global key: token 0, additive mask 0
    {
        const float* k0 = &g_k[(size_t)nh * TT * DH];
        const float* v0 = &g_v[(size_t)nh * TT * DH];
        float dot = 0.f;
        #pragma unroll
        for (int d = 0; d < DH; d++) dot += qreg[d] * k0[d];
        float s = dot * 0.125f;
        float newm = fmaxf(m, s);
        float scale = expf(m - newm);
        float p = expf(s - newm);
        l = l * scale + p;
        #pragma unroll
        for (int d = 0; d < DH; d++) acc[d] = acc[d] * scale + p * v0[d];
        m = newm;
    }

    float lsel = m + logf(l);
    float lseg = g_lseg[nh * TT + qt];
    float pmix = 1.f / (1.f + expf(lseg - lsel));
    const float* cg = &g_ctxg[((size_t)nh * TT + qt) * DH];
    float invl = 1.f / l;
    float* op = &out[((size_t)n * TT + qt) * HID + h * DH];
    #pragma unroll
    for (int d = 0; d < DH; d++) {
        float cl = acc[d] * invl;
        float gv = cg[d];
        op[d] = gv + pmix * (cl - gv);
    }
}

// ---------------------------------------------------------------------------
// BOS: token-0 query, full UNscaled attention over all 4096 keys + mask.
// Overwrites output row t=0. Runs last.
// ---------------------------------------------------------------------------
__global__ __launch_bounds__(128) void attn_bos(const float* __restrict__ mask,
                                                float* __restrict__ out)
{
    int h = blockIdx.x, n = blockIdx.y;
    int nh = n * NHD + h;
    __shared__ float sc[TT];
    __shared__ float q0s[DH];
    __shared__ float red[128];
    int tid = threadIdx.x;
    if (tid < DH) q0s[tid] = g_q[(size_t)nh * TT * DH + tid];
    __syncthreads();

    float lmax = -1e30f;
    for (int t = tid; t < TT; t += 128) {
        const float* kp = &g_k[((size_t)nh * TT + t) * DH];
        float dot = 0.f;
        #pragma unroll
        for (int d = 0; d < DH; d++) dot += q0s[d] * kp[d];
        float s = dot + mask[n * TT + t];
        sc[t] = s;
        lmax = fmaxf(lmax, s);
    }
    red[tid] = lmax; __syncthreads();
    for (int o = 64; o > 0; o >>= 1) {
        if (tid < o) red[tid] = fmaxf(red[tid], red[tid + o]);
        __syncthreads();
    }
    float mx = red[0]; __syncthreads();

    float ls = 0.f;
    for (int t = tid; t < TT; t += 128) {
        float p = expf(sc[t] - mx);
        sc[t] = p;
        ls += p;
    }
    red[tid] = ls; __syncthreads();
    for (int o = 64; o > 0; o >>= 1) {
        if (tid < o) red[tid] += red[tid + o];
        __syncthreads();
    }
    float inv = 1.f / red[0];

    if (tid < DH) {
        float a = 0.f;
        for (int t = 0; t < TT; t++)
            a += sc[t] * g_v[((size_t)nh * TT + t) * DH + tid];
        out[(size_t)n * TT * HID + h * DH + tid] = a * inv;
    }
}

// ---------------------------------------------------------------------------
extern "C" void kernel_launch(void* const* d_in, const int* in_sizes, int n_in,
                              void* d_out, int out_size)
{
    const float* hs   = (const float*)d_in[0];
    const float* mask = (const float*)d_in[1];
    const float* Wq   = (const float*)d_in[2];
    const float* bq   = (const float*)d_in[3];
    const float* Wk   = (const float*)d_in[4];
    const float* bk   = (const float*)d_in[5];
    const float* Wv   = (const float*)d_in[6];
    const float* bv   = (const float*)d_in[7];
    float* out = (float*)d_out;

    dim3 ggrid(1024 / BN, (NB * TT) / BM, 3);
    qkv_gemm<<<ggrid, 256>>>(hs, Wq, bq, Wk, bk, Wv, bv);
    norm_kernel<<<(NB * NHD * TT + 255) / 256, 256>>>(bq, mask);
    select_kernel<<<NB * NHD * 64, 64>>>();
    attn_global<<<dim3(64, NHD, NB), 64>>>(mask);
    attn_local<<<dim3(32, NHD, NB), 128>>>(mask, out);
    attn_bos<<<dim3(NHD, NB), 128>>>(mask, out);
}

// round 5
// speedup vs baseline: 1.1239x; 1.1239x over previous
#include <cuda_runtime.h>
#include <math.h>
#include <stdint.h>

// Problem dims
#define NB   2
#define TT   4096
#define NHD  16      // heads
#define DH   64      // head dim
#define HID  1024
#define SELC 64
#define TOPK 16
#define LOCC 128

// Scratch (device globals: allocation-free rule)
__device__ float g_q[(size_t)NB*NHD*TT*DH];
__device__ float g_k[(size_t)NB*NHD*TT*DH];
__device__ float g_v[(size_t)NB*NHD*TT*DH];
__device__ float g_ctxg[(size_t)NB*NHD*TT*DH];
__device__ float g_lseg[NB*NHD*TT];
__device__ float g_norm[NB*NHD*TT];
__device__ int   g_gidx[NB*NHD*1024];
__device__ int   g_lidx[NB*NHD*3072];

// ---------------------------------------------------------------------------
// tf32 helpers (plain PTX, valid on target sm_103 — no tcgen05)
// ---------------------------------------------------------------------------
__device__ __forceinline__ uint32_t f2tf32(float x) {
    uint32_t r;
    asm("cvt.rna.tf32.f32 %0, %1;" : "=r"(r) : "f"(x));
    return r;
}

#define MMA_TF32(c, a, b0, b1) \
    asm volatile("mma.sync.aligned.m16n8k8.row.col.f32.tf32.tf32.f32 " \
        "{%0,%1,%2,%3}, {%4,%5,%6,%7}, {%8,%9}, {%0,%1,%2,%3};" \
        : "+f"((c)[0]), "+f"((c)[1]), "+f"((c)[2]), "+f"((c)[3]) \
        : "r"((a)[0]), "r"((a)[1]), "r"((a)[2]), "r"((a)[3]), "r"(b0), "r"(b1))

// ---------------------------------------------------------------------------
// tf32 mma.sync GEMM. C[8192,1024] = A[8192,1024] * W^T + bias, scattered
// into (n,h,t,d) in g_q/g_k/g_v (selected by `which`).
// SPLIT=3: hi/lo split accumulation (hi*hi + hi*lo + lo*hi), err ~2^-22.
// SPLIT=1: plain tf32.
// CTA 128x128, BK=16, 8 warps, warp tile 32x64 (2x8 m16n8k8), double buffer.
// ---------------------------------------------------------------------------
#define BKC  16
#define SROW 132                 // padded smem row stride (words)
#define MSZ  (BKC * SROW)        // 2112 words per matrix slab

template<int SPLIT>
__global__ __launch_bounds__(256) void gemm_tc(
    const float* __restrict__ A, const float* __restrict__ W,
    const float* __restrict__ bias, int which)
{
    float* out = (which == 0) ? g_q : (which == 1) ? g_k : g_v;
    extern __shared__ uint32_t sm[];
    const int NMAT = (SPLIT == 3) ? 4 : 2;       // Ahi,(Alo),Bhi,(Blo)
    const int BUF  = NMAT * MSZ;

    const int tid = threadIdx.x;
    const int wid = tid >> 5, lane = tid & 31;
    const int gid = lane >> 2, tq = lane & 3;
    const int row0 = blockIdx.y * 128, col0 = blockIdx.x * 128;
    const int warpM = (wid & 3) * 32, warpN = (wid >> 2) * 64;

    float acc[2][8][4];
    #pragma unroll
    for (int i = 0; i < 2; i++)
        #pragma unroll
        for (int j = 0; j < 8; j++)
            #pragma unroll
            for (int r = 0; r < 4; r++) acc[i][j][r] = 0.f;

    // gmem->smem mapping: 2 threads per row; each covers 8 consecutive k.
    const int lrow = tid >> 1, kq = tid & 1;
    const float* aBase = A + (size_t)(row0 + lrow) * 1024 + kq * 8;
    const float* bBase = W + (size_t)(col0 + lrow) * 1024 + kq * 8;

    float4 pa0, pa1, pb0, pb1;

    auto prefetch = [&](int c) {
        const float* ap = aBase + c * BKC;
        const float* bp = bBase + c * BKC;
        pa0 = *(const float4*)ap;  pa1 = *(const float4*)(ap + 4);
        pb0 = *(const float4*)bp;  pb1 = *(const float4*)(bp + 4);
    };

    auto store_chunk = [&](uint32_t* b) {
        uint32_t* Ah = b;
        uint32_t* Al = b + MSZ;
        uint32_t* Bh = b + (SPLIT == 3 ? 2 : 1) * MSZ;
        uint32_t* Bl = b + 3 * MSZ;
        float av[8] = {pa0.x, pa0.y, pa0.z, pa0.w, pa1.x, pa1.y, pa1.z, pa1.w};
        float bv[8] = {pb0.x, pb0.y, pb0.z, pb0.w, pb1.x, pb1.y, pb1.z, pb1.w};
        #pragma unroll
        for (int j = 0; j < 8; j++) {
            int k = kq * 8 + j;
            uint32_t ah = f2tf32(av[j]);
            Ah[k * SROW + lrow] = ah;
            uint32_t bh = f2tf32(bv[j]);
            Bh[k * SROW + lrow] = bh;
            if (SPLIT == 3) {
                Al[k * SROW + lrow] = f2tf32(av[j] - __uint_as_float(ah));
                Bl[k * SROW + lrow] = f2tf32(bv[j] - __uint_as_float(bh));
            }
        }
    };

    auto compute_chunk = [&](const uint32_t* b) {
        const uint32_t* Ah = b;
        const uint32_t* Al = b + MSZ;
        const uint32_t* Bh = b + (SPLIT == 3 ? 2 : 1) * MSZ;
        const uint32_t* Bl = b + 3 * MSZ;
        #pragma unroll
        for (int ks = 0; ks < 2; ks++) {
            const int k0 = ks * 8;
            const int ka = (k0 + tq) * SROW, kb = (k0 + tq + 4) * SROW;
            uint32_t afh[2][4], afl[2][4];
            #pragma unroll
            for (int mt = 0; mt < 2; mt++) {
                int m0 = warpM + mt * 16 + gid;
                afh[mt][0] = Ah[ka + m0];     afh[mt][1] = Ah[ka + m0 + 8];
                afh[mt][2] = Ah[kb + m0];     afh[mt][3] = Ah[kb + m0 + 8];
                if (SPLIT == 3) {
                    afl[mt][0] = Al[ka + m0]; afl[mt][1] = Al[ka + m0 + 8];
                    afl[mt][2] = Al[kb + m0]; afl[mt][3] = Al[kb + m0 + 8];
                }
            }
            #pragma unroll
            for (int nt = 0; nt < 8; nt++) {
                int n0 = warpN + nt * 8 + gid;
                uint32_t bh0 = Bh[ka + n0], bh1 = Bh[kb + n0];
                uint32_t bl0 = 0, bl1 = 0;
                if (SPLIT == 3) { bl0 = Bl[ka + n0]; bl1 = Bl[kb + n0]; }
                #pragma unroll
                for (int mt = 0; mt < 2; mt++) {
                    MMA_TF32(acc[mt][nt], afh[mt], bh0, bh1);
                    if (SPLIT == 3) {
                        MMA_TF32(acc[mt][nt], afh[mt], bl0, bl1);
                        MMA_TF32(acc[mt][nt], afl[mt], bh0, bh1);
                    }
                }
            }
        }
    };

    prefetch(0);
    store_chunk(sm);
    __syncthreads();

    const int NCH = 1024 / BKC;   // 64
    for (int c = 0; c < NCH; c++) {
        if (c + 1 < NCH) prefetch(c + 1);
        compute_chunk((c & 1) ? (sm + BUF) : sm);
        __syncthreads();
        if (c + 1 < NCH) {
            store_chunk(((c + 1) & 1) ? (sm + BUF) : sm);
            __syncthreads();
        }
    }

    // Epilogue. Per warp: h is constant (warp spans 64 cols = 1 head).
    const int hcol = col0 + warpN;
    const int h = hcol >> 6;
    float2 bb[8];
    #pragma unroll
    for (int nt = 0; nt < 8; nt++) {
        int cc = hcol + nt * 8 + 2 * tq;
        bb[nt].x = bias[cc];
        bb[nt].y = bias[cc + 1];
    }
    #pragma unroll
    for (int mt = 0; mt < 2; mt++) {
        #pragma unroll
        for (int rr = 0; rr < 2; rr++) {
            int grow = row0 + warpM + mt * 16 + gid + rr * 8;
            int nn = grow >> 12, t = grow & 4095;
            float* p = out + (((size_t)(nn * NHD + h)) * TT + t) * DH;
            #pragma unroll
            for (int nt = 0; nt < 8; nt++) {
                float2 v;
                v.x = acc[mt][nt][rr * 2]     + bb[nt].x;
                v.y = acc[mt][nt][rr * 2 + 1] + bb[nt].y;
                *(float2*)(p + nt * 8 + 2 * tq) = v;
            }
        }
    }
}

// ---------------------------------------------------------------------------
// norms: ||k[n,h,t,:] + bq[h*64:]||^2 * (mask[n,t]==0)
// ---------------------------------------------------------------------------
__global__ void norm_kernel(const float* __restrict__ bq, const float* __restrict__ mask)
{
    int g = blockIdx.x * 256 + threadIdx.x;
    if (g >= NB * NHD * TT) return;
    int t = g & (TT - 1);
    int h = (g >> 12) & (NHD - 1);
    int n = g >> 16;
    const float* kp = &g_k[(size_t)g * DH];
    const float* bh = &bq[h * DH];
    float s = 0.f;
    #pragma unroll
    for (int d = 0; d < DH; d += 4) {
        float4 kv = *(const float4*)&kp[d];
        float x0 = kv.x + bh[d+0];
        float x1 = kv.y + bh[d+1];
        float x2 = kv.z + bh[d+2];
        float x3 = kv.w + bh[d+3];
        s += x0*x0 + x1*x1 + x2*x2 + x3*x3;
    }
    float valid = (mask[n * TT + t] == 0.0f) ? 1.0f : 0.0f;
    g_norm[g] = s * valid;
}

// ---------------------------------------------------------------------------
// selection: stable rank -> top-16 / bottom-48, index-ordered
// ---------------------------------------------------------------------------
__global__ void select_kernel()
{
    int b  = blockIdx.x;
    int c  = b & 63;
    int nh = b >> 6;
    int i  = threadIdx.x;
    __shared__ float nrm[64];
    __shared__ int   sel[64];
    nrm[i] = g_norm[(size_t)nh * TT + c * SELC + i];
    __syncthreads();
    float mine = nrm[i];
    int rank = 0;
    #pragma unroll 8
    for (int j = 0; j < 64; j++) {
        float oj = nrm[j];
        rank += (oj < mine) || (oj == mine && j < i);
    }
    sel[i] = (rank >= SELC - TOPK) ? 1 : 0;
    __syncthreads();
    int gcnt = 0;
    for (int j = 0; j < i; j++) gcnt += sel[j];
    if (sel[i]) g_gidx[nh * 1024 + c * TOPK + gcnt] = c * SELC + i;
    else        g_lidx[nh * 3072 + c * (SELC - TOPK) + (i - gcnt)] = c * SELC + i;
}

// ---------------------------------------------------------------------------
// Global pass: 64 queries/block x 2 half-threads (32 dims each).
// ---------------------------------------------------------------------------
__global__ __launch_bounds__(128) void attn_global(const float* __restrict__ mask)
{
    int qb = blockIdx.x;
    int h  = blockIdx.y, n = blockIdx.z;
    int nh = n * NHD + h;
    __shared__ float ks[48][DH];
    __shared__ float vs[48][DH];
    __shared__ float am[48];
    __shared__ float sc[48][SELC];
    int tid = threadIdx.x;

    for (int idx = tid; idx < 48 * DH; idx += 128) {
        int s = idx >> 6, d = idx & 63;
        int gs = qb * 16 - 16 + s;
        if (gs >= 0 && gs < 1024) {
            int tok = g_gidx[nh * 1024 + gs];
            ks[s][d] = g_k[((size_t)nh * TT + tok) * DH + d];
            vs[s][d] = g_v[((size_t)nh * TT + tok) * DH + d];
            if (d == 0) am[s] = mask[n * TT + tok];
        } else {
            ks[s][d] = 0.f; vs[s][d] = 0.f;
            if (d == 0) am[s] = -1e30f;
        }
    }
    __syncthreads();

    int q = tid >> 1, half = tid & 1;
    int qt = qb * SELC + q;
    int dbase = half * 32;
    float qreg[32];
    const float* qp = &g_q[((size_t)nh * TT + qt) * DH + dbase];
    #pragma unroll
    for (int d = 0; d < 32; d++) qreg[d] = qp[d];

    float m = -1e30f;
    for (int s = 0; s < 48; s++) {
        float dot = 0.f;
        #pragma unroll
        for (int d = 0; d < 32; d += 4) {
            float4 kv = *(const float4*)&ks[s][dbase + d];
            dot += qreg[d]*kv.x + qreg[d+1]*kv.y + qreg[d+2]*kv.z + qreg[d+3]*kv.w;
        }
        dot += __shfl_xor_sync(0xffffffffu, dot, 1);
        float a = am[s];
        float v = (a > -1e29f) ? dot * 0.125f + a : -1e30f;
        if (half == 0) sc[s][q] = v;
        m = fmaxf(m, v);
    }
    __syncwarp();

    float l = 0.f;
    float acc[32];
    #pragma unroll
    for (int d = 0; d < 32; d++) acc[d] = 0.f;
    for (int s = 0; s < 48; s++) {
        float v = sc[s][q];
        float p = (v > -1e29f) ? expf(v - m) : 0.f;
        l += p;
        #pragma unroll
        for (int d = 0; d < 32; d += 4) {
            float4 vv = *(const float4*)&vs[s][dbase + d];
            acc[d]   += p * vv.x; acc[d+1] += p * vv.y;
            acc[d+2] += p * vv.z; acc[d+3] += p * vv.w;
        }
    }
    float inv = 1.f / l;
    float* cg = &g_ctxg[((size_t)nh * TT + qt) * DH + dbase];
    #pragma unroll
    for (int d = 0; d < 32; d++) cg[d] = acc[d] * inv;
    if (half == 0) g_lseg[nh * TT + qt] = m + logf(l);
}

// ---------------------------------------------------------------------------
// Local pass + merge: 128 queries/block x 2 half-threads.
// ---------------------------------------------------------------------------
__global__ __launch_bounds__(256) void attn_local(const float* __restrict__ mask,
                                                  float* __restrict__ out)
{
    int qb = blockIdx.x;
    int h  = blockIdx.y, n = blockIdx.z;
    int nh = n * NHD + h;
    __shared__ float ks[32][DH];
    __shared__ float vs[32][DH];
    __shared__ float am[32];
    __shared__ int   toks[32];
    __shared__ float sc[32][128];

    int tid = threadIdx.x;
    int q = tid >> 1, half = tid & 1;
    int qt = qb * LOCC + q;
    int dbase = half * 32;
    float qreg[32];
    const float* qp = &g_q[((size_t)nh * TT + qt) * DH + dbase];
    #pragma unroll
    for (int d = 0; d < 32; d++) qreg[d] = qp[d];

    float acc[32];
    #pragma unroll
    for (int d = 0; d < 32; d++) acc[d] = 0.f;
    float m = -1e30f, l = 0.f;
    int base = qb * 96 - 96;

    for (int t0 = 0; t0 < 288; t0 += 32) {
        if (tid < 32) {
            int gs = base + t0 + tid;
            int tok = (gs >= 0 && gs < 3072) ? g_lidx[nh * 3072 + gs] : -1;
            toks[tid] = tok;
            am[tid] = (tok >= 0) ? mask[n * TT + tok] : -1e30f;
        }
        __syncthreads();
        for (int idx = tid; idx < 32 * DH; idx += 256) {
            int s = idx >> 6, d = idx & 63;
            int tok = toks[s];
            if (tok >= 0) {
                ks[s][d] = g_k[((size_t)nh * TT + tok) * DH + d];
                vs[s][d] = g_v[((size_t)nh * TT + tok) * DH + d];
            } else { ks[s][d] = 0.f; vs[s][d] = 0.f; }
        }
        __syncthreads();

        float tmax = -1e30f;
        for (int s = 0; s < 32; s++) {
            float dot = 0.f;
            #pragma unroll
            for (int d = 0; d < 32; d += 4) {
                float4 kv = *(const float4*)&ks[s][dbase + d];
                dot += qreg[d]*kv.x + qreg[d+1]*kv.y + qreg[d+2]*kv.z + qreg[d+3]*kv.w;
            }
            dot += __shfl_xor_sync(0xffffffffu, dot, 1);
            float a = am[s];
            float v = (a > -1e29f) ? dot * 0.125f + a : -1e30f;
            if (half == 0) sc[s][q] = v;
            tmax = fmaxf(tmax, v);
        }
        __syncwarp();
        if (tmax > -1e29f) {
            float newm = fmaxf(m, tmax);
            float scale = expf(m - newm);
            l *= scale;
            #pragma unroll
            for (int d = 0; d < 32; d++) acc[d] *= scale;
            for (int s = 0; s < 32; s++) {
                float v = sc[s][q];
                float p = (v > -1e29f) ? expf(v - newm) : 0.f;
                l += p;
                #pragma unroll
                for (int d = 0; d < 32; d += 4) {
                    float4 vv = *(const float4*)&vs[s][dbase + d];
                    acc[d]   += p * vv.x; acc[d+1] += p * vv.y;
                    acc[d+2] += p * vv.z; acc[d+3] += p * vv.w;
                }
            }
            m = newm;
        }
        __syncthreads();
    }

    // appended global key (token 0, additive mask 0)
    {
        const float* k0 = &g_k[(size_t)nh * TT * DH + dbase];
        const float* v0 = &g_v[(size_t)nh * TT * DH + dbase];
        float dot = 0.f;
        #pragma unroll
        for (int d = 0; d < 32; d++) dot += qreg[d] * k0[d];
        dot += __shfl_xor_sync(0xffffffffu, dot, 1);
        float s = dot * 0.125f;
        float newm = fmaxf(m, s);
        float scale = expf(m - newm);
        float p = expf(s - newm);
        l = l * scale + p;
        #pragma unroll
        for (int d = 0; d < 32; d++) acc[d] = acc[d] * scale + p * v0[d];
        m = newm;
    }

    float lsel = m + logf(l);
    float lseg = g_lseg[nh * TT + qt];
    float pmix = 1.f / (1.f + expf(lseg - lsel));
    const float* cg = &g_ctxg[((size_t)nh * TT + qt) * DH + dbase];
    float invl = 1.f / l;
    float* op = &out[((size_t)n * TT + qt) * HID + h * DH + dbase];
    #pragma unroll
    for (int d = 0; d < 32; d++) {
        float cl = acc[d] * invl;
        float gv = cg[d];
        op[d] = gv + pmix * (cl - gv);
    }
}

// ---------------------------------------------------------------------------
// BOS: token-0 query, full UNscaled attention over all 4096 keys + mask.
// ---------------------------------------------------------------------------
__global__ __launch_bounds__(512) void attn_bos(const float* __restrict__ mask,
                                                float* __restrict__ out)
{
    int h = blockIdx.x, n = blockIdx.y;
    int nh = n * NHD + h;
    __shared__ float sc[TT];
    __shared__ float q0s[DH];
    __shared__ float red[512];
    __shared__ float part[8][DH];
    int tid = threadIdx.x;
    if (tid < DH) q0s[tid] = g_q[(size_t)nh * TT * DH + tid];
    __syncthreads();

    float lmax = -1e30f;
    for (int t = tid; t < TT; t += 512) {
        const float* kp = &g_k[((size_t)nh * TT + t) * DH];
        float dot = 0.f;
        #pragma unroll
        for (int d = 0; d < DH; d += 4) {
            float4 kv = *(const float4*)&kp[d];
            dot += q0s[d]*kv.x + q0s[d+1]*kv.y + q0s[d+2]*kv.z + q0s[d+3]*kv.w;
        }
        float s = dot + mask[n * TT + t];
        sc[t] = s;
        lmax = fmaxf(lmax, s);
    }
    red[tid] = lmax; __syncthreads();
    for (int o = 256; o > 0; o >>= 1) {
        if (tid < o) red[tid] = fmaxf(red[tid], red[tid + o]);
        __syncthreads();
    }
    float mx = red[0]; __syncthreads();

    float ls = 0.f;
    for (int t = tid; t < TT; t += 512) {
        float p = expf(sc[t] - mx);
        sc[t] = p;
        ls += p;
    }
    red[tid] = ls; __syncthreads();
    for (int o = 256; o > 0; o >>= 1) {
        if (tid < o) red[tid] += red[tid + o];
        __syncthreads();
    }
    float inv = 1.f / red[0];
    __syncthreads();

    {
        int d = tid & 63, sl = tid >> 6;
        float a = 0.f;
        int tstart = sl * 512;
        for (int t = tstart; t < tstart + 512; t++)
            a += sc[t] * g_v[((size_t)nh * TT + t) * DH + d];
        part[sl][d] = a;
    }
    __syncthreads();
    if (tid < DH) {
        float a = 0.f;
        #pragma unroll
        for (int sl = 0; sl < 8; sl++) a += part[sl][tid];
        out[(size_t)n * TT * HID + h * DH + tid] = a * inv;
    }
}

// ---------------------------------------------------------------------------
extern "C" void kernel_launch(void* const* d_in, const int* in_sizes, int n_in,
                              void* d_out, int out_size)
{
    const float* hs   = (const float*)d_in[0];
    const float* mask = (const float*)d_in[1];
    const float* Wq   = (const float*)d_in[2];
    const float* bq   = (const float*)d_in[3];
    const float* Wk   = (const float*)d_in[4];
    const float* bk   = (const float*)d_in[5];
    const float* Wv   = (const float*)d_in[6];
    const float* bv   = (const float*)d_in[7];
    float* out = (float*)d_out;

    const int SMEM3 = 2 * 4 * MSZ * 4;   // 67584 B
    const int SMEM1 = 2 * 2 * MSZ * 4;   // 33792 B
    static int attr_done = 0;
    if (!attr_done) {
        cudaFuncSetAttribute(gemm_tc<3>, cudaFuncAttributeMaxDynamicSharedMemorySize, SMEM3);
        cudaFuncSetAttribute(gemm_tc<1>, cudaFuncAttributeMaxDynamicSharedMemorySize, SMEM1);
        attr_done = 1;
    }

    dim3 ggrid(1024 / 128, (NB * TT) / 128);
    gemm_tc<3><<<ggrid, 256, SMEM3>>>(hs, Wq, bq, 0);
    gemm_tc<3><<<ggrid, 256, SMEM3>>>(hs, Wk, bk, 1);
    gemm_tc<1><<<ggrid, 256, SMEM1>>>(hs, Wv, bv, 2);
    norm_kernel<<<(NB * NHD * TT + 255) / 256, 256>>>(bq, mask);
    select_kernel<<<NB * NHD * 64, 64>>>();
    attn_global<<<dim3(64, NHD, NB), 128>>>(mask);
    attn_local<<<dim3(32, NHD, NB), 256>>>(mask, out);
    attn_bos<<<dim3(NHD, NB), 512>>>(mask, out);
}

// round 6
// speedup vs baseline: 1.4550x; 1.2947x over previous
#include <cuda_runtime.h>
#include <cuda_fp16.h>
#include <math.h>
#include <stdint.h>

// Problem dims
#define NB   2
#define TT   4096
#define NHD  16      // heads
#define DH   64      // head dim
#define HID  1024
#define SELC 64
#define TOPK 16
#define LOCC 128

// Scratch (device globals: allocation-free rule)
__device__ float g_q[(size_t)NB*NHD*TT*DH];
__device__ float g_k[(size_t)NB*NHD*TT*DH];
__device__ float g_v[(size_t)NB*NHD*TT*DH];
__device__ float g_ctxg[(size_t)NB*NHD*TT*DH];
__device__ float g_lseg[NB*NHD*TT];
__device__ float g_norm[NB*NHD*TT];
__device__ int   g_gidx[NB*NHD*1024];
__device__ int   g_lidx[NB*NHD*3072];

// fp16 split scratch
__device__ __half g_ah[(size_t)8192*1024];
__device__ __half g_al[(size_t)8192*1024];
__device__ __half g_wh[(size_t)3*1024*1024];
__device__ __half g_wl[(size_t)3*1024*1024];

// ---------------------------------------------------------------------------
// PTX helpers (plain PTX only — valid on target sm_103)
// ---------------------------------------------------------------------------
#define MMA_F16(c, a, b0, b1) \
    asm volatile("mma.sync.aligned.m16n8k16.row.col.f32.f16.f16.f32 " \
        "{%0,%1,%2,%3}, {%4,%5,%6,%7}, {%8,%9}, {%0,%1,%2,%3};" \
        : "+f"((c)[0]), "+f"((c)[1]), "+f"((c)[2]), "+f"((c)[3]) \
        : "r"((a)[0]), "r"((a)[1]), "r"((a)[2]), "r"((a)[3]), "r"(b0), "r"(b1))

__device__ __forceinline__ void cp16(uint32_t dst, const void* src) {
    asm volatile("cp.async.cg.shared.global [%0], [%1], 16;" :: "r"(dst), "l"(src));
}
#define CP_COMMIT() asm volatile("cp.async.commit_group;" ::: "memory")
#define CP_WAIT2()  asm volatile("cp.async.wait_group 2;" ::: "memory")

// ---------------------------------------------------------------------------
// fp32 -> (fp16 hi, fp16 lo) split, vectorized x4
// ---------------------------------------------------------------------------
__global__ void split_f16(const float* __restrict__ src, __half* __restrict__ hi,
                          __half* __restrict__ lo, int n4)
{
    int i = blockIdx.x * 256 + threadIdx.x;
    if (i >= n4) return;
    float4 v = ((const float4*)src)[i];
    __half h[4], l[4];
    h[0] = __float2half_rn(v.x); l[0] = __float2half_rn(v.x - __half2float(h[0]));
    h[1] = __float2half_rn(v.y); l[1] = __float2half_rn(v.y - __half2float(h[1]));
    h[2] = __float2half_rn(v.z); l[2] = __float2half_rn(v.z - __half2float(h[2]));
    h[3] = __float2half_rn(v.w); l[3] = __float2half_rn(v.w - __half2float(h[3]));
    ((uint2*)hi)[i] = *(uint2*)h;
    ((uint2*)lo)[i] = *(uint2*)l;
}

// ---------------------------------------------------------------------------
// fp16 mma GEMM, split-3 accumulation as virtual K=3072:
//   C = Ahi.Whi^T + Ahi.Wlo^T + Alo.Whi^T + bias   (error ~2^-22)
// CTA 128x128, BK=32, 8 warps (warp tile 32x64), 4-stage cp.async pipeline.
// z selects Q/K/V (weight slab, bias, output). Output scattered to (n,h,t,d).
// ---------------------------------------------------------------------------
#define NCH  96                    // 3 phases x 32 chunks of K=32
#define STG_BYTES 20480            // A: 128 rows x 80B + B: same
#define GEMM_SMEM (4 * STG_BYTES)  // 81920

__global__ __launch_bounds__(256, 2) void gemm_f16(
    const float* __restrict__ bq, const float* __restrict__ bk,
    const float* __restrict__ bv)
{
    extern __shared__ char smc[];
    uint32_t sbase;
    asm("{ .reg .u64 t; cvta.to.shared.u64 t, %1; cvt.u32.u64 %0, t; }"
        : "=r"(sbase) : "l"(smc));
    uint32_t* smw = (uint32_t*)smc;

    const int z = blockIdx.z;
    float* out = (z == 0) ? g_q : (z == 1) ? g_k : g_v;
    const float* bias = (z == 0) ? bq : (z == 1) ? bk : bv;
    const __half* Whi = g_wh + (size_t)z * 1048576;
    const __half* Wlo = g_wl + (size_t)z * 1048576;

    const int tid = threadIdx.x;
    const int wid = tid >> 5, lane = tid & 31;
    const int gid = lane >> 2, tq = lane & 3;
    const int row0 = blockIdx.y * 128, col0 = blockIdx.x * 128;
    const int warpM = (wid & 3) * 32, warpN = (wid >> 2) * 64;

    float acc[2][8][4];
    #pragma unroll
    for (int i = 0; i < 2; i++)
        #pragma unroll
        for (int j = 0; j < 8; j++)
            #pragma unroll
            for (int r = 0; r < 4; r++) acc[i][j][r] = 0.f;

    const int crow = tid >> 1;     // 0..127
    const int h2 = tid & 1;        // which 32B half-row

    auto issue_copy = [&](int c, int stg) {
        int kv = c * 32;
        int ph = kv >> 10;
        int kl = kv & 1023;
        const __half* aS = (ph == 2) ? g_al : g_ah;
        const __half* bS = (ph == 1) ? Wlo : Whi;
        const __half* asrc = aS + (size_t)(row0 + crow) * 1024 + kl + h2 * 16;
        const __half* bsrc = bS + (size_t)(col0 + crow) * 1024 + kl + h2 * 16;
        uint32_t ad = sbase + stg * STG_BYTES + crow * 80 + h2 * 32;
        uint32_t bd = ad + 10240;
        cp16(ad, asrc);      cp16(ad + 16, asrc + 8);
        cp16(bd, bsrc);      cp16(bd + 16, bsrc + 8);
    };

    // prefetch 3 chunks
    #pragma unroll
    for (int s = 0; s < 3; s++) { issue_copy(s, s); CP_COMMIT(); }

    for (int c = 0; c < NCH; c++) {
        CP_WAIT2();
        __syncthreads();
        int cn = c + 3;
        if (cn < NCH) issue_copy(cn, cn & 3);
        CP_COMMIT();

        const uint32_t* SA = smw + (c & 3) * (STG_BYTES / 4);
        const uint32_t* SB = SA + 2560;
        #pragma unroll
        for (int ks = 0; ks < 2; ks++) {
            const int kb = ks * 8 + tq;
            uint32_t af[2][4];
            #pragma unroll
            for (int mt = 0; mt < 2; mt++) {
                int m = warpM + mt * 16 + gid;
                af[mt][0] = SA[m * 20 + kb];
                af[mt][1] = SA[(m + 8) * 20 + kb];
                af[mt][2] = SA[m * 20 + kb + 4];
                af[mt][3] = SA[(m + 8) * 20 + kb + 4];
            }
            #pragma unroll
            for (int nt = 0; nt < 8; nt++) {
                int nrow = warpN + nt * 8 + gid;
                uint32_t b0 = SB[nrow * 20 + kb];
                uint32_t b1 = SB[nrow * 20 + kb + 4];
                MMA_F16(acc[0][nt], af[0], b0, b1);
                MMA_F16(acc[1][nt], af[1], b0, b1);
            }
        }
    }

    // Epilogue: warp spans 64 cols = one head.
    const int hcol = col0 + warpN;
    const int h = hcol >> 6;
    float2 bb[8];
    #pragma unroll
    for (int nt = 0; nt < 8; nt++) {
        int cc = hcol + nt * 8 + 2 * tq;
        bb[nt].x = bias[cc];
        bb[nt].y = bias[cc + 1];
    }
    #pragma unroll
    for (int mt = 0; mt < 2; mt++) {
        #pragma unroll
        for (int rr = 0; rr < 2; rr++) {
            int grow = row0 + warpM + mt * 16 + gid + rr * 8;
            int nn = grow >> 12, t = grow & 4095;
            float* p = out + (((size_t)(nn * NHD + h)) * TT + t) * DH;
            #pragma unroll
            for (int nt = 0; nt < 8; nt++) {
                float2 v;
                v.x = acc[mt][nt][rr * 2]     + bb[nt].x;
                v.y = acc[mt][nt][rr * 2 + 1] + bb[nt].y;
                *(float2*)(p + nt * 8 + 2 * tq) = v;
            }
        }
    }
}

// ---------------------------------------------------------------------------
// norms: ||k[n,h,t,:] + bq[h*64:]||^2 * (mask[n,t]==0)
// ---------------------------------------------------------------------------
__global__ void norm_kernel(const float* __restrict__ bq, const float* __restrict__ mask)
{
    int g = blockIdx.x * 256 + threadIdx.x;
    if (g >= NB * NHD * TT) return;
    int t = g & (TT - 1);
    int h = (g >> 12) & (NHD - 1);
    int n = g >> 16;
    const float* kp = &g_k[(size_t)g * DH];
    const float* bh = &bq[h * DH];
    float s = 0.f;
    #pragma unroll
    for (int d = 0; d < DH; d += 4) {
        float4 kv = *(const float4*)&kp[d];
        float x0 = kv.x + bh[d+0];
        float x1 = kv.y + bh[d+1];
        float x2 = kv.z + bh[d+2];
        float x3 = kv.w + bh[d+3];
        s += x0*x0 + x1*x1 + x2*x2 + x3*x3;
    }
    float valid = (mask[n * TT + t] == 0.0f) ? 1.0f : 0.0f;
    g_norm[g] = s * valid;
}

// ---------------------------------------------------------------------------
// selection: stable rank -> top-16 / bottom-48, index-ordered
// ---------------------------------------------------------------------------
__global__ void select_kernel()
{
    int b  = blockIdx.x;
    int c  = b & 63;
    int nh = b >> 6;
    int i  = threadIdx.x;
    __shared__ float nrm[64];
    __shared__ int   sel[64];
    nrm[i] = g_norm[(size_t)nh * TT + c * SELC + i];
    __syncthreads();
    float mine = nrm[i];
    int rank = 0;
    #pragma unroll 8
    for (int j = 0; j < 64; j++) {
        float oj = nrm[j];
        rank += (oj < mine) || (oj == mine && j < i);
    }
    sel[i] = (rank >= SELC - TOPK) ? 1 : 0;
    __syncthreads();
    int gcnt = 0;
    for (int j = 0; j < i; j++) gcnt += sel[j];
    if (sel[i]) g_gidx[nh * 1024 + c * TOPK + gcnt] = c * SELC + i;
    else        g_lidx[nh * 3072 + c * (SELC - TOPK) + (i - gcnt)] = c * SELC + i;
}

// ---------------------------------------------------------------------------
// Global pass: 64 queries/block x 2 half-threads (32 dims each).
// ---------------------------------------------------------------------------
__global__ __launch_bounds__(128) void attn_global(const float* __restrict__ mask)
{
    int qb = blockIdx.x;
    int h  = blockIdx.y, n = blockIdx.z;
    int nh = n * NHD + h;
    __shared__ float ks[48][DH];
    __shared__ float vs[48][DH];
    __shared__ float am[48];
    __shared__ float sc[48][SELC];
    int tid = threadIdx.x;

    for (int idx = tid; idx < 48 * DH; idx += 128) {
        int s = idx >> 6, d = idx & 63;
        int gs = qb * 16 - 16 + s;
        if (gs >= 0 && gs < 1024) {
            int tok = g_gidx[nh * 1024 + gs];
            ks[s][d] = g_k[((size_t)nh * TT + tok) * DH + d];
            vs[s][d] = g_v[((size_t)nh * TT + tok) * DH + d];
            if (d == 0) am[s] = mask[n * TT + tok];
        } else {
            ks[s][d] = 0.f; vs[s][d] = 0.f;
            if (d == 0) am[s] = -1e30f;
        }
    }
    __syncthreads();

    int q = tid >> 1, half = tid & 1;
    int qt = qb * SELC + q;
    int dbase = half * 32;
    float qreg[32];
    const float* qp = &g_q[((size_t)nh * TT + qt) * DH + dbase];
    #pragma unroll
    for (int d = 0; d < 32; d++) qreg[d] = qp[d];

    float m = -1e30f;
    for (int s = 0; s < 48; s++) {
        float dot = 0.f;
        #pragma unroll
        for (int d = 0; d < 32; d += 4) {
            float4 kv = *(const float4*)&ks[s][dbase + d];
            dot += qreg[d]*kv.x + qreg[d+1]*kv.y + qreg[d+2]*kv.z + qreg[d+3]*kv.w;
        }
        dot += __shfl_xor_sync(0xffffffffu, dot, 1);
        float a = am[s];
        float v = (a > -1e29f) ? dot * 0.125f + a : -1e30f;
        if (half == 0) sc[s][q] = v;
        m = fmaxf(m, v);
    }
    __syncwarp();

    float l = 0.f;
    float acc[32];
    #pragma unroll
    for (int d = 0; d < 32; d++) acc[d] = 0.f;
    for (int s = 0; s < 48; s++) {
        float v = sc[s][q];
        float p = (v > -1e29f) ? expf(v - m) : 0.f;
        l += p;
        #pragma unroll
        for (int d = 0; d < 32; d += 4) {
            float4 vv = *(const float4*)&vs[s][dbase + d];
            acc[d]   += p * vv.x; acc[d+1] += p * vv.y;
            acc[d+2] += p * vv.z; acc[d+3] += p * vv.w;
        }
    }
    float inv = 1.f / l;
    float* cg = &g_ctxg[((size_t)nh * TT + qt) * DH + dbase];
    #pragma unroll
    for (int d = 0; d < 32; d++) cg[d] = acc[d] * inv;
    if (half == 0) g_lseg[nh * TT + qt] = m + logf(l);
}

// ---------------------------------------------------------------------------
// Local pass + merge: 128 queries/block x 2 half-threads.
// ---------------------------------------------------------------------------
__global__ __launch_bounds__(256) void attn_local(const float* __restrict__ mask,
                                                  float* __restrict__ out)
{
    int qb = blockIdx.x;
    int h  = blockIdx.y, n = blockIdx.z;
    int nh = n * NHD + h;
    __shared__ float ks[32][DH];
    __shared__ float vs[32][DH];
    __shared__ float am[32];
    __shared__ int   toks[32];
    __shared__ float sc[32][128];

    int tid = threadIdx.x;
    int q = tid >> 1, half = tid & 1;
    int qt = qb * LOCC + q;
    int dbase = half * 32;
    float qreg[32];
    const float* qp = &g_q[((size_t)nh * TT + qt) * DH + dbase];
    #pragma unroll
    for (int d = 0; d < 32; d++) qreg[d] = qp[d];

    float acc[32];
    #pragma unroll
    for (int d = 0; d < 32; d++) acc[d] = 0.f;
    float m = -1e30f, l = 0.f;
    int base = qb * 96 - 96;

    for (int t0 = 0; t0 < 288; t0 += 32) {
        if (tid < 32) {
            int gs = base + t0 + tid;
            int tok = (gs >= 0 && gs < 3072) ? g_lidx[nh * 3072 + gs] : -1;
            toks[tid] = tok;
            am[tid] = (tok >= 0) ? mask[n * TT + tok] : -1e30f;
        }
        __syncthreads();
        for (int idx = tid; idx < 32 * DH; idx += 256) {
            int s = idx >> 6, d = idx & 63;
            int tok = toks[s];
            if (tok >= 0) {
                ks[s][d] = g_k[((size_t)nh * TT + tok) * DH + d];
                vs[s][d] = g_v[((size_t)nh * TT + tok) * DH + d];
            } else { ks[s][d] = 0.f; vs[s][d] = 0.f; }
        }
        __syncthreads();

        float tmax = -1e30f;
        for (int s = 0; s < 32; s++) {
            float dot = 0.f;
            #pragma unroll
            for (int d = 0; d < 32; d += 4) {
                float4 kv = *(const float4*)&ks[s][dbase + d];
                dot += qreg[d]*kv.x + qreg[d+1]*kv.y + qreg[d+2]*kv.z + qreg[d+3]*kv.w;
            }
            dot += __shfl_xor_sync(0xffffffffu, dot, 1);
            float a = am[s];
            float v = (a > -1e29f) ? dot * 0.125f + a : -1e30f;
            if (half == 0) sc[s][q] = v;
            tmax = fmaxf(tmax, v);
        }
        __syncwarp();
        if (tmax > -1e29f) {
            float newm = fmaxf(m, tmax);
            float scale = expf(m - newm);
            l *= scale;
            #pragma unroll
            for (int d = 0; d < 32; d++) acc[d] *= scale;
            for (int s = 0; s < 32; s++) {
                float v = sc[s][q];
                float p = (v > -1e29f) ? expf(v - newm) : 0.f;
                l += p;
                #pragma unroll
                for (int d = 0; d < 32; d += 4) {
                    float4 vv = *(const float4*)&vs[s][dbase + d];
                    acc[d]   += p * vv.x; acc[d+1] += p * vv.y;
                    acc[d+2] += p * vv.z; acc[d+3] += p * vv.w;
                }
            }
            m = newm;
        }
        __syncthreads();
    }

    // appended global key (token 0, additive mask 0)
    {
        const float* k0 = &g_k[(size_t)nh * TT * DH + dbase];
        const float* v0 = &g_v[(size_t)nh * TT * DH + dbase];
        float dot = 0.f;
        #pragma unroll
        for (int d = 0; d < 32; d++) dot += qreg[d] * k0[d];
        dot += __shfl_xor_sync(0xffffffffu, dot, 1);
        float s = dot * 0.125f;
        float newm = fmaxf(m, s);
        float scale = expf(m - newm);
        float p = expf(s - newm);
        l = l * scale + p;
        #pragma unroll
        for (int d = 0; d < 32; d++) acc[d] = acc[d] * scale + p * v0[d];
        m = newm;
    }

    float lsel = m + logf(l);
    float lseg = g_lseg[nh * TT + qt];
    float pmix = 1.f / (1.f + expf(lseg - lsel));
    const float* cg = &g_ctxg[((size_t)nh * TT + qt) * DH + dbase];
    float invl = 1.f / l;
    float* op = &out[((size_t)n * TT + qt) * HID + h * DH + dbase];
    #pragma unroll
    for (int d = 0; d < 32; d++) {
        float cl = acc[d] * invl;
        float gv = cg[d];
        op[d] = gv + pmix * (cl - gv);
    }
}

// ---------------------------------------------------------------------------
// BOS: token-0 query, full UNscaled attention over all 4096 keys + mask.
// ---------------------------------------------------------------------------
__global__ __launch_bounds__(512) void attn_bos(const float* __restrict__ mask,
                                                float* __restrict__ out)
{
    int h = blockIdx.x, n = blockIdx.y;
    int nh = n * NHD + h;
    __shared__ float sc[TT];
    __shared__ float q0s[DH];
    __shared__ float red[512];
    __shared__ float part[8][DH];
    int tid = threadIdx.x;
    if (tid < DH) q0s[tid] = g_q[(size_t)nh * TT * DH + tid];
    __syncthreads();

    float lmax = -1e30f;
    for (int t = tid; t < TT; t += 512) {
        const float* kp = &g_k[((size_t)nh * TT + t) * DH];
        float dot = 0.f;
        #pragma unroll
        for (int d = 0; d < DH; d += 4) {
            float4 kv = *(const float4*)&kp[d];
            dot += q0s[d]*kv.x + q0s[d+1]*kv.y + q0s[d+2]*kv.z + q0s[d+3]*kv.w;
        }
        float s = dot + mask[n * TT + t];
        sc[t] = s;
        lmax = fmaxf(lmax, s);
    }
    red[tid] = lmax; __syncthreads();
    for (int o = 256; o > 0; o >>= 1) {
        if (tid < o) red[tid] = fmaxf(red[tid], red[tid + o]);
        __syncthreads();
    }
    float mx = red[0]; __syncthreads();

    float ls = 0.f;
    for (int t = tid; t < TT; t += 512) {
        float p = expf(sc[t] - mx);
        sc[t] = p;
        ls += p;
    }
    red[tid] = ls; __syncthreads();
    for (int o = 256; o > 0; o >>= 1) {
        if (tid < o) red[tid] += red[tid + o];
        __syncthreads();
    }
    float inv = 1.f / red[0];
    __syncthreads();

    {
        int d = tid & 63, sl = tid >> 6;
        float a = 0.f;
        int tstart = sl * 512;
        for (int t = tstart; t < tstart + 512; t++)
            a += sc[t] * g_v[((size_t)nh * TT + t) * DH + d];
        part[sl][d] = a;
    }
    __syncthreads();
    if (tid < DH) {
        float a = 0.f;
        #pragma unroll
        for (int sl = 0; sl < 8; sl++) a += part[sl][tid];
        out[(size_t)n * TT * HID + h * DH + tid] = a * inv;
    }
}

// ---------------------------------------------------------------------------
extern "C" void kernel_launch(void* const* d_in, const int* in_sizes, int n_in,
                              void* d_out, int out_size)
{
    const float* hs   = (const float*)d_in[0];
    const float* mask = (const float*)d_in[1];
    const float* Wq   = (const float*)d_in[2];
    const float* bq   = (const float*)d_in[3];
    const float* Wk   = (const float*)d_in[4];
    const float* bk   = (const float*)d_in[5];
    const float* Wv   = (const float*)d_in[6];
    const float* bv   = (const float*)d_in[7];
    float* out = (float*)d_out;

    static int attr_done = 0;
    if (!attr_done) {
        cudaFuncSetAttribute(gemm_f16, cudaFuncAttributeMaxDynamicSharedMemorySize,
                             GEMM_SMEM);
        attr_done = 1;
    }

    // resolve device-global scratch addresses (host side)
    __half *ah, *al, *wh, *wl;
    cudaGetSymbolAddress((void**)&ah, g_ah);
    cudaGetSymbolAddress((void**)&al, g_al);
    cudaGetSymbolAddress((void**)&wh, g_wh);
    cudaGetSymbolAddress((void**)&wl, g_wl);

    const int nA4 = 8192 * 1024 / 4;     // 2097152
    const int nW4 = 1024 * 1024 / 4;     // 262144
    split_f16<<<(nA4 + 255) / 256, 256>>>(hs, ah, al, nA4);
    split_f16<<<(nW4 + 255) / 256, 256>>>(Wq, wh,            wl,            nW4);
    split_f16<<<(nW4 + 255) / 256, 256>>>(Wk, wh + 1048576,  wl + 1048576,  nW4);
    split_f16<<<(nW4 + 255) / 256, 256>>>(Wv, wh + 2097152,  wl + 2097152,  nW4);

    gemm_f16<<<dim3(8, 64, 3), 256, GEMM_SMEM>>>(bq, bk, bv);

    norm_kernel<<<(NB * NHD * TT + 255) / 256, 256>>>(bq, mask);
    select_kernel<<<NB * NHD * 64, 64>>>();
    attn_global<<<dim3(64, NHD, NB), 128>>>(mask);
    attn_local<<<dim3(32, NHD, NB), 256>>>(mask, out);
    attn_bos<<<dim3(NHD, NB), 512>>>(mask, out);
}

// round 7
// speedup vs baseline: 1.5282x; 1.0503x over previous
#include <cuda_runtime.h>
#include <cuda_fp16.h>
#include <math.h>
#include <stdint.h>

// Problem dims
#define NB   2
#define TT   4096
#define NHD  16      // heads
#define DH   64      // head dim
#define HID  1024
#define SELC 64
#define TOPK 16
#define LOCC 128

// Scratch (device globals: allocation-free rule)
__device__ float g_q[(size_t)NB*NHD*TT*DH];
__device__ float g_k[(size_t)NB*NHD*TT*DH];
__device__ float g_v[(size_t)NB*NHD*TT*DH];
__device__ float g_ctxg[(size_t)NB*NHD*TT*DH];
__device__ float g_lseg[NB*NHD*TT];
__device__ float g_norm[NB*NHD*TT];
__device__ int   g_gidx[NB*NHD*1024];
__device__ int   g_lidx[NB*NHD*3072];

// fp16 split scratch
__device__ __half g_ah[(size_t)8192*1024];
__device__ __half g_al[(size_t)8192*1024];
__device__ __half g_wh[(size_t)3*1024*1024];
__device__ __half g_wl[(size_t)3*1024*1024];

// ---------------------------------------------------------------------------
// PTX helpers (plain PTX only — valid on target sm_103)
// ---------------------------------------------------------------------------
#define MMA_F16(c, a, b0, b1) \
    asm volatile("mma.sync.aligned.m16n8k16.row.col.f32.f16.f16.f32 " \
        "{%0,%1,%2,%3}, {%4,%5,%6,%7}, {%8,%9}, {%0,%1,%2,%3};" \
        : "+f"((c)[0]), "+f"((c)[1]), "+f"((c)[2]), "+f"((c)[3]) \
        : "r"((a)[0]), "r"((a)[1]), "r"((a)[2]), "r"((a)[3]), "r"(b0), "r"(b1))

#define LDSM_X4(r, addr) \
    asm volatile("ldmatrix.sync.aligned.m8n8.x4.shared.b16 {%0,%1,%2,%3}, [%4];" \
        : "=r"((r)[0]), "=r"((r)[1]), "=r"((r)[2]), "=r"((r)[3]) : "r"(addr))

__device__ __forceinline__ void cp16(uint32_t dst, const void* src) {
    asm volatile("cp.async.cg.shared.global [%0], [%1], 16;" :: "r"(dst), "l"(src));
}
#define CP_COMMIT() asm volatile("cp.async.commit_group;" ::: "memory")
#define CP_WAIT2()  asm volatile("cp.async.wait_group 2;" ::: "memory")

// ---------------------------------------------------------------------------
// fp32 -> (fp16 hi, fp16 lo) split, vectorized x4
// ---------------------------------------------------------------------------
__global__ void split_f16(const float* __restrict__ src, __half* __restrict__ hi,
                          __half* __restrict__ lo, int n4)
{
    int i = blockIdx.x * 256 + threadIdx.x;
    if (i >= n4) return;
    float4 v = ((const float4*)src)[i];
    __half h[4], l[4];
    h[0] = __float2half_rn(v.x); l[0] = __float2half_rn(v.x - __half2float(h[0]));
    h[1] = __float2half_rn(v.y); l[1] = __float2half_rn(v.y - __half2float(h[1]));
    h[2] = __float2half_rn(v.z); l[2] = __float2half_rn(v.z - __half2float(h[2]));
    h[3] = __float2half_rn(v.w); l[3] = __float2half_rn(v.w - __half2float(h[3]));
    ((uint2*)hi)[i] = *(uint2*)h;
    ((uint2*)lo)[i] = *(uint2*)l;
}

// ---------------------------------------------------------------------------
// fp16 mma GEMM, split-3 accumulation as virtual K=3072:
//   C = Ahi.Whi^T + Ahi.Wlo^T + Alo.Whi^T + bias   (error ~2^-22)
// CTA 128x128, BK=32, 8 warps (warp tile 32x64), 4-stage cp.async pipeline.
// Fragment loads via ldmatrix.x4 (12 LDSM per warp-chunk vs 48 LDS.32).
// z selects Q/K/V. Output scattered to (n,h,t,d).
// ---------------------------------------------------------------------------
#define NCH  96                    // 3 phases x 32 chunks of K=32
#define STG_BYTES 20480            // A: 128 rows x 80B + B: same
#define GEMM_SMEM (4 * STG_BYTES)  // 81920

__global__ __launch_bounds__(256, 2) void gemm_f16(
    const float* __restrict__ bq, const float* __restrict__ bk,
    const float* __restrict__ bv)
{
    extern __shared__ char smc[];
    uint32_t sbase;
    asm("{ .reg .u64 t; cvta.to.shared.u64 t, %1; cvt.u32.u64 %0, t; }"
        : "=r"(sbase) : "l"(smc));

    const int z = blockIdx.z;
    float* out = (z == 0) ? g_q : (z == 1) ? g_k : g_v;
    const float* bias = (z == 0) ? bq : (z == 1) ? bk : bv;
    const __half* Whi = g_wh + (size_t)z * 1048576;
    const __half* Wlo = g_wl + (size_t)z * 1048576;

    const int tid = threadIdx.x;
    const int wid = tid >> 5, lane = tid & 31;
    const int gid = lane >> 2, tq = lane & 3;
    const int row0 = blockIdx.y * 128, col0 = blockIdx.x * 128;
    const int warpM = (wid & 3) * 32, warpN = (wid >> 2) * 64;

    float acc[2][8][4];
    #pragma unroll
    for (int i = 0; i < 2; i++)
        #pragma unroll
        for (int j = 0; j < 8; j++)
            #pragma unroll
            for (int r = 0; r < 4; r++) acc[i][j][r] = 0.f;

    const int crow = tid >> 1;     // 0..127
    const int h2 = tid & 1;        // which 32B half-row

    // ldmatrix per-lane byte offsets (within a stage)
    const int lg = lane >> 3;      // lane group 0..3
    const int lr = lane & 7;
    // A fragments: matrix g: rows warpM + mt*16 + (g&1)*8 + lr, k-halfbyte (g>>1)*16
    uint32_t aoff[2];
    #pragma unroll
    for (int mt = 0; mt < 2; mt++)
        aoff[mt] = (uint32_t)((warpM + mt * 16 + (lg & 1) * 8 + lr) * 80 + (lg >> 1) * 16);
    // B fragments: pair p: matrix g: rows warpN + p*16 + (g>>1)*8 + lr, k (g&1)*16
    uint32_t boff[4];
    #pragma unroll
    for (int p = 0; p < 4; p++)
        boff[p] = (uint32_t)(10240 + (warpN + p * 16 + (lg >> 1) * 8 + lr) * 80 + (lg & 1) * 16);

    auto issue_copy = [&](int c, int stg) {
        int kv = c * 32;
        int ph = kv >> 10;
        int kl = kv & 1023;
        const __half* aS = (ph == 2) ? g_al : g_ah;
        const __half* bS = (ph == 1) ? Wlo : Whi;
        const __half* asrc = aS + (size_t)(row0 + crow) * 1024 + kl + h2 * 16;
        const __half* bsrc = bS + (size_t)(col0 + crow) * 1024 + kl + h2 * 16;
        uint32_t ad = sbase + stg * STG_BYTES + crow * 80 + h2 * 32;
        uint32_t bd = ad + 10240;
        cp16(ad, asrc);      cp16(ad + 16, asrc + 8);
        cp16(bd, bsrc);      cp16(bd + 16, bsrc + 8);
    };

    // prefetch 3 chunks
    #pragma unroll
    for (int s = 0; s < 3; s++) { issue_copy(s, s); CP_COMMIT(); }

    for (int c = 0; c < NCH; c++) {
        CP_WAIT2();
        __syncthreads();
        int cn = c + 3;
        if (cn < NCH) issue_copy(cn, cn & 3);
        CP_COMMIT();

        const uint32_t sstage = sbase + (c & 3) * STG_BYTES;
        #pragma unroll
        for (int ks = 0; ks < 2; ks++) {
            const uint32_t ko = ks * 32;
            uint32_t a0[4], a1[4];
            LDSM_X4(a0, sstage + aoff[0] + ko);
            LDSM_X4(a1, sstage + aoff[1] + ko);
            #pragma unroll
            for (int p = 0; p < 4; p++) {
                uint32_t br[4];
                LDSM_X4(br, sstage + boff[p] + ko);
                MMA_F16(acc[0][2*p],   a0, br[0], br[1]);
                MMA_F16(acc[1][2*p],   a1, br[0], br[1]);
                MMA_F16(acc[0][2*p+1], a0, br[2], br[3]);
                MMA_F16(acc[1][2*p+1], a1, br[2], br[3]);
            }
        }
    }

    // Epilogue: warp spans 64 cols = one head.
    const int hcol = col0 + warpN;
    const int h = hcol >> 6;
    float2 bb[8];
    #pragma unroll
    for (int nt = 0; nt < 8; nt++) {
        int cc = hcol + nt * 8 + 2 * tq;
        bb[nt].x = bias[cc];
        bb[nt].y = bias[cc + 1];
    }
    #pragma unroll
    for (int mt = 0; mt < 2; mt++) {
        #pragma unroll
        for (int rr = 0; rr < 2; rr++) {
            int grow = row0 + warpM + mt * 16 + gid + rr * 8;
            int nn = grow >> 12, t = grow & 4095;
            float* p = out + (((size_t)(nn * NHD + h)) * TT + t) * DH;
            #pragma unroll
            for (int nt = 0; nt < 8; nt++) {
                float2 v;
                v.x = acc[mt][nt][rr * 2]     + bb[nt].x;
                v.y = acc[mt][nt][rr * 2 + 1] + bb[nt].y;
                *(float2*)(p + nt * 8 + 2 * tq) = v;
            }
        }
    }
}

// ---------------------------------------------------------------------------
// norms: ||k[n,h,t,:] + bq[h*64:]||^2 * (mask[n,t]==0)
// ---------------------------------------------------------------------------
__global__ void norm_kernel(const float* __restrict__ bq, const float* __restrict__ mask)
{
    int g = blockIdx.x * 256 + threadIdx.x;
    if (g >= NB * NHD * TT) return;
    int t = g & (TT - 1);
    int h = (g >> 12) & (NHD - 1);
    int n = g >> 16;
    const float* kp = &g_k[(size_t)g * DH];
    const float* bh = &bq[h * DH];
    float s = 0.f;
    #pragma unroll
    for (int d = 0; d < DH; d += 4) {
        float4 kv = *(const float4*)&kp[d];
        float x0 = kv.x + bh[d+0];
        float x1 = kv.y + bh[d+1];
        float x2 = kv.z + bh[d+2];
        float x3 = kv.w + bh[d+3];
        s += x0*x0 + x1*x1 + x2*x2 + x3*x3;
    }
    float valid = (mask[n * TT + t] == 0.0f) ? 1.0f : 0.0f;
    g_norm[g] = s * valid;
}

// ---------------------------------------------------------------------------
// selection: stable rank -> top-16 / bottom-48, index-ordered
// ---------------------------------------------------------------------------
__global__ void select_kernel()
{
    int b  = blockIdx.x;
    int c  = b & 63;
    int nh = b >> 6;
    int i  = threadIdx.x;
    __shared__ float nrm[64];
    __shared__ int   sel[64];
    nrm[i] = g_norm[(size_t)nh * TT + c * SELC + i];
    __syncthreads();
    float mine = nrm[i];
    int rank = 0;
    #pragma unroll 8
    for (int j = 0; j < 64; j++) {
        float oj = nrm[j];
        rank += (oj < mine) || (oj == mine && j < i);
    }
    sel[i] = (rank >= SELC - TOPK) ? 1 : 0;
    __syncthreads();
    int gcnt = 0;
    for (int j = 0; j < i; j++) gcnt += sel[j];
    if (sel[i]) g_gidx[nh * 1024 + c * TOPK + gcnt] = c * SELC + i;
    else        g_lidx[nh * 3072 + c * (SELC - TOPK) + (i - gcnt)] = c * SELC + i;
}

// ---------------------------------------------------------------------------
// Global pass: 64 queries/block x 2 half-threads (32 dims each).
// ---------------------------------------------------------------------------
__global__ __launch_bounds__(128) void attn_global(const float* __restrict__ mask)
{
    int qb = blockIdx.x;
    int h  = blockIdx.y, n = blockIdx.z;
    int nh = n * NHD + h;
    __shared__ float ks[48][DH];
    __shared__ float vs[48][DH];
    __shared__ float am[48];
    __shared__ float sc[48][SELC];
    int tid = threadIdx.x;

    for (int idx = tid; idx < 48 * DH; idx += 128) {
        int s = idx >> 6, d = idx & 63;
        int gs = qb * 16 - 16 + s;
        if (gs >= 0 && gs < 1024) {
            int tok = g_gidx[nh * 1024 + gs];
            ks[s][d] = g_k[((size_t)nh * TT + tok) * DH + d];
            vs[s][d] = g_v[((size_t)nh * TT + tok) * DH + d];
            if (d == 0) am[s] = mask[n * TT + tok];
        } else {
            ks[s][d] = 0.f; vs[s][d] = 0.f;
            if (d == 0) am[s] = -1e30f;
        }
    }
    __syncthreads();

    int q = tid >> 1, half = tid & 1;
    int qt = qb * SELC + q;
    int dbase = half * 32;
    float qreg[32];
    const float* qp = &g_q[((size_t)nh * TT + qt) * DH + dbase];
    #pragma unroll
    for (int d = 0; d < 32; d++) qreg[d] = qp[d];

    float m = -1e30f;
    for (int s = 0; s < 48; s++) {
        float dot = 0.f;
        #pragma unroll
        for (int d = 0; d < 32; d += 4) {
            float4 kv = *(const float4*)&ks[s][dbase + d];
            dot += qreg[d]*kv.x + qreg[d+1]*kv.y + qreg[d+2]*kv.z + qreg[d+3]*kv.w;
        }
        dot += __shfl_xor_sync(0xffffffffu, dot, 1);
        float a = am[s];
        float v = (a > -1e29f) ? dot * 0.125f + a : -1e30f;
        if (half == 0) sc[s][q] = v;
        m = fmaxf(m, v);
    }
    __syncwarp();

    float l = 0.f;
    float acc[32];
    #pragma unroll
    for (int d = 0; d < 32; d++) acc[d] = 0.f;
    for (int s = 0; s < 48; s++) {
        float v = sc[s][q];
        float p = (v > -1e29f) ? expf(v - m) : 0.f;
        l += p;
        #pragma unroll
        for (int d = 0; d < 32; d += 4) {
            float4 vv = *(const float4*)&vs[s][dbase + d];
            acc[d]   += p * vv.x; acc[d+1] += p * vv.y;
            acc[d+2] += p * vv.z; acc[d+3] += p * vv.w;
        }
    }
    float inv = 1.f / l;
    float* cg = &g_ctxg[((size_t)nh * TT + qt) * DH + dbase];
    #pragma unroll
    for (int d = 0; d < 32; d++) cg[d] = acc[d] * inv;
    if (half == 0) g_lseg[nh * TT + qt] = m + logf(l);
}

// ---------------------------------------------------------------------------
// Local pass + merge: 128 queries/block x 2 half-threads.
// ---------------------------------------------------------------------------
__global__ __launch_bounds__(256) void attn_local(const float* __restrict__ mask,
                                                  float* __restrict__ out)
{
    int qb = blockIdx.x;
    int h  = blockIdx.y, n = blockIdx.z;
    int nh = n * NHD + h;
    __shared__ float ks[32][DH];
    __shared__ float vs[32][DH];
    __shared__ float am[32];
    __shared__ int   toks[32];
    __shared__ float sc[32][128];

    int tid = threadIdx.x;
    int q = tid >> 1, half = tid & 1;
    int qt = qb * LOCC + q;
    int dbase = half * 32;
    float qreg[32];
    const float* qp = &g_q[((size_t)nh * TT + qt) * DH + dbase];
    #pragma unroll
    for (int d = 0; d < 32; d++) qreg[d] = qp[d];

    float acc[32];
    #pragma unroll
    for (int d = 0; d < 32; d++) acc[d] = 0.f;
    float m = -1e30f, l = 0.f;
    int base = qb * 96 - 96;

    for (int t0 = 0; t0 < 288; t0 += 32) {
        if (tid < 32) {
            int gs = base + t0 + tid;
            int tok = (gs >= 0 && gs < 3072) ? g_lidx[nh * 3072 + gs] : -1;
            toks[tid] = tok;
            am[tid] = (tok >= 0) ? mask[n * TT + tok] : -1e30f;
        }
        __syncthreads();
        for (int idx = tid; idx < 32 * DH; idx += 256) {
            int s = idx >> 6, d = idx & 63;
            int tok = toks[s];
            if (tok >= 0) {
                ks[s][d] = g_k[((size_t)nh * TT + tok) * DH + d];
                vs[s][d] = g_v[((size_t)nh * TT + tok) * DH + d];
            } else { ks[s][d] = 0.f; vs[s][d] = 0.f; }
        }
        __syncthreads();

        float tmax = -1e30f;
        for (int s = 0; s < 32; s++) {
            float dot = 0.f;
            #pragma unroll
            for (int d = 0; d < 32; d += 4) {
                float4 kv = *(const float4*)&ks[s][dbase + d];
                dot += qreg[d]*kv.x + qreg[d+1]*kv.y + qreg[d+2]*kv.z + qreg[d+3]*kv.w;
            }
            dot += __shfl_xor_sync(0xffffffffu, dot, 1);
            float a = am[s];
            float v = (a > -1e29f) ? dot * 0.125f + a : -1e30f;
            if (half == 0) sc[s][q] = v;
            tmax = fmaxf(tmax, v);
        }
        __syncwarp();
        if (tmax > -1e29f) {
            float newm = fmaxf(m, tmax);
            float scale = expf(m - newm);
            l *= scale;
            #pragma unroll
            for (int d = 0; d < 32; d++) acc[d] *= scale;
            for (int s = 0; s < 32; s++) {
                float v = sc[s][q];
                float p = (v > -1e29f) ? expf(v - newm) : 0.f;
                l += p;
                #pragma unroll
                for (int d = 0; d < 32; d += 4) {
                    float4 vv = *(const float4*)&vs[s][dbase + d];
                    acc[d]   += p * vv.x; acc[d+1] += p * vv.y;
                    acc[d+2] += p * vv.z; acc[d+3] += p * vv.w;
                }
            }
            m = newm;
        }
        __syncthreads();
    }

    // appended global key (token 0, additive mask 0)
    {
        const float* k0 = &g_k[(size_t)nh * TT * DH + dbase];
        const float* v0 = &g_v[(size_t)nh * TT * DH + dbase];
        float dot = 0.f;
        #pragma unroll
        for (int d = 0; d < 32; d++) dot += qreg[d] * k0[d];
        dot += __shfl_xor_sync(0xffffffffu, dot, 1);
        float s = dot * 0.125f;
        float newm = fmaxf(m, s);
        float scale = expf(m - newm);
        float p = expf(s - newm);
        l = l * scale + p;
        #pragma unroll
        for (int d = 0; d < 32; d++) acc[d] = acc[d] * scale + p * v0[d];
        m = newm;
    }

    float lsel = m + logf(l);
    float lseg = g_lseg[nh * TT + qt];
    float pmix = 1.f / (1.f + expf(lseg - lsel));
    const float* cg = &g_ctxg[((size_t)nh * TT + qt) * DH + dbase];
    float invl = 1.f / l;
    float* op = &out[((size_t)n * TT + qt) * HID + h * DH + dbase];
    #pragma unroll
    for (int d = 0; d < 32; d++) {
        float cl = acc[d] * invl;
        float gv = cg[d];
        op[d] = gv + pmix * (cl - gv);
    }
}

// ---------------------------------------------------------------------------
// BOS: token-0 query, full UNscaled attention over all 4096 keys + mask.
// ---------------------------------------------------------------------------
__global__ __launch_bounds__(512) void attn_bos(const float* __restrict__ mask,
                                                float* __restrict__ out)
{
    int h = blockIdx.x, n = blockIdx.y;
    int nh = n * NHD + h;
    __shared__ float sc[TT];
    __shared__ float q0s[DH];
    __shared__ float red[512];
    __shared__ float part[8][DH];
    int tid = threadIdx.x;
    if (tid < DH) q0s[tid] = g_q[(size_t)nh * TT * DH + tid];
    __syncthreads();

    float lmax = -1e30f;
    for (int t = tid; t < TT; t += 512) {
        const float* kp = &g_k[((size_t)nh * TT + t) * DH];
        float dot = 0.f;
        #pragma unroll
        for (int d = 0; d < DH; d += 4) {
            float4 kv = *(const float4*)&kp[d];
            dot += q0s[d]*kv.x + q0s[d+1]*kv.y + q0s[d+2]*kv.z + q0s[d+3]*kv.w;
        }
        float s = dot + mask[n * TT + t];
        sc[t] = s;
        lmax = fmaxf(lmax, s);
    }
    red[tid] = lmax; __syncthreads();
    for (int o = 256; o > 0; o >>= 1) {
        if (tid < o) red[tid] = fmaxf(red[tid], red[tid + o]);
        __syncthreads();
    }
    float mx = red[0]; __syncthreads();

    float ls = 0.f;
    for (int t = tid; t < TT; t += 512) {
        float p = expf(sc[t] - mx);
        sc[t] = p;
        ls += p;
    }
    red[tid] = ls; __syncthreads();
    for (int o = 256; o > 0; o >>= 1) {
        if (tid < o) red[tid] += red[tid + o];
        __syncthreads();
    }
    float inv = 1.f / red[0];
    __syncthreads();

    {
        int d = tid & 63, sl = tid >> 6;
        float a = 0.f;
        int tstart = sl * 512;
        for (int t = tstart; t < tstart + 512; t++)
            a += sc[t] * g_v[((size_t)nh * TT + t) * DH + d];
        part[sl][d] = a;
    }
    __syncthreads();
    if (tid < DH) {
        float a = 0.f;
        #pragma unroll
        for (int sl = 0; sl < 8; sl++) a += part[sl][tid];
        out[(size_t)n * TT * HID + h * DH + tid] = a * inv;
    }
}

// ---------------------------------------------------------------------------
extern "C" void kernel_launch(void* const* d_in, const int* in_sizes, int n_in,
                              void* d_out, int out_size)
{
    const float* hs   = (const float*)d_in[0];
    const float* mask = (const float*)d_in[1];
    const float* Wq   = (const float*)d_in[2];
    const float* bq   = (const float*)d_in[3];
    const float* Wk   = (const float*)d_in[4];
    const float* bk   = (const float*)d_in[5];
    const float* Wv   = (const float*)d_in[6];
    const float* bv   = (const float*)d_in[7];
    float* out = (float*)d_out;

    static int attr_done = 0;
    if (!attr_done) {
        cudaFuncSetAttribute(gemm_f16, cudaFuncAttributeMaxDynamicSharedMemorySize,
                             GEMM_SMEM);
        attr_done = 1;
    }

    // resolve device-global scratch addresses (host side)
    __half *ah, *al, *wh, *wl;
    cudaGetSymbolAddress((void**)&ah, g_ah);
    cudaGetSymbolAddress((void**)&al, g_al);
    cudaGetSymbolAddress((void**)&wh, g_wh);
    cudaGetSymbolAddress((void**)&wl, g_wl);

    const int nA4 = 8192 * 1024 / 4;     // 2097152
    const int nW4 = 1024 * 1024 / 4;     // 262144
    split_f16<<<(nA4 + 255) / 256, 256>>>(hs, ah, al, nA4);
    split_f16<<<(nW4 + 255) / 256, 256>>>(Wq, wh,            wl,            nW4);
    split_f16<<<(nW4 + 255) / 256, 256>>>(Wk, wh + 1048576,  wl + 1048576,  nW4);
    split_f16<<<(nW4 + 255) / 256, 256>>>(Wv, wh + 2097152,  wl + 2097152,  nW4);

    gemm_f16<<<dim3(8, 64, 3), 256, GEMM_SMEM>>>(bq, bk, bv);

    norm_kernel<<<(NB * NHD * TT + 255) / 256, 256>>>(bq, mask);
    select_kernel<<<NB * NHD * 64, 64>>>();
    attn_global<<<dim3(64, NHD, NB), 128>>>(mask);
    attn_local<<<dim3(32, NHD, NB), 256>>>(mask, out);
    attn_bos<<<dim3(NHD, NB), 512>>>(mask, out);
}

// round 9
// speedup vs baseline: 1.8278x; 1.1961x over previous
#include <cuda_runtime.h>
#include <cuda_fp16.h>
#include <math.h>
#include <stdint.h>

// Problem dims
#define NB   2
#define TT   4096
#define NHD  16      // heads
#define DH   64      // head dim
#define HID  1024
#define SELC 64
#define TOPK 16
#define LOCC 128

// Scratch (device globals: allocation-free rule)
__device__ float g_q[(size_t)NB*NHD*TT*DH];
__device__ float g_k[(size_t)NB*NHD*TT*DH];
__device__ float g_v[(size_t)NB*NHD*TT*DH];
__device__ float g_ctxg[(size_t)NB*NHD*TT*DH];
__device__ float g_lseg[NB*NHD*TT];
__device__ float g_norm[NB*NHD*TT];
__device__ int   g_gidx[NB*NHD*1024];
__device__ int   g_lidx[NB*NHD*3072];

// fp16 split scratch
__device__ __half g_ah[(size_t)8192*1024];
__device__ __half g_al[(size_t)8192*1024];
__device__ __half g_wh[(size_t)3*1024*1024];
__device__ __half g_wl[(size_t)3*1024*1024];

// ---------------------------------------------------------------------------
// PTX helpers (plain PTX only — valid on target sm_103)
// ---------------------------------------------------------------------------
#define MMA_F16(c, a, b0, b1) \
    asm volatile("mma.sync.aligned.m16n8k16.row.col.f32.f16.f16.f32 " \
        "{%0,%1,%2,%3}, {%4,%5,%6,%7}, {%8,%9}, {%0,%1,%2,%3};" \
        : "+f"((c)[0]), "+f"((c)[1]), "+f"((c)[2]), "+f"((c)[3]) \
        : "r"((a)[0]), "r"((a)[1]), "r"((a)[2]), "r"((a)[3]), "r"(b0), "r"(b1))

#define LDSM_X4(r, addr) \
    asm volatile("ldmatrix.sync.aligned.m8n8.x4.shared.b16 {%0,%1,%2,%3}, [%4];" \
        : "=r"((r)[0]), "=r"((r)[1]), "=r"((r)[2]), "=r"((r)[3]) : "r"(addr))

__device__ __forceinline__ void cp16(uint32_t dst, const void* src) {
    asm volatile("cp.async.cg.shared.global [%0], [%1], 16;" :: "r"(dst), "l"(src));
}
#define CP_COMMIT() asm volatile("cp.async.commit_group;" ::: "memory")
#define CP_WAIT2()  asm volatile("cp.async.wait_group 2;" ::: "memory")

// ---------------------------------------------------------------------------
// fp32 -> (fp16 hi, fp16 lo) split, vectorized x4
// ---------------------------------------------------------------------------
__global__ void split_f16(const float* __restrict__ src, __half* __restrict__ hi,
                          __half* __restrict__ lo, int n4)
{
    int i = blockIdx.x * 256 + threadIdx.x;
    if (i >= n4) return;
    float4 v = ((const float4*)src)[i];
    __half h[4], l[4];
    h[0] = __float2half_rn(v.x); l[0] = __float2half_rn(v.x - __half2float(h[0]));
    h[1] = __float2half_rn(v.y); l[1] = __float2half_rn(v.y - __half2float(h[1]));
    h[2] = __float2half_rn(v.z); l[2] = __float2half_rn(v.z - __half2float(h[2]));
    h[3] = __float2half_rn(v.w); l[3] = __float2half_rn(v.w - __half2float(h[3]));
    ((uint2*)hi)[i] = *(uint2*)h;
    ((uint2*)lo)[i] = *(uint2*)l;
}

// ---------------------------------------------------------------------------
// fp16 mma GEMM. K (z==1): split-3 (Ahi.Whi + Ahi.Wlo + Alo.Whi), err ~2^-22.
// Q,V (z==0,2): exact-A x Whi (Ahi.Whi + Alo.Whi), err ~2.8e-4 — safe: Q/V
// feed continuous paths only; top-k selection depends only on K.
// CTA 128x128, BK=32, 8 warps (warp tile 32x64), 4-stage cp.async pipeline,
// ldmatrix.x4 fragment loads. Output scattered to (n,h,t,d).
// ---------------------------------------------------------------------------
#define STG_BYTES 20480            // A: 128 rows x 80B + B: same
#define GEMM_SMEM (4 * STG_BYTES)  // 81920

__global__ __launch_bounds__(256, 2) void gemm_f16(
    const float* __restrict__ bq, const float* __restrict__ bk,
    const float* __restrict__ bv)
{
    extern __shared__ char smc[];
    uint32_t sbase;
    asm("{ .reg .u64 t; cvta.to.shared.u64 t, %1; cvt.u32.u64 %0, t; }"
        : "=r"(sbase) : "l"(smc));

    const int z = blockIdx.z;
    float* out = (z == 0) ? g_q : (z == 1) ? g_k : g_v;
    const float* bias = (z == 0) ? bq : (z == 1) ? bk : bv;
    const __half* Whi = g_wh + (size_t)z * 1048576;
    const __half* Wlo = g_wl + (size_t)z * 1048576;
    const int nch = (z == 1) ? 96 : 64;

    const int tid = threadIdx.x;
    const int wid = tid >> 5, lane = tid & 31;
    const int gid = lane >> 2, tq = lane & 3;
    const int row0 = blockIdx.y * 128, col0 = blockIdx.x * 128;
    const int warpM = (wid & 3) * 32, warpN = (wid >> 2) * 64;

    float acc[2][8][4];
    #pragma unroll
    for (int i = 0; i < 2; i++)
        #pragma unroll
        for (int j = 0; j < 8; j++)
            #pragma unroll
            for (int r = 0; r < 4; r++) acc[i][j][r] = 0.f;

    const int crow = tid >> 1;     // 0..127
    const int h2 = tid & 1;        // which 32B half-row

    // ldmatrix per-lane byte offsets (within a stage)
    const int lg = lane >> 3;      // lane group 0..3
    const int lr = lane & 7;
    uint32_t aoff[2];
    #pragma unroll
    for (int mt = 0; mt < 2; mt++)
        aoff[mt] = (uint32_t)((warpM + mt * 16 + (lg & 1) * 8 + lr) * 80 + (lg >> 1) * 16);
    uint32_t boff[4];
    #pragma unroll
    for (int p = 0; p < 4; p++)
        boff[p] = (uint32_t)(10240 + (warpN + p * 16 + (lg >> 1) * 8 + lr) * 80 + (lg & 1) * 16);

    auto issue_copy = [&](int c, int stg) {
        int kv = c * 32;
        int ph = kv >> 10;
        int kl = kv & 1023;
        const __half* aS; const __half* bS;
        if (z == 1) { aS = (ph == 2) ? g_al : g_ah; bS = (ph == 1) ? Wlo : Whi; }
        else        { aS = (ph == 1) ? g_al : g_ah; bS = Whi; }
        const __half* asrc = aS + (size_t)(row0 + crow) * 1024 + kl + h2 * 16;
        const __half* bsrc = bS + (size_t)(col0 + crow) * 1024 + kl + h2 * 16;
        uint32_t ad = sbase + stg * STG_BYTES + crow * 80 + h2 * 32;
        uint32_t bd = ad + 10240;
        cp16(ad, asrc);      cp16(ad + 16, asrc + 8);
        cp16(bd, bsrc);      cp16(bd + 16, bsrc + 8);
    };

    // prefetch 3 chunks
    #pragma unroll
    for (int s = 0; s < 3; s++) { issue_copy(s, s); CP_COMMIT(); }

    for (int c = 0; c < nch; c++) {
        CP_WAIT2();
        __syncthreads();
        int cn = c + 3;
        if (cn < nch) issue_copy(cn, cn & 3);
        CP_COMMIT();

        const uint32_t sstage = sbase + (c & 3) * STG_BYTES;
        #pragma unroll
        for (int ks = 0; ks < 2; ks++) {
            const uint32_t ko = ks * 32;
            uint32_t a0[4], a1[4];
            LDSM_X4(a0, sstage + aoff[0] + ko);
            LDSM_X4(a1, sstage + aoff[1] + ko);
            #pragma unroll
            for (int p = 0; p < 4; p++) {
                uint32_t br[4];
                LDSM_X4(br, sstage + boff[p] + ko);
                MMA_F16(acc[0][2*p],   a0, br[0], br[1]);
                MMA_F16(acc[1][2*p],   a1, br[0], br[1]);
                MMA_F16(acc[0][2*p+1], a0, br[2], br[3]);
                MMA_F16(acc[1][2*p+1], a1, br[2], br[3]);
            }
        }
    }

    // Epilogue: warp spans 64 cols = one head.
    const int hcol = col0 + warpN;
    const int h = hcol >> 6;
    float2 bb[8];
    #pragma unroll
    for (int nt = 0; nt < 8; nt++) {
        int cc = hcol + nt * 8 + 2 * tq;
        bb[nt].x = bias[cc];
        bb[nt].y = bias[cc + 1];
    }
    #pragma unroll
    for (int mt = 0; mt < 2; mt++) {
        #pragma unroll
        for (int rr = 0; rr < 2; rr++) {
            int grow = row0 + warpM + mt * 16 + gid + rr * 8;
            int nn = grow >> 12, t = grow & 4095;
            float* p = out + (((size_t)(nn * NHD + h)) * TT + t) * DH;
            #pragma unroll
            for (int nt = 0; nt < 8; nt++) {
                float2 v;
                v.x = acc[mt][nt][rr * 2]     + bb[nt].x;
                v.y = acc[mt][nt][rr * 2 + 1] + bb[nt].y;
                *(float2*)(p + nt * 8 + 2 * tq) = v;
            }
        }
    }
}

// ---------------------------------------------------------------------------
// norms: ||k[n,h,t,:] + bq[h*64:]||^2 * (mask[n,t]==0)
// ---------------------------------------------------------------------------
__global__ void norm_kernel(const float* __restrict__ bq, const float* __restrict__ mask)
{
    int g = blockIdx.x * 256 + threadIdx.x;
    if (g >= NB * NHD * TT) return;
    int t = g & (TT - 1);
    int h = (g >> 12) & (NHD - 1);
    int n = g >> 16;
    const float* kp = &g_k[(size_t)g * DH];
    const float* bh = &bq[h * DH];
    float s = 0.f;
    #pragma unroll
    for (int d = 0; d < DH; d += 4) {
        float4 kv = *(const float4*)&kp[d];
        float x0 = kv.x + bh[d+0];
        float x1 = kv.y + bh[d+1];
        float x2 = kv.z + bh[d+2];
        float x3 = kv.w + bh[d+3];
        s += x0*x0 + x1*x1 + x2*x2 + x3*x3;
    }
    float valid = (mask[n * TT + t] == 0.0f) ? 1.0f : 0.0f;
    g_norm[g] = s * valid;
}

// ---------------------------------------------------------------------------
// selection: stable rank -> top-16 / bottom-48, index-ordered
// ---------------------------------------------------------------------------
__global__ void select_kernel()
{
    int b  = blockIdx.x;
    int c  = b & 63;
    int nh = b >> 6;
    int i  = threadIdx.x;
    __shared__ float nrm[64];
    __shared__ int   sel[64];
    nrm[i] = g_norm[(size_t)nh * TT + c * SELC + i];
    __syncthreads();
    float mine = nrm[i];
    int rank = 0;
    #pragma unroll 8
    for (int j = 0; j < 64; j++) {
        float oj = nrm[j];
        rank += (oj < mine) || (oj == mine && j < i);
    }
    sel[i] = (rank >= SELC - TOPK) ? 1 : 0;
    __syncthreads();
    int gcnt = 0;
    for (int j = 0; j < i; j++) gcnt += sel[j];
    if (sel[i]) g_gidx[nh * 1024 + c * TOPK + gcnt] = c * SELC + i;
    else        g_lidx[nh * 3072 + c * (SELC - TOPK) + (i - gcnt)] = c * SELC + i;
}

// ---------------------------------------------------------------------------
// Global pass: 64 queries/block; thread = (4 queries x 16 dims); 64 threads.
// Partial dots reduced via shfl butterfly over the 4 dim-groups.
// ---------------------------------------------------------------------------
__global__ __launch_bounds__(64) void attn_global(const float* __restrict__ mask)
{
    int qb = blockIdx.x;
    int h  = blockIdx.y, n = blockIdx.z;
    int nh = n * NHD + h;
    __shared__ float ks[48][DH];
    __shared__ float vs[48][DH];
    __shared__ float am[48];
    __shared__ float sc[48][SELC];
    int tid = threadIdx.x;
    int qg = tid >> 2, dg = tid & 3;
    int qt = qb * SELC + qg * 4;
    int db = dg * 16;

    for (int idx = tid; idx < 48 * DH; idx += 64) {
        int s = idx >> 6, d = idx & 63;
        int gs = qb * 16 - 16 + s;
        if (gs >= 0 && gs < 1024) {
            int tok = g_gidx[nh * 1024 + gs];
            ks[s][d] = g_k[((size_t)nh * TT + tok) * DH + d];
            vs[s][d] = g_v[((size_t)nh * TT + tok) * DH + d];
            if (d == 0) am[s] = mask[n * TT + tok];
        } else {
            ks[s][d] = 0.f; vs[s][d] = 0.f;
            if (d == 0) am[s] = -1e30f;
        }
    }
    __syncthreads();

    float qreg[4][16];
    #pragma unroll
    for (int j = 0; j < 4; j++) {
        const float* qp = &g_q[((size_t)nh * TT + qt + j) * DH + db];
        #pragma unroll
        for (int d = 0; d < 16; d += 4) {
            float4 t4 = *(const float4*)(qp + d);
            qreg[j][d] = t4.x; qreg[j][d+1] = t4.y; qreg[j][d+2] = t4.z; qreg[j][d+3] = t4.w;
        }
    }

    float tmax[4] = {-1e30f, -1e30f, -1e30f, -1e30f};
    for (int s = 0; s < 48; s++) {
        float4 k0 = *(const float4*)&ks[s][db];
        float4 k1 = *(const float4*)&ks[s][db + 4];
        float4 k2 = *(const float4*)&ks[s][db + 8];
        float4 k3 = *(const float4*)&ks[s][db + 12];
        float p[4];
        #pragma unroll
        for (int j = 0; j < 4; j++) {
            p[j] = qreg[j][0]*k0.x + qreg[j][1]*k0.y + qreg[j][2]*k0.z + qreg[j][3]*k0.w
                 + qreg[j][4]*k1.x + qreg[j][5]*k1.y + qreg[j][6]*k1.z + qreg[j][7]*k1.w
                 + qreg[j][8]*k2.x + qreg[j][9]*k2.y + qreg[j][10]*k2.z + qreg[j][11]*k2.w
                 + qreg[j][12]*k3.x + qreg[j][13]*k3.y + qreg[j][14]*k3.z + qreg[j][15]*k3.w;
        }
        #pragma unroll
        for (int j = 0; j < 4; j++) {
            p[j] += __shfl_xor_sync(0xffffffffu, p[j], 1);
            p[j] += __shfl_xor_sync(0xffffffffu, p[j], 2);
        }
        float a = am[s];
        float4 vv;
        #pragma unroll
        for (int j = 0; j < 4; j++) {
            float vj = (a > -1e29f) ? p[j] * 0.125f + a : -1e30f;
            (&vv.x)[j] = vj;
            tmax[j] = fmaxf(tmax[j], vj);
        }
        if (dg == 0) *(float4*)&sc[s][qg * 4] = vv;
    }
    __syncwarp();

    float l[4] = {0.f, 0.f, 0.f, 0.f};
    float acc[4][16];
    #pragma unroll
    for (int j = 0; j < 4; j++)
        #pragma unroll
        for (int d = 0; d < 16; d++) acc[j][d] = 0.f;

    for (int s = 0; s < 48; s++) {
        float4 pv = *(const float4*)&sc[s][qg * 4];
        float p[4];
        #pragma unroll
        for (int j = 0; j < 4; j++) {
            float vj = (&pv.x)[j];
            p[j] = (vj > -1e29f) ? expf(vj - tmax[j]) : 0.f;
            l[j] += p[j];
        }
        float4 v0 = *(const float4*)&vs[s][db];
        float4 v1 = *(const float4*)&vs[s][db + 4];
        float4 v2 = *(const float4*)&vs[s][db + 8];
        float4 v3 = *(const float4*)&vs[s][db + 12];
        #pragma unroll
        for (int j = 0; j < 4; j++) {
            acc[j][0]  += p[j]*v0.x; acc[j][1]  += p[j]*v0.y; acc[j][2]  += p[j]*v0.z; acc[j][3]  += p[j]*v0.w;
            acc[j][4]  += p[j]*v1.x; acc[j][5]  += p[j]*v1.y; acc[j][6]  += p[j]*v1.z; acc[j][7]  += p[j]*v1.w;
            acc[j][8]  += p[j]*v2.x; acc[j][9]  += p[j]*v2.y; acc[j][10] += p[j]*v2.z; acc[j][11] += p[j]*v2.w;
            acc[j][12] += p[j]*v3.x; acc[j][13] += p[j]*v3.y; acc[j][14] += p[j]*v3.z; acc[j][15] += p[j]*v3.w;
        }
    }

    #pragma unroll
    for (int j = 0; j < 4; j++) {
        float inv = 1.f / l[j];
        float* cg = &g_ctxg[((size_t)nh * TT + qt + j) * DH + db];
        #pragma unroll
        for (int d = 0; d < 16; d += 4) {
            float4 o;
            o.x = acc[j][d] * inv; o.y = acc[j][d+1] * inv;
            o.z = acc[j][d+2] * inv; o.w = acc[j][d+3] * inv;
            *(float4*)(cg + d) = o;
        }
        if (dg == 0) g_lseg[nh * TT + qt + j] = tmax[j] + logf(l[j]);
    }
}

// ---------------------------------------------------------------------------
// Local pass + merge: 128 queries/block; thread = (4 queries x 16 dims);
// 128 threads. Online softmax per 32-slot tile; final merge with global pass.
// ---------------------------------------------------------------------------
__global__ __launch_bounds__(128) void attn_local(const float* __restrict__ mask,
                                                  float* __restrict__ out)
{
    int qb = blockIdx.x;
    int h  = blockIdx.y, n = blockIdx.z;
    int nh = n * NHD + h;
    __shared__ float ks[32][DH];
    __shared__ float vs[32][DH];
    __shared__ float am[32];
    __shared__ int   toks[32];
    __shared__ float sc[32][128];

    int tid = threadIdx.x;
    int qg = tid >> 2, dg = tid & 3;
    int qt = qb * LOCC + qg * 4;
    int db = dg * 16;

    float qreg[4][16];
    #pragma unroll
    for (int j = 0; j < 4; j++) {
        const float* qp = &g_q[((size_t)nh * TT + qt + j) * DH + db];
        #pragma unroll
        for (int d = 0; d < 16; d += 4) {
            float4 t4 = *(const float4*)(qp + d);
            qreg[j][d] = t4.x; qreg[j][d+1] = t4.y; qreg[j][d+2] = t4.z; qreg[j][d+3] = t4.w;
        }
    }

    float acc[4][16];
    float m[4], l[4];
    #pragma unroll
    for (int j = 0; j < 4; j++) {
        m[j] = -1e30f; l[j] = 0.f;
        #pragma unroll
        for (int d = 0; d < 16; d++) acc[j][d] = 0.f;
    }
    int base = qb * 96 - 96;

    for (int t0 = 0; t0 < 288; t0 += 32) {
        if (tid < 32) {
            int gs = base + t0 + tid;
            int tok = (gs >= 0 && gs < 3072) ? g_lidx[nh * 3072 + gs] : -1;
            toks[tid] = tok;
            am[tid] = (tok >= 0) ? mask[n * TT + tok] : -1e30f;
        }
        __syncthreads();
        for (int idx = tid; idx < 32 * DH; idx += 128) {
            int s = idx >> 6, d = idx & 63;
            int tok = toks[s];
            if (tok >= 0) {
                ks[s][d] = g_k[((size_t)nh * TT + tok) * DH + d];
                vs[s][d] = g_v[((size_t)nh * TT + tok) * DH + d];
            } else { ks[s][d] = 0.f; vs[s][d] = 0.f; }
        }
        __syncthreads();

        float tmax[4] = {-1e30f, -1e30f, -1e30f, -1e30f};
        for (int s = 0; s < 32; s++) {
            float4 k0 = *(const float4*)&ks[s][db];
            float4 k1 = *(const float4*)&ks[s][db + 4];
            float4 k2 = *(const float4*)&ks[s][db + 8];
            float4 k3 = *(const float4*)&ks[s][db + 12];
            float p[4];
            #pragma unroll
            for (int j = 0; j < 4; j++) {
                p[j] = qreg[j][0]*k0.x + qreg[j][1]*k0.y + qreg[j][2]*k0.z + qreg[j][3]*k0.w
                     + qreg[j][4]*k1.x + qreg[j][5]*k1.y + qreg[j][6]*k1.z + qreg[j][7]*k1.w
                     + qreg[j][8]*k2.x + qreg[j][9]*k2.y + qreg[j][10]*k2.z + qreg[j][11]*k2.w
                     + qreg[j][12]*k3.x + qreg[j][13]*k3.y + qreg[j][14]*k3.z + qreg[j][15]*k3.w;
            }
            #pragma unroll
            for (int j = 0; j < 4; j++) {
                p[j] += __shfl_xor_sync(0xffffffffu, p[j], 1);
                p[j] += __shfl_xor_sync(0xffffffffu, p[j], 2);
            }
            float a = am[s];
            float4 vv;
            #pragma unroll
            for (int j = 0; j < 4; j++) {
                float vj = (a > -1e29f) ? p[j] * 0.125f + a : -1e30f;
                (&vv.x)[j] = vj;
                tmax[j] = fmaxf(tmax[j], vj);
            }
            if (dg == 0) *(float4*)&sc[s][qg * 4] = vv;
        }
        __syncwarp();

        if (tmax[0] > -1e29f) {
            #pragma unroll
            for (int j = 0; j < 4; j++) {
                float nm = fmaxf(m[j], tmax[j]);
                float scl = expf(m[j] - nm);
                l[j] *= scl;
                #pragma unroll
                for (int d = 0; d < 16; d++) acc[j][d] *= scl;
                m[j] = nm;
            }
            for (int s = 0; s < 32; s++) {
                float4 pv = *(const float4*)&sc[s][qg * 4];
                float p[4];
                #pragma unroll
                for (int j = 0; j < 4; j++) {
                    float vj = (&pv.x)[j];
                    p[j] = (vj > -1e29f) ? expf(vj - m[j]) : 0.f;
                    l[j] += p[j];
                }
                float4 v0 = *(const float4*)&vs[s][db];
                float4 v1 = *(const float4*)&vs[s][db + 4];
                float4 v2 = *(const float4*)&vs[s][db + 8];
                float4 v3 = *(const float4*)&vs[s][db + 12];
                #pragma unroll
                for (int j = 0; j < 4; j++) {
                    acc[j][0]  += p[j]*v0.x; acc[j][1]  += p[j]*v0.y; acc[j][2]  += p[j]*v0.z; acc[j][3]  += p[j]*v0.w;
                    acc[j][4]  += p[j]*v1.x; acc[j][5]  += p[j]*v1.y; acc[j][6]  += p[j]*v1.z; acc[j][7]  += p[j]*v1.w;
                    acc[j][8]  += p[j]*v2.x; acc[j][9]  += p[j]*v2.y; acc[j][10] += p[j]*v2.z; acc[j][11] += p[j]*v2.w;
                    acc[j][12] += p[j]*v3.x; acc[j][13] += p[j]*v3.y; acc[j][14] += p[j]*v3.z; acc[j][15] += p[j]*v3.w;
                }
            }
        }
        __syncthreads();
    }

    // appended global key (token 0, additive mask 0)
    {
        const float* k0p = &g_k[(size_t)nh * TT * DH + db];
        const float* v0p = &g_v[(size_t)nh * TT * DH + db];
        float v0r[16];
        #pragma unroll
        for (int d = 0; d < 16; d++) v0r[d] = v0p[d];
        float p[4];
        #pragma unroll
        for (int j = 0; j < 4; j++) {
            float dot = 0.f;
            #pragma unroll
            for (int d = 0; d < 16; d++) dot += qreg[j][d] * k0p[d];
            p[j] = dot;
        }
        #pragma unroll
        for (int j = 0; j < 4; j++) {
            p[j] += __shfl_xor_sync(0xffffffffu, p[j], 1);
            p[j] += __shfl_xor_sync(0xffffffffu, p[j], 2);
        }
        #pragma unroll
        for (int j = 0; j < 4; j++) {
            float s = p[j] * 0.125f;
            float nm = fmaxf(m[j], s);
            float scl = expf(m[j] - nm);
            float pe = expf(s - nm);
            l[j] = l[j] * scl + pe;
            #pragma unroll
            for (int d = 0; d < 16; d++) acc[j][d] = acc[j][d] * scl + pe * v0r[d];
            m[j] = nm;
        }
    }

    // merge with global pass and write output
    #pragma unroll
    for (int j = 0; j < 4; j++) {
        float lsel = m[j] + logf(l[j]);
        float lseg = g_lseg[nh * TT + qt + j];
        float pmix = 1.f / (1.f + expf(lseg - lsel));
        float invl = 1.f / l[j];
        const float* cg = &g_ctxg[((size_t)nh * TT + qt + j) * DH + db];
        float* op = &out[((size_t)n * TT + qt + j) * HID + h * DH + db];
        #pragma unroll
        for (int d = 0; d < 16; d += 4) {
            float4 cgv = *(const float4*)(cg + d);
            float4 o;
            o.x = cgv.x + pmix * (acc[j][d]   * invl - cgv.x);
            o.y = cgv.y + pmix * (acc[j][d+1] * invl - cgv.y);
            o.z = cgv.z + pmix * (acc[j][d+2] * invl - cgv.z);
            o.w = cgv.w + pmix * (acc[j][d+3] * invl - cgv.w);
            *(float4*)(op + d) = o;
        }
    }
}

// ---------------------------------------------------------------------------
// BOS: token-0 query, full UNscaled attention over all 4096 keys + mask.
// ---------------------------------------------------------------------------
__global__ __launch_bounds__(512) void attn_bos(const float* __restrict__ mask,
                                                float* __restrict__ out)
{
    int h = blockIdx.x, n = blockIdx.y;
    int nh = n * NHD + h;
    __shared__ float sc[TT];
    __shared__ float q0s[DH];
    __shared__ float red[512];
    __shared__ float part[8][DH];
    int tid = threadIdx.x;
    if (tid < DH) q0s[tid] = g_q[(size_t)nh * TT * DH + tid];
    __syncthreads();

    float lmax = -1e30f;
    for (int t = tid; t < TT; t += 512) {
        const float* kp = &g_k[((size_t)nh * TT + t) * DH];
        float dot = 0.f;
        #pragma unroll
        for (int d = 0; d < DH; d += 4) {
            float4 kv = *(const float4*)&kp[d];
            dot += q0s[d]*kv.x + q0s[d+1]*kv.y + q0s[d+2]*kv.z + q0s[d+3]*kv.w;
        }
        float s = dot + mask[n * TT + t];
        sc[t] = s;
        lmax = fmaxf(lmax, s);
    }
    red[tid] = lmax; __syncthreads();
    for (int o = 256; o > 0; o >>= 1) {
        if (tid < o) red[tid] = fmaxf(red[tid], red[tid + o]);
        __syncthreads();
    }
    float mx = red[0]; __syncthreads();

    float ls = 0.f;
    for (int t = tid; t < TT; t += 512) {
        float p = expf(sc[t] - mx);
        sc[t] = p;
        ls += p;
    }
    red[tid] = ls; __syncthreads();
    for (int o = 256; o > 0; o >>= 1) {
        if (tid < o) red[tid] += red[tid + o];
        __syncthreads();
    }
    float inv = 1.f / red[0];
    __syncthreads();

    {
        int d = tid & 63, sl = tid >> 6;
        float a = 0.f;
        int tstart = sl * 512;
        for (int t = tstart; t < tstart + 512; t++)
            a += sc[t] * g_v[((size_t)nh * TT + t) * DH + d];
        part[sl][d] = a;
    }
    __syncthreads();
    if (tid < DH) {
        float a = 0.f;
        #pragma unroll
        for (int sl = 0; sl < 8; sl++) a += part[sl][tid];
        out[(size_t)n * TT * HID + h * DH + tid] = a * inv;
    }
}

// ---------------------------------------------------------------------------
extern "C" void kernel_launch(void* const* d_in, const int* in_sizes, int n_in,
                              void* d_out, int out_size)
{
    const float* hs   = (const float*)d_in[0];
    const float* mask = (const float*)d_in[1];
    const float* Wq   = (const float*)d_in[2];
    const float* bq   = (const float*)d_in[3];
    const float* Wk   = (const float*)d_in[4];
    const float* bk   = (const float*)d_in[5];
    const float* Wv   = (const float*)d_in[6];
    const float* bv   = (const float*)d_in[7];
    float* out = (float*)d_out;

    static int attr_done = 0;
    if (!attr_done) {
        cudaFuncSetAttribute(gemm_f16, cudaFuncAttributeMaxDynamicSharedMemorySize,
                             GEMM_SMEM);
        attr_done = 1;
    }

    // resolve device-global scratch addresses (host side)
    __half *ah, *al, *wh, *wl;
    cudaGetSymbolAddress((void**)&ah, g_ah);
    cudaGetSymbolAddress((void**)&al, g_al);
    cudaGetSymbolAddress((void**)&wh, g_wh);
    cudaGetSymbolAddress((void**)&wl, g_wl);

    const int nA4 = 8192 * 1024 / 4;     // 2097152
    const int nW4 = 1024 * 1024 / 4;     // 262144
    split_f16<<<(nA4 + 255) / 256, 256>>>(hs, ah, al, nA4);
    split_f16<<<(nW4 + 255) / 256, 256>>>(Wq, wh,            wl,            nW4);
    split_f16<<<(nW4 + 255) / 256, 256>>>(Wk, wh + 1048576,  wl + 1048576,  nW4);
    split_f16<<<(nW4 + 255) / 256, 256>>>(Wv, wh + 2097152,  wl + 2097152,  nW4);

    gemm_f16<<<dim3(8, 64, 3), 256, GEMM_SMEM>>>(bq, bk, bv);

    norm_kernel<<<(NB * NHD * TT + 255) / 256, 256>>>(bq, mask);
    select_kernel<<<NB * NHD * 64, 64>>>();
    attn_global<<<dim3(64, NHD, NB), 64>>>(mask);
    attn_local<<<dim3(32, NHD, NB), 128>>>(mask, out);
    attn_bos<<<dim3(NHD, NB), 512>>>(mask, out);
}

// round 11
// speedup vs baseline: 1.9222x; 1.0516x over previous
#include <cuda_runtime.h>
#include <cuda_fp16.h>
#include <math.h>
#include <stdint.h>

// Problem dims
#define NB   2
#define TT   4096
#define NHD  16      // heads
#define DH   64      // head dim
#define HID  1024
#define SELC 64
#define TOPK 16
#define LOCC 128

// Scratch (device globals: allocation-free rule)
__device__ float g_q[(size_t)NB*NHD*TT*DH];
__device__ float g_k[(size_t)NB*NHD*TT*DH];
__device__ float g_v[(size_t)NB*NHD*TT*DH];
__device__ float g_ctxg[(size_t)NB*NHD*TT*DH];
__device__ float g_lseg[NB*NHD*TT];
__device__ float g_norm[NB*NHD*TT];
__device__ int   g_gidx[NB*NHD*1024];
__device__ int   g_lidx[NB*NHD*3072];

// fp16 split scratch
__device__ __half g_ah[(size_t)8192*1024];
__device__ __half g_al[(size_t)8192*1024];
__device__ __half g_wh[(size_t)3*1024*1024];
__device__ __half g_wl[(size_t)3*1024*1024];

// ---------------------------------------------------------------------------
// PTX helpers (plain PTX only — valid on target sm_103)
// ---------------------------------------------------------------------------
#define MMA_F16(c, a, b0, b1) \
    asm volatile("mma.sync.aligned.m16n8k16.row.col.f32.f16.f16.f32 " \
        "{%0,%1,%2,%3}, {%4,%5,%6,%7}, {%8,%9}, {%0,%1,%2,%3};" \
        : "+f"((c)[0]), "+f"((c)[1]), "+f"((c)[2]), "+f"((c)[3]) \
        : "r"((a)[0]), "r"((a)[1]), "r"((a)[2]), "r"((a)[3]), "r"(b0), "r"(b1))

#define LDSM_X4(r, addr) \
    asm volatile("ldmatrix.sync.aligned.m8n8.x4.shared.b16 {%0,%1,%2,%3}, [%4];" \
        : "=r"((r)[0]), "=r"((r)[1]), "=r"((r)[2]), "=r"((r)[3]) : "r"(addr))

__device__ __forceinline__ void cp16(uint32_t dst, const void* src) {
    asm volatile("cp.async.cg.shared.global [%0], [%1], 16;" :: "r"(dst), "l"(src));
}
#define CP_COMMIT() asm volatile("cp.async.commit_group;" ::: "memory")
#define CP_WAIT2()  asm volatile("cp.async.wait_group 2;" ::: "memory")

// ---------------------------------------------------------------------------
// fp32 -> (fp16 hi, fp16 lo) split, vectorized x4
// ---------------------------------------------------------------------------
__global__ void split_f16(const float* __restrict__ src, __half* __restrict__ hi,
                          __half* __restrict__ lo, int n4)
{
    int i = blockIdx.x * 256 + threadIdx.x;
    if (i >= n4) return;
    float4 v = ((const float4*)src)[i];
    __half h[4], l[4];
    h[0] = __float2half_rn(v.x); l[0] = __float2half_rn(v.x - __half2float(h[0]));
    h[1] = __float2half_rn(v.y); l[1] = __float2half_rn(v.y - __half2float(h[1]));
    h[2] = __float2half_rn(v.z); l[2] = __float2half_rn(v.z - __half2float(h[2]));
    h[3] = __float2half_rn(v.w); l[3] = __float2half_rn(v.w - __half2float(h[3]));
    ((uint2*)hi)[i] = *(uint2*)h;
    ((uint2*)lo)[i] = *(uint2*)l;
}

// ---------------------------------------------------------------------------
// fp16 mma GEMM. K (z==1): split-3 (Ahi.Whi + Ahi.Wlo + Alo.Whi), err ~2^-22
// — protects the discontinuous top-k norm selection (K-only).
// Q,V (z==0,2): single product Ahi.Whi, err ~3e-4 — Q enters only via softmax
// logits; V linearly. Output rel_err budget ~4e-4 vs 1e-3 gate.
// CTA 128x128, BK=32, 8 warps (warp tile 32x64), 4-stage cp.async pipeline,
// ldmatrix.x4 fragment loads. Output scattered to (n,h,t,d).
// ---------------------------------------------------------------------------
#define STG_BYTES 20480            // A: 128 rows x 80B + B: same
#define GEMM_SMEM (4 * STG_BYTES)  // 81920

__global__ __launch_bounds__(256, 2) void gemm_f16(
    const float* __restrict__ bq, const float* __restrict__ bk,
    const float* __restrict__ bv)
{
    extern __shared__ char smc[];
    uint32_t sbase;
    asm("{ .reg .u64 t; cvta.to.shared.u64 t, %1; cvt.u32.u64 %0, t; }"
        : "=r"(sbase) : "l"(smc));

    const int z = blockIdx.z;
    float* out = (z == 0) ? g_q : (z == 1) ? g_k : g_v;
    const float* bias = (z == 0) ? bq : (z == 1) ? bk : bv;
    const __half* Whi = g_wh + (size_t)z * 1048576;
    const __half* Wlo = g_wl + (size_t)z * 1048576;
    const int nch = (z == 1) ? 96 : 32;

    const int tid = threadIdx.x;
    const int wid = tid >> 5, lane = tid & 31;
    const int gid = lane >> 2, tq = lane & 3;
    const int row0 = blockIdx.y * 128, col0 = blockIdx.x * 128;
    const int warpM = (wid & 3) * 32, warpN = (wid >> 2) * 64;

    float acc[2][8][4];
    #pragma unroll
    for (int i = 0; i < 2; i++)
        #pragma unroll
        for (int j = 0; j < 8; j++)
            #pragma unroll
            for (int r = 0; r < 4; r++) acc[i][j][r] = 0.f;

    const int crow = tid >> 1;     // 0..127
    const int h2 = tid & 1;        // which 32B half-row

    // ldmatrix per-lane byte offsets (within a stage)
    const int lg = lane >> 3;      // lane group 0..3
    const int lr = lane & 7;
    uint32_t aoff[2];
    #pragma unroll
    for (int mt = 0; mt < 2; mt++)
        aoff[mt] = (uint32_t)((warpM + mt * 16 + (lg & 1) * 8 + lr) * 80 + (lg >> 1) * 16);
    uint32_t boff[4];
    #pragma unroll
    for (int p = 0; p < 4; p++)
        boff[p] = (uint32_t)(10240 + (warpN + p * 16 + (lg >> 1) * 8 + lr) * 80 + (lg & 1) * 16);

    auto issue_copy = [&](int c, int stg) {
        int kv = c * 32;
        int ph = kv >> 10;
        int kl = kv & 1023;
        const __half* aS; const __half* bS;
        if (z == 1) { aS = (ph == 2) ? g_al : g_ah; bS = (ph == 1) ? Wlo : Whi; }
        else        { aS = g_ah; bS = Whi; }
        const __half* asrc = aS + (size_t)(row0 + crow) * 1024 + kl + h2 * 16;
        const __half* bsrc = bS + (size_t)(col0 + crow) * 1024 + kl + h2 * 16;
        uint32_t ad = sbase + stg * STG_BYTES + crow * 80 + h2 * 32;
        uint32_t bd = ad + 10240;
        cp16(ad, asrc);      cp16(ad + 16, asrc + 8);
        cp16(bd, bsrc);      cp16(bd + 16, bsrc + 8);
    };

    // prefetch 3 chunks
    #pragma unroll
    for (int s = 0; s < 3; s++) { issue_copy(s, s); CP_COMMIT(); }

    for (int c = 0; c < nch; c++) {
        CP_WAIT2();
        __syncthreads();
        int cn = c + 3;
        if (cn < nch) issue_copy(cn, cn & 3);
        CP_COMMIT();

        const uint32_t sstage = sbase + (c & 3) * STG_BYTES;
        #pragma unroll
        for (int ks = 0; ks < 2; ks++) {
            const uint32_t ko = ks * 32;
            uint32_t a0[4], a1[4];
            LDSM_X4(a0, sstage + aoff[0] + ko);
            LDSM_X4(a1, sstage + aoff[1] + ko);
            #pragma unroll
            for (int p = 0; p < 4; p++) {
                uint32_t br[4];
                LDSM_X4(br, sstage + boff[p] + ko);
                MMA_F16(acc[0][2*p],   a0, br[0], br[1]);
                MMA_F16(acc[1][2*p],   a1, br[0], br[1]);
                MMA_F16(acc[0][2*p+1], a0, br[2], br[3]);
                MMA_F16(acc[1][2*p+1], a1, br[2], br[3]);
            }
        }
    }

    // Epilogue: warp spans 64 cols = one head.
    const int hcol = col0 + warpN;
    const int h = hcol >> 6;
    float2 bb[8];
    #pragma unroll
    for (int nt = 0; nt < 8; nt++) {
        int cc = hcol + nt * 8 + 2 * tq;
        bb[nt].x = bias[cc];
        bb[nt].y = bias[cc + 1];
    }
    #pragma unroll
    for (int mt = 0; mt < 2; mt++) {
        #pragma unroll
        for (int rr = 0; rr < 2; rr++) {
            int grow = row0 + warpM + mt * 16 + gid + rr * 8;
            int nn = grow >> 12, t = grow & 4095;
            float* p = out + (((size_t)(nn * NHD + h)) * TT + t) * DH;
            #pragma unroll
            for (int nt = 0; nt < 8; nt++) {
                float2 v;
                v.x = acc[mt][nt][rr * 2]     + bb[nt].x;
                v.y = acc[mt][nt][rr * 2 + 1] + bb[nt].y;
                *(float2*)(p + nt * 8 + 2 * tq) = v;
            }
        }
    }
}

// ---------------------------------------------------------------------------
// norms: ||k[n,h,t,:] + bq[h*64:]||^2 * (mask[n,t]==0)
// ---------------------------------------------------------------------------
__global__ void norm_kernel(const float* __restrict__ bq, const float* __restrict__ mask)
{
    int g = blockIdx.x * 256 + threadIdx.x;
    if (g >= NB * NHD * TT) return;
    int t = g & (TT - 1);
    int h = (g >> 12) & (NHD - 1);
    int n = g >> 16;
    const float* kp = &g_k[(size_t)g * DH];
    const float* bh = &bq[h * DH];
    float s = 0.f;
    #pragma unroll
    for (int d = 0; d < DH; d += 4) {
        float4 kv = *(const float4*)&kp[d];
        float x0 = kv.x + bh[d+0];
        float x1 = kv.y + bh[d+1];
        float x2 = kv.z + bh[d+2];
        float x3 = kv.w + bh[d+3];
        s += x0*x0 + x1*x1 + x2*x2 + x3*x3;
    }
    float valid = (mask[n * TT + t] == 0.0f) ? 1.0f : 0.0f;
    g_norm[g] = s * valid;
}

// ---------------------------------------------------------------------------
// selection: stable rank -> top-16 / bottom-48, index-ordered
// ---------------------------------------------------------------------------
__global__ void select_kernel()
{
    int b  = blockIdx.x;
    int c  = b & 63;
    int nh = b >> 6;
    int i  = threadIdx.x;
    __shared__ float nrm[64];
    __shared__ int   sel[64];
    nrm[i] = g_norm[(size_t)nh * TT + c * SELC + i];
    __syncthreads();
    float mine = nrm[i];
    int rank = 0;
    #pragma unroll 8
    for (int j = 0; j < 64; j++) {
        float oj = nrm[j];
        rank += (oj < mine) || (oj == mine && j < i);
    }
    sel[i] = (rank >= SELC - TOPK) ? 1 : 0;
    __syncthreads();
    int gcnt = 0;
    for (int j = 0; j < i; j++) gcnt += sel[j];
    if (sel[i]) g_gidx[nh * 1024 + c * TOPK + gcnt] = c * SELC + i;
    else        g_lidx[nh * 3072 + c * (SELC - TOPK) + (i - gcnt)] = c * SELC + i;
}

// ---------------------------------------------------------------------------
// Global pass: 64 queries/block; thread = (4 queries x 16 dims); 64 threads.
// Partial dots reduced via shfl butterfly over the 4 dim-groups.
// ---------------------------------------------------------------------------
__global__ __launch_bounds__(64) void attn_global(const float* __restrict__ mask)
{
    int qb = blockIdx.x;
    int h  = blockIdx.y, n = blockIdx.z;
    int nh = n * NHD + h;
    __shared__ float ks[48][DH];
    __shared__ float vs[48][DH];
    __shared__ float am[48];
    __shared__ float sc[48][SELC];
    int tid = threadIdx.x;
    int qg = tid >> 2, dg = tid & 3;
    int qt = qb * SELC + qg * 4;
    int db = dg * 16;

    for (int idx = tid; idx < 48 * DH; idx += 64) {
        int s = idx >> 6, d = idx & 63;
        int gs = qb * 16 - 16 + s;
        if (gs >= 0 && gs < 1024) {
            int tok = g_gidx[nh * 1024 + gs];
            ks[s][d] = g_k[((size_t)nh * TT + tok) * DH + d];
            vs[s][d] = g_v[((size_t)nh * TT + tok) * DH + d];
            if (d == 0) am[s] = mask[n * TT + tok];
        } else {
            ks[s][d] = 0.f; vs[s][d] = 0.f;
            if (d == 0) am[s] = -1e30f;
        }
    }
    __syncthreads();

    float qreg[4][16];
    #pragma unroll
    for (int j = 0; j < 4; j++) {
        const float* qp = &g_q[((size_t)nh * TT + qt + j) * DH + db];
        #pragma unroll
        for (int d = 0; d < 16; d += 4) {
            float4 t4 = *(const float4*)(qp + d);
            qreg[j][d] = t4.x; qreg[j][d+1] = t4.y; qreg[j][d+2] = t4.z; qreg[j][d+3] = t4.w;
        }
    }

    float tmax[4] = {-1e30f, -1e30f, -1e30f, -1e30f};
    for (int s = 0; s < 48; s++) {
        float4 k0 = *(const float4*)&ks[s][db];
        float4 k1 = *(const float4*)&ks[s][db + 4];
        float4 k2 = *(const float4*)&ks[s][db + 8];
        float4 k3 = *(const float4*)&ks[s][db + 12];
        float p[4];
        #pragma unroll
        for (int j = 0; j < 4; j++) {
            p[j] = qreg[j][0]*k0.x + qreg[j][1]*k0.y + qreg[j][2]*k0.z + qreg[j][3]*k0.w
                 + qreg[j][4]*k1.x + qreg[j][5]*k1.y + qreg[j][6]*k1.z + qreg[j][7]*k1.w
                 + qreg[j][8]*k2.x + qreg[j][9]*k2.y + qreg[j][10]*k2.z + qreg[j][11]*k2.w
                 + qreg[j][12]*k3.x + qreg[j][13]*k3.y + qreg[j][14]*k3.z + qreg[j][15]*k3.w;
        }
        #pragma unroll
        for (int j = 0; j < 4; j++) {
            p[j] += __shfl_xor_sync(0xffffffffu, p[j], 1);
            p[j] += __shfl_xor_sync(0xffffffffu, p[j], 2);
        }
        float a = am[s];
        float4 vv;
        #pragma unroll
        for (int j = 0; j < 4; j++) {
            float vj = (a > -1e29f) ? p[j] * 0.125f + a : -1e30f;
            (&vv.x)[j] = vj;
            tmax[j] = fmaxf(tmax[j], vj);
        }
        if (dg == 0) *(float4*)&sc[s][qg * 4] = vv;
    }
    __syncwarp();

    float l[4] = {0.f, 0.f, 0.f, 0.f};
    float acc[4][16];
    #pragma unroll
    for (int j = 0; j < 4; j++)
        #pragma unroll
        for (int d = 0; d < 16; d++) acc[j][d] = 0.f;

    for (int s = 0; s < 48; s++) {
        float4 pv = *(const float4*)&sc[s][qg * 4];
        float p[4];
        #pragma unroll
        for (int j = 0; j < 4; j++) {
            float vj = (&pv.x)[j];
            p[j] = (vj > -1e29f) ? expf(vj - tmax[j]) : 0.f;
            l[j] += p[j];
        }
        float4 v0 = *(const float4*)&vs[s][db];
        float4 v1 = *(const float4*)&vs[s][db + 4];
        float4 v2 = *(const float4*)&vs[s][db + 8];
        float4 v3 = *(const float4*)&vs[s][db + 12];
        #pragma unroll
        for (int j = 0; j < 4; j++) {
            acc[j][0]  += p[j]*v0.x; acc[j][1]  += p[j]*v0.y; acc[j][2]  += p[j]*v0.z; acc[j][3]  += p[j]*v0.w;
            acc[j][4]  += p[j]*v1.x; acc[j][5]  += p[j]*v1.y; acc[j][6]  += p[j]*v1.z; acc[j][7]  += p[j]*v1.w;
            acc[j][8]  += p[j]*v2.x; acc[j][9]  += p[j]*v2.y; acc[j][10] += p[j]*v2.z; acc[j][11] += p[j]*v2.w;
            acc[j][12] += p[j]*v3.x; acc[j][13] += p[j]*v3.y; acc[j][14] += p[j]*v3.z; acc[j][15] += p[j]*v3.w;
        }
    }

    #pragma unroll
    for (int j = 0; j < 4; j++) {
        float inv = 1.f / l[j];
        float* cg = &g_ctxg[((size_t)nh * TT + qt + j) * DH + db];
        #pragma unroll
        for (int d = 0; d < 16; d += 4) {
            float4 o;
            o.x = acc[j][d] * inv; o.y = acc[j][d+1] * inv;
            o.z = acc[j][d+2] * inv; o.w = acc[j][d+3] * inv;
            *(float4*)(cg + d) = o;
        }
        if (dg == 0) g_lseg[nh * TT + qt + j] = tmax[j] + logf(l[j]);
    }
}

// ---------------------------------------------------------------------------
// Local pass + merge: 128 queries/block; thread = (4 queries x 16 dims);
// 128 threads. Online softmax per 32-slot tile; final merge with global pass.
// ---------------------------------------------------------------------------
__global__ __launch_bounds__(128) void attn_local(const float* __restrict__ mask,
                                                  float* __restrict__ out)
{
    int qb = blockIdx.x;
    int h  = blockIdx.y, n = blockIdx.z;
    int nh = n * NHD + h;
    __shared__ float ks[32][DH];
    __shared__ float vs[32][DH];
    __shared__ float am[32];
    __shared__ int   toks[32];
    __shared__ float sc[32][128];

    int tid = threadIdx.x;
    int qg = tid >> 2, dg = tid & 3;
    int qt = qb * LOCC + qg * 4;
    int db = dg * 16;

    float qreg[4][16];
    #pragma unroll
    for (int j = 0; j < 4; j++) {
        const float* qp = &g_q[((size_t)nh * TT + qt + j) * DH + db];
        #pragma unroll
        for (int d = 0; d < 16; d += 4) {
            float4 t4 = *(const float4*)(qp + d);
            qreg[j][d] = t4.x; qreg[j][d+1] = t4.y; qreg[j][d+2] = t4.z; qreg[j][d+3] = t4.w;
        }
    }

    float acc[4][16];
    float m[4], l[4];
    #pragma unroll
    for (int j = 0; j < 4; j++) {
        m[j] = -1e30f; l[j] = 0.f;
        #pragma unroll
        for (int d = 0; d < 16; d++) acc[j][d] = 0.f;
    }
    int base = qb * 96 - 96;

    for (int t0 = 0; t0 < 288; t0 += 32) {
        if (tid < 32) {
            int gs = base + t0 + tid;
            int tok = (gs >= 0 && gs < 3072) ? g_lidx[nh * 3072 + gs] : -1;
            toks[tid] = tok;
            am[tid] = (tok >= 0) ? mask[n * TT + tok] : -1e30f;
        }
        __syncthreads();
        for (int idx = tid; idx < 32 * DH; idx += 128) {
            int s = idx >> 6, d = idx & 63;
            int tok = toks[s];
            if (tok >= 0) {
                ks[s][d] = g_k[((size_t)nh * TT + tok) * DH + d];
                vs[s][d] = g_v[((size_t)nh * TT + tok) * DH + d];
            } else { ks[s][d] = 0.f; vs[s][d] = 0.f; }
        }
        __syncthreads();

        float tmax[4] = {-1e30f, -1e30f, -1e30f, -1e30f};
        for (int s = 0; s < 32; s++) {
            float4 k0 = *(const float4*)&ks[s][db];
            float4 k1 = *(const float4*)&ks[s][db + 4];
            float4 k2 = *(const float4*)&ks[s][db + 8];
            float4 k3 = *(const float4*)&ks[s][db + 12];
            float p[4];
            #pragma unroll
            for (int j = 0; j < 4; j++) {
                p[j] = qreg[j][0]*k0.x + qreg[j][1]*k0.y + qreg[j][2]*k0.z + qreg[j][3]*k0.w
                     + qreg[j][4]*k1.x + qreg[j][5]*k1.y + qreg[j][6]*k1.z + qreg[j][7]*k1.w
                     + qreg[j][8]*k2.x + qreg[j][9]*k2.y + qreg[j][10]*k2.z + qreg[j][11]*k2.w
                     + qreg[j][12]*k3.x + qreg[j][13]*k3.y + qreg[j][14]*k3.z + qreg[j][15]*k3.w;
            }
            #pragma unroll
            for (int j = 0; j < 4; j++) {
                p[j] += __shfl_xor_sync(0xffffffffu, p[j], 1);
                p[j] += __shfl_xor_sync(0xffffffffu, p[j], 2);
            }
            float a = am[s];
            float4 vv;
            #pragma unroll
            for (int j = 0; j < 4; j++) {
                float vj = (a > -1e29f) ? p[j] * 0.125f + a : -1e30f;
                (&vv.x)[j] = vj;
                tmax[j] = fmaxf(tmax[j], vj);
            }
            if (dg == 0) *(float4*)&sc[s][qg * 4] = vv;
        }
        __syncwarp();

        if (tmax[0] > -1e29f) {
            #pragma unroll
            for (int j = 0; j < 4; j++) {
                float nm = fmaxf(m[j], tmax[j]);
                float scl = expf(m[j] - nm);
                l[j] *= scl;
                #pragma unroll
                for (int d = 0; d < 16; d++) acc[j][d] *= scl;
                m[j] = nm;
            }
            for (int s = 0; s < 32; s++) {
                float4 pv = *(const float4*)&sc[s][qg * 4];
                float p[4];
                #pragma unroll
                for (int j = 0; j < 4; j++) {
                    float vj = (&pv.x)[j];
                    p[j] = (vj > -1e29f) ? expf(vj - m[j]) : 0.f;
                    l[j] += p[j];
                }
                float4 v0 = *(const float4*)&vs[s][db];
                float4 v1 = *(const float4*)&vs[s][db + 4];
                float4 v2 = *(const float4*)&vs[s][db + 8];
                float4 v3 = *(const float4*)&vs[s][db + 12];
                #pragma unroll
                for (int j = 0; j < 4; j++) {
                    acc[j][0]  += p[j]*v0.x; acc[j][1]  += p[j]*v0.y; acc[j][2]  += p[j]*v0.z; acc[j][3]  += p[j]*v0.w;
                    acc[j][4]  += p[j]*v1.x; acc[j][5]  += p[j]*v1.y; acc[j][6]  += p[j]*v1.z; acc[j][7]  += p[j]*v1.w;
                    acc[j][8]  += p[j]*v2.x; acc[j][9]  += p[j]*v2.y; acc[j][10] += p[j]*v2.z; acc[j][11] += p[j]*v2.w;
                    acc[j][12] += p[j]*v3.x; acc[j][13] += p[j]*v3.y; acc[j][14] += p[j]*v3.z; acc[j][15] += p[j]*v3.w;
                }
            }
        }
        __syncthreads();
    }

    // appended global key (token 0, additive mask 0)
    {
        const float* k0p = &g_k[(size_t)nh * TT * DH + db];
        const float* v0p = &g_v[(size_t)nh * TT * DH + db];
        float v0r[16];
        #pragma unroll
        for (int d = 0; d < 16; d++) v0r[d] = v0p[d];
        float p[4];
        #pragma unroll
        for (int j = 0; j < 4; j++) {
            float dot = 0.f;
            #pragma unroll
            for (int d = 0; d < 16; d++) dot += qreg[j][d] * k0p[d];
            p[j] = dot;
        }
        #pragma unroll
        for (int j = 0; j < 4; j++) {
            p[j] += __shfl_xor_sync(0xffffffffu, p[j], 1);
            p[j] += __shfl_xor_sync(0xffffffffu, p[j], 2);
        }
        #pragma unroll
        for (int j = 0; j < 4; j++) {
            float s = p[j] * 0.125f;
            float nm = fmaxf(m[j], s);
            float scl = expf(m[j] - nm);
            float pe = expf(s - nm);
            l[j] = l[j] * scl + pe;
            #pragma unroll
            for (int d = 0; d < 16; d++) acc[j][d] = acc[j][d] * scl + pe * v0r[d];
            m[j] = nm;
        }
    }

    // merge with global pass and write output
    #pragma unroll
    for (int j = 0; j < 4; j++) {
        float lsel = m[j] + logf(l[j]);
        float lseg = g_lseg[nh * TT + qt + j];
        float pmix = 1.f / (1.f + expf(lseg - lsel));
        float invl = 1.f / l[j];
        const float* cg = &g_ctxg[((size_t)nh * TT + qt + j) * DH + db];
        float* op = &out[((size_t)n * TT + qt + j) * HID + h * DH + db];
        #pragma unroll
        for (int d = 0; d < 16; d += 4) {
            float4 cgv = *(const float4*)(cg + d);
            float4 o;
            o.x = cgv.x + pmix * (acc[j][d]   * invl - cgv.x);
            o.y = cgv.y + pmix * (acc[j][d+1] * invl - cgv.y);
            o.z = cgv.z + pmix * (acc[j][d+2] * invl - cgv.z);
            o.w = cgv.w + pmix * (acc[j][d+3] * invl - cgv.w);
            *(float4*)(op + d) = o;
        }
    }
}

// ---------------------------------------------------------------------------
// BOS: token-0 query, full UNscaled attention over all 4096 keys + mask.
// ---------------------------------------------------------------------------
__global__ __launch_bounds__(512) void attn_bos(const float* __restrict__ mask,
                                                float* __restrict__ out)
{
    int h = blockIdx.x, n = blockIdx.y;
    int nh = n * NHD + h;
    __shared__ float sc[TT];
    __shared__ float q0s[DH];
    __shared__ float red[512];
    __shared__ float part[8][DH];
    int tid = threadIdx.x;
    if (tid < DH) q0s[tid] = g_q[(size_t)nh * TT * DH + tid];
    __syncthreads();

    float lmax = -1e30f;
    for (int t = tid; t < TT; t += 512) {
        const float* kp = &g_k[((size_t)nh * TT + t) * DH];
        float dot = 0.f;
        #pragma unroll
        for (int d = 0; d < DH; d += 4) {
            float4 kv = *(const float4*)&kp[d];
            dot += q0s[d]*kv.x + q0s[d+1]*kv.y + q0s[d+2]*kv.z + q0s[d+3]*kv.w;
        }
        float s = dot + mask[n * TT + t];
        sc[t] = s;
        lmax = fmaxf(lmax, s);
    }
    red[tid] = lmax; __syncthreads();
    for (int o = 256; o > 0; o >>= 1) {
        if (tid < o) red[tid] = fmaxf(red[tid], red[tid + o]);
        __syncthreads();
    }
    float mx = red[0]; __syncthreads();

    float ls = 0.f;
    for (int t = tid; t < TT; t += 512) {
        float p = expf(sc[t] - mx);
        sc[t] = p;
        ls += p;
    }
    red[tid] = ls; __syncthreads();
    for (int o = 256; o > 0; o >>= 1) {
        if (tid < o) red[tid] += red[tid + o];
        __syncthreads();
    }
    float inv = 1.f / red[0];
    __syncthreads();

    {
        int d = tid & 63, sl = tid >> 6;
        float a = 0.f;
        int tstart = sl * 512;
        for (int t = tstart; t < tstart + 512; t++)
            a += sc[t] * g_v[((size_t)nh * TT + t) * DH + d];
        part[sl][d] = a;
    }
    __syncthreads();
    if (tid < DH) {
        float a = 0.f;
        #pragma unroll
        for (int sl = 0; sl < 8; sl++) a += part[sl][tid];
        out[(size_t)n * TT * HID + h * DH + tid] = a * inv;
    }
}

// ---------------------------------------------------------------------------
extern "C" void kernel_launch(void* const* d_in, const int* in_sizes, int n_in,
                              void* d_out, int out_size)
{
    const float* hs   = (const float*)d_in[0];
    const float* mask = (const float*)d_in[1];
    const float* Wq   = (const float*)d_in[2];
    const float* bq   = (const float*)d_in[3];
    const float* Wk   = (const float*)d_in[4];
    const float* bk   = (const float*)d_in[5];
    const float* Wv   = (const float*)d_in[6];
    const float* bv   = (const float*)d_in[7];
    float* out = (float*)d_out;

    static int attr_done = 0;
    if (!attr_done) {
        cudaFuncSetAttribute(gemm_f16, cudaFuncAttributeMaxDynamicSharedMemorySize,
                             GEMM_SMEM);
        attr_done = 1;
    }

    // resolve device-global scratch addresses (host side)
    __half *ah, *al, *wh, *wl;
    cudaGetSymbolAddress((void**)&ah, g_ah);
    cudaGetSymbolAddress((void**)&al, g_al);
    cudaGetSymbolAddress((void**)&wh, g_wh);
    cudaGetSymbolAddress((void**)&wl, g_wl);

    const int nA4 = 8192 * 1024 / 4;     // 2097152
    const int nW4 = 1024 * 1024 / 4;     // 262144
    split_f16<<<(nA4 + 255) / 256, 256>>>(hs, ah, al, nA4);
    split_f16<<<(nW4 + 255) / 256, 256>>>(Wq, wh,            wl,            nW4);
    split_f16<<<(nW4 + 255) / 256, 256>>>(Wk, wh + 1048576,  wl + 1048576,  nW4);
    split_f16<<<(nW4 + 255) / 256, 256>>>(Wv, wh + 2097152,  wl + 2097152,  nW4);

    gemm_f16<<<dim3(8, 64, 3), 256, GEMM_SMEM>>>(bq, bk, bv);

    norm_kernel<<<(NB * NHD * TT + 255) / 256, 256>>>(bq, mask);
    select_kernel<<<NB * NHD * 64, 64>>>();
    attn_global<<<dim3(64, NHD, NB), 64>>>(mask);
    attn_local<<<dim3(32, NHD, NB), 128>>>(mask, out);
    attn_bos<<<dim3(NHD, NB), 512>>>(mask, out);
}

// round 12
// speedup vs baseline: 2.0052x; 1.0432x over previous
#include <cuda_runtime.h>
#include <cuda_fp16.h>
#include <math.h>
#include <stdint.h>

// Problem dims
#define NB   2
#define TT   4096
#define NHD  16      // heads
#define DH   64      // head dim
#define HID  1024
#define SELC 64
#define TOPK 16
#define LOCC 128

// Scratch (device globals: allocation-free rule)
__device__ float g_q[(size_t)NB*NHD*TT*DH];
__device__ float g_k[(size_t)NB*NHD*TT*DH];
__device__ float g_v[(size_t)NB*NHD*TT*DH];
__device__ float g_ctxg[(size_t)NB*NHD*TT*DH];
__device__ float g_lseg[NB*NHD*TT];
__device__ float g_norm[NB*NHD*TT];
__device__ int   g_gidx[NB*NHD*1024];
__device__ int   g_lidx[NB*NHD*3072];

// fp16 split scratch
__device__ __half g_ah[(size_t)8192*1024];
__device__ __half g_al[(size_t)8192*1024];
__device__ __half g_wh[(size_t)3*1024*1024];
__device__ __half g_wl[(size_t)3*1024*1024];

// ---------------------------------------------------------------------------
// PTX helpers (plain PTX only — valid on target sm_103)
// ---------------------------------------------------------------------------
#define MMA_F16(c, a, b0, b1) \
    asm volatile("mma.sync.aligned.m16n8k16.row.col.f32.f16.f16.f32 " \
        "{%0,%1,%2,%3}, {%4,%5,%6,%7}, {%8,%9}, {%0,%1,%2,%3};" \
        : "+f"((c)[0]), "+f"((c)[1]), "+f"((c)[2]), "+f"((c)[3]) \
        : "r"((a)[0]), "r"((a)[1]), "r"((a)[2]), "r"((a)[3]), "r"(b0), "r"(b1))

#define LDSM_X4(r, addr) \
    asm volatile("ldmatrix.sync.aligned.m8n8.x4.shared.b16 {%0,%1,%2,%3}, [%4];" \
        : "=r"((r)[0]), "=r"((r)[1]), "=r"((r)[2]), "=r"((r)[3]) : "r"(addr))

__device__ __forceinline__ void cp16(uint32_t dst, const void* src) {
    asm volatile("cp.async.cg.shared.global [%0], [%1], 16;" :: "r"(dst), "l"(src));
}
#define CP_COMMIT() asm volatile("cp.async.commit_group;" ::: "memory")
#define CP_WAIT2()  asm volatile("cp.async.wait_group 2;" ::: "memory")

// 4-partial tree dot of 16 dims against float4 quads
__device__ __forceinline__ float dot16(const float* q, float4 k0, float4 k1,
                                       float4 k2, float4 k3) {
    float d0 = q[0]*k0.x + q[1]*k0.y + q[2]*k0.z + q[3]*k0.w;
    float d1 = q[4]*k1.x + q[5]*k1.y + q[6]*k1.z + q[7]*k1.w;
    float d2 = q[8]*k2.x + q[9]*k2.y + q[10]*k2.z + q[11]*k2.w;
    float d3 = q[12]*k3.x + q[13]*k3.y + q[14]*k3.z + q[15]*k3.w;
    return (d0 + d1) + (d2 + d3);
}

// ---------------------------------------------------------------------------
// fp32 -> (fp16 hi, fp16 lo) split, vectorized x4
// ---------------------------------------------------------------------------
__global__ void split_f16(const float* __restrict__ src, __half* __restrict__ hi,
                          __half* __restrict__ lo, int n4)
{
    int i = blockIdx.x * 256 + threadIdx.x;
    if (i >= n4) return;
    float4 v = ((const float4*)src)[i];
    __half h[4], l[4];
    h[0] = __float2half_rn(v.x); l[0] = __float2half_rn(v.x - __half2float(h[0]));
    h[1] = __float2half_rn(v.y); l[1] = __float2half_rn(v.y - __half2float(h[1]));
    h[2] = __float2half_rn(v.z); l[2] = __float2half_rn(v.z - __half2float(h[2]));
    h[3] = __float2half_rn(v.w); l[3] = __float2half_rn(v.w - __half2float(h[3]));
    ((uint2*)hi)[i] = *(uint2*)h;
    ((uint2*)lo)[i] = *(uint2*)l;
}

// ---------------------------------------------------------------------------
// fp16 mma GEMM. K (z==1): split-3 (Ahi.Whi + Ahi.Wlo + Alo.Whi), err ~2^-22
// — protects the discontinuous top-k norm selection (K-only).
// Q,V (z==0,2): single product Ahi.Whi, err ~3e-4 (continuous paths only).
// CTA 128x128, BK=32, 8 warps (warp tile 32x64), 4-stage cp.async pipeline,
// ldmatrix.x4 fragment loads. Output scattered to (n,h,t,d).
// ---------------------------------------------------------------------------
#define STG_BYTES 20480            // A: 128 rows x 80B + B: same
#define GEMM_SMEM (4 * STG_BYTES)  // 81920

__global__ __launch_bounds__(256, 2) void gemm_f16(
    const float* __restrict__ bq, const float* __restrict__ bk,
    const float* __restrict__ bv)
{
    extern __shared__ char smc[];
    uint32_t sbase;
    asm("{ .reg .u64 t; cvta.to.shared.u64 t, %1; cvt.u32.u64 %0, t; }"
        : "=r"(sbase) : "l"(smc));

    const int z = blockIdx.z;
    float* out = (z == 0) ? g_q : (z == 1) ? g_k : g_v;
    const float* bias = (z == 0) ? bq : (z == 1) ? bk : bv;
    const __half* Whi = g_wh + (size_t)z * 1048576;
    const __half* Wlo = g_wl + (size_t)z * 1048576;
    const int nch = (z == 1) ? 96 : 32;

    const int tid = threadIdx.x;
    const int wid = tid >> 5, lane = tid & 31;
    const int gid = lane >> 2, tq = lane & 3;
    const int row0 = blockIdx.y * 128, col0 = blockIdx.x * 128;
    const int warpM = (wid & 3) * 32, warpN = (wid >> 2) * 64;

    float acc[2][8][4];
    #pragma unroll
    for (int i = 0; i < 2; i++)
        #pragma unroll
        for (int j = 0; j < 8; j++)
            #pragma unroll
            for (int r = 0; r < 4; r++) acc[i][j][r] = 0.f;

    const int crow = tid >> 1;     // 0..127
    const int h2 = tid & 1;        // which 32B half-row

    // ldmatrix per-lane byte offsets (within a stage)
    const int lg = lane >> 3;      // lane group 0..3
    const int lr = lane & 7;
    uint32_t aoff[2];
    #pragma unroll
    for (int mt = 0; mt < 2; mt++)
        aoff[mt] = (uint32_t)((warpM + mt * 16 + (lg & 1) * 8 + lr) * 80 + (lg >> 1) * 16);
    uint32_t boff[4];
    #pragma unroll
    for (int p = 0; p < 4; p++)
        boff[p] = (uint32_t)(10240 + (warpN + p * 16 + (lg >> 1) * 8 + lr) * 80 + (lg & 1) * 16);

    auto issue_copy = [&](int c, int stg) {
        int kv = c * 32;
        int ph = kv >> 10;
        int kl = kv & 1023;
        const __half* aS; const __half* bS;
        if (z == 1) { aS = (ph == 2) ? g_al : g_ah; bS = (ph == 1) ? Wlo : Whi; }
        else        { aS = g_ah; bS = Whi; }
        const __half* asrc = aS + (size_t)(row0 + crow) * 1024 + kl + h2 * 16;
        const __half* bsrc = bS + (size_t)(col0 + crow) * 1024 + kl + h2 * 16;
        uint32_t ad = sbase + stg * STG_BYTES + crow * 80 + h2 * 32;
        uint32_t bd = ad + 10240;
        cp16(ad, asrc);      cp16(ad + 16, asrc + 8);
        cp16(bd, bsrc);      cp16(bd + 16, bsrc + 8);
    };

    // prefetch 3 chunks
    #pragma unroll
    for (int s = 0; s < 3; s++) { issue_copy(s, s); CP_COMMIT(); }

    for (int c = 0; c < nch; c++) {
        CP_WAIT2();
        __syncthreads();
        int cn = c + 3;
        if (cn < nch) issue_copy(cn, cn & 3);
        CP_COMMIT();

        const uint32_t sstage = sbase + (c & 3) * STG_BYTES;
        #pragma unroll
        for (int ks = 0; ks < 2; ks++) {
            const uint32_t ko = ks * 32;
            uint32_t a0[4], a1[4];
            LDSM_X4(a0, sstage + aoff[0] + ko);
            LDSM_X4(a1, sstage + aoff[1] + ko);
            #pragma unroll
            for (int p = 0; p < 4; p++) {
                uint32_t br[4];
                LDSM_X4(br, sstage + boff[p] + ko);
                MMA_F16(acc[0][2*p],   a0, br[0], br[1]);
                MMA_F16(acc[1][2*p],   a1, br[0], br[1]);
                MMA_F16(acc[0][2*p+1], a0, br[2], br[3]);
                MMA_F16(acc[1][2*p+1], a1, br[2], br[3]);
            }
        }
    }

    // Epilogue: warp spans 64 cols = one head.
    const int hcol = col0 + warpN;
    const int h = hcol >> 6;
    float2 bb[8];
    #pragma unroll
    for (int nt = 0; nt < 8; nt++) {
        int cc = hcol + nt * 8 + 2 * tq;
        bb[nt].x = bias[cc];
        bb[nt].y = bias[cc + 1];
    }
    #pragma unroll
    for (int mt = 0; mt < 2; mt++) {
        #pragma unroll
        for (int rr = 0; rr < 2; rr++) {
            int grow = row0 + warpM + mt * 16 + gid + rr * 8;
            int nn = grow >> 12, t = grow & 4095;
            float* p = out + (((size_t)(nn * NHD + h)) * TT + t) * DH;
            #pragma unroll
            for (int nt = 0; nt < 8; nt++) {
                float2 v;
                v.x = acc[mt][nt][rr * 2]     + bb[nt].x;
                v.y = acc[mt][nt][rr * 2 + 1] + bb[nt].y;
                *(float2*)(p + nt * 8 + 2 * tq) = v;
            }
        }
    }
}

// ---------------------------------------------------------------------------
// norms: ||k[n,h,t,:] + bq[h*64:]||^2 * (mask[n,t]==0)
// ---------------------------------------------------------------------------
__global__ void norm_kernel(const float* __restrict__ bq, const float* __restrict__ mask)
{
    int g = blockIdx.x * 256 + threadIdx.x;
    if (g >= NB * NHD * TT) return;
    int t = g & (TT - 1);
    int h = (g >> 12) & (NHD - 1);
    int n = g >> 16;
    const float* kp = &g_k[(size_t)g * DH];
    const float* bh = &bq[h * DH];
    float s = 0.f;
    #pragma unroll
    for (int d = 0; d < DH; d += 4) {
        float4 kv = *(const float4*)&kp[d];
        float x0 = kv.x + bh[d+0];
        float x1 = kv.y + bh[d+1];
        float x2 = kv.z + bh[d+2];
        float x3 = kv.w + bh[d+3];
        s += x0*x0 + x1*x1 + x2*x2 + x3*x3;
    }
    float valid = (mask[n * TT + t] == 0.0f) ? 1.0f : 0.0f;
    g_norm[g] = s * valid;
}

// ---------------------------------------------------------------------------
// selection: stable rank -> top-16 / bottom-48, index-ordered
// ---------------------------------------------------------------------------
__global__ void select_kernel()
{
    int b  = blockIdx.x;
    int c  = b & 63;
    int nh = b >> 6;
    int i  = threadIdx.x;
    __shared__ float nrm[64];
    __shared__ int   sel[64];
    nrm[i] = g_norm[(size_t)nh * TT + c * SELC + i];
    __syncthreads();
    float mine = nrm[i];
    int rank = 0;
    #pragma unroll 8
    for (int j = 0; j < 64; j++) {
        float oj = nrm[j];
        rank += (oj < mine) || (oj == mine && j < i);
    }
    sel[i] = (rank >= SELC - TOPK) ? 1 : 0;
    __syncthreads();
    int gcnt = 0;
    for (int j = 0; j < i; j++) gcnt += sel[j];
    if (sel[i]) g_gidx[nh * 1024 + c * TOPK + gcnt] = c * SELC + i;
    else        g_lidx[nh * 3072 + c * (SELC - TOPK) + (i - gcnt)] = c * SELC + i;
}

// ---------------------------------------------------------------------------
// Global pass: 64 queries/block; thread = (2 queries x 16 dims); 128 threads.
// Quad shfl butterfly reduces the 4 dim-groups.
// ---------------------------------------------------------------------------
__global__ __launch_bounds__(128) void attn_global(const float* __restrict__ mask)
{
    int qb = blockIdx.x;
    int h  = blockIdx.y, n = blockIdx.z;
    int nh = n * NHD + h;
    __shared__ float ks[48][DH];
    __shared__ float vs[48][DH];
    __shared__ float am[48];
    __shared__ float sc[48][SELC];
    int tid = threadIdx.x;
    int qg = tid >> 2, dg = tid & 3;
    int qt = qb * SELC + qg * 2;
    int db = dg * 16;

    for (int idx = tid; idx < 48 * DH; idx += 128) {
        int s = idx >> 6, d = idx & 63;
        int gs = qb * 16 - 16 + s;
        if (gs >= 0 && gs < 1024) {
            int tok = g_gidx[nh * 1024 + gs];
            ks[s][d] = g_k[((size_t)nh * TT + tok) * DH + d];
            vs[s][d] = g_v[((size_t)nh * TT + tok) * DH + d];
            if (d == 0) am[s] = mask[n * TT + tok];
        } else {
            ks[s][d] = 0.f; vs[s][d] = 0.f;
            if (d == 0) am[s] = -1e30f;
        }
    }
    __syncthreads();

    float qreg[2][16];
    #pragma unroll
    for (int j = 0; j < 2; j++) {
        const float* qp = &g_q[((size_t)nh * TT + qt + j) * DH + db];
        #pragma unroll
        for (int d = 0; d < 16; d += 4) {
            float4 t4 = *(const float4*)(qp + d);
            qreg[j][d] = t4.x; qreg[j][d+1] = t4.y; qreg[j][d+2] = t4.z; qreg[j][d+3] = t4.w;
        }
    }

    float tmax[2] = {-1e30f, -1e30f};
    for (int s = 0; s < 48; s++) {
        float4 k0 = *(const float4*)&ks[s][db];
        float4 k1 = *(const float4*)&ks[s][db + 4];
        float4 k2 = *(const float4*)&ks[s][db + 8];
        float4 k3 = *(const float4*)&ks[s][db + 12];
        float p0 = dot16(qreg[0], k0, k1, k2, k3);
        float p1 = dot16(qreg[1], k0, k1, k2, k3);
        p0 += __shfl_xor_sync(0xffffffffu, p0, 1);
        p0 += __shfl_xor_sync(0xffffffffu, p0, 2);
        p1 += __shfl_xor_sync(0xffffffffu, p1, 1);
        p1 += __shfl_xor_sync(0xffffffffu, p1, 2);
        float a = am[s];
        float v0 = (a > -1e29f) ? p0 * 0.125f + a : -1e30f;
        float v1 = (a > -1e29f) ? p1 * 0.125f + a : -1e30f;
        tmax[0] = fmaxf(tmax[0], v0);
        tmax[1] = fmaxf(tmax[1], v1);
        if (dg == 0) { float2 vv = {v0, v1}; *(float2*)&sc[s][qg * 2] = vv; }
    }
    __syncwarp();

    float l[2] = {0.f, 0.f};
    float acc[2][16];
    #pragma unroll
    for (int j = 0; j < 2; j++)
        #pragma unroll
        for (int d = 0; d < 16; d++) acc[j][d] = 0.f;

    for (int s = 0; s < 48; s++) {
        float2 pv = *(const float2*)&sc[s][qg * 2];
        float p0 = (pv.x > -1e29f) ? __expf(pv.x - tmax[0]) : 0.f;
        float p1 = (pv.y > -1e29f) ? __expf(pv.y - tmax[1]) : 0.f;
        l[0] += p0; l[1] += p1;
        float4 v0 = *(const float4*)&vs[s][db];
        float4 v1 = *(const float4*)&vs[s][db + 4];
        float4 v2 = *(const float4*)&vs[s][db + 8];
        float4 v3 = *(const float4*)&vs[s][db + 12];
        acc[0][0]  += p0*v0.x; acc[0][1]  += p0*v0.y; acc[0][2]  += p0*v0.z; acc[0][3]  += p0*v0.w;
        acc[0][4]  += p0*v1.x; acc[0][5]  += p0*v1.y; acc[0][6]  += p0*v1.z; acc[0][7]  += p0*v1.w;
        acc[0][8]  += p0*v2.x; acc[0][9]  += p0*v2.y; acc[0][10] += p0*v2.z; acc[0][11] += p0*v2.w;
        acc[0][12] += p0*v3.x; acc[0][13] += p0*v3.y; acc[0][14] += p0*v3.z; acc[0][15] += p0*v3.w;
        acc[1][0]  += p1*v0.x; acc[1][1]  += p1*v0.y; acc[1][2]  += p1*v0.z; acc[1][3]  += p1*v0.w;
        acc[1][4]  += p1*v1.x; acc[1][5]  += p1*v1.y; acc[1][6]  += p1*v1.z; acc[1][7]  += p1*v1.w;
        acc[1][8]  += p1*v2.x; acc[1][9]  += p1*v2.y; acc[1][10] += p1*v2.z; acc[1][11] += p1*v2.w;
        acc[1][12] += p1*v3.x; acc[1][13] += p1*v3.y; acc[1][14] += p1*v3.z; acc[1][15] += p1*v3.w;
    }

    #pragma unroll
    for (int j = 0; j < 2; j++) {
        float inv = 1.f / l[j];
        float* cg = &g_ctxg[((size_t)nh * TT + qt + j) * DH + db];
        #pragma unroll
        for (int d = 0; d < 16; d += 4) {
            float4 o;
            o.x = acc[j][d] * inv; o.y = acc[j][d+1] * inv;
            o.z = acc[j][d+2] * inv; o.w = acc[j][d+3] * inv;
            *(float4*)(cg + d) = o;
        }
        if (dg == 0) g_lseg[nh * TT + qt + j] = tmax[j] + __logf(l[j]);
    }
}

// ---------------------------------------------------------------------------
// Local pass + merge: 128 queries/block; thread = (2 queries x 16 dims);
// 256 threads. Online softmax per 32-slot tile; final merge with global pass.
// ---------------------------------------------------------------------------
__global__ __launch_bounds__(256) void attn_local(const float* __restrict__ mask,
                                                  float* __restrict__ out)
{
    int qb = blockIdx.x;
    int h  = blockIdx.y, n = blockIdx.z;
    int nh = n * NHD + h;
    __shared__ float ks[32][DH];
    __shared__ float vs[32][DH];
    __shared__ float am[32];
    __shared__ int   toks[32];
    __shared__ float sc[32][128];

    int tid = threadIdx.x;
    int qg = tid >> 2, dg = tid & 3;
    int qt = qb * LOCC + qg * 2;
    int db = dg * 16;

    float qreg[2][16];
    #pragma unroll
    for (int j = 0; j < 2; j++) {
        const float* qp = &g_q[((size_t)nh * TT + qt + j) * DH + db];
        #pragma unroll
        for (int d = 0; d < 16; d += 4) {
            float4 t4 = *(const float4*)(qp + d);
            qreg[j][d] = t4.x; qreg[j][d+1] = t4.y; qreg[j][d+2] = t4.z; qreg[j][d+3] = t4.w;
        }
    }

    float acc[2][16];
    float m[2], l[2];
    #pragma unroll
    for (int j = 0; j < 2; j++) {
        m[j] = -1e30f; l[j] = 0.f;
        #pragma unroll
        for (int d = 0; d < 16; d++) acc[j][d] = 0.f;
    }
    int base = qb * 96 - 96;

    for (int t0 = 0; t0 < 288; t0 += 32) {
        if (tid < 32) {
            int gs = base + t0 + tid;
            int tok = (gs >= 0 && gs < 3072) ? g_lidx[nh * 3072 + gs] : -1;
            toks[tid] = tok;
            am[tid] = (tok >= 0) ? mask[n * TT + tok] : -1e30f;
        }
        __syncthreads();
        for (int idx = tid; idx < 32 * DH; idx += 256) {
            int s = idx >> 6, d = idx & 63;
            int tok = toks[s];
            if (tok >= 0) {
                ks[s][d] = g_k[((size_t)nh * TT + tok) * DH + d];
                vs[s][d] = g_v[((size_t)nh * TT + tok) * DH + d];
            } else { ks[s][d] = 0.f; vs[s][d] = 0.f; }
        }
        __syncthreads();

        float tmax[2] = {-1e30f, -1e30f};
        for (int s = 0; s < 32; s++) {
            float4 k0 = *(const float4*)&ks[s][db];
            float4 k1 = *(const float4*)&ks[s][db + 4];
            float4 k2 = *(const float4*)&ks[s][db + 8];
            float4 k3 = *(const float4*)&ks[s][db + 12];
            float p0 = dot16(qreg[0], k0, k1, k2, k3);
            float p1 = dot16(qreg[1], k0, k1, k2, k3);
            p0 += __shfl_xor_sync(0xffffffffu, p0, 1);
            p0 += __shfl_xor_sync(0xffffffffu, p0, 2);
            p1 += __shfl_xor_sync(0xffffffffu, p1, 1);
            p1 += __shfl_xor_sync(0xffffffffu, p1, 2);
            float a = am[s];
            float v0 = (a > -1e29f) ? p0 * 0.125f + a : -1e30f;
            float v1 = (a > -1e29f) ? p1 * 0.125f + a : -1e30f;
            tmax[0] = fmaxf(tmax[0], v0);
            tmax[1] = fmaxf(tmax[1], v1);
            if (dg == 0) { float2 vv = {v0, v1}; *(float2*)&sc[s][qg * 2] = vv; }
        }
        __syncwarp();

        if (tmax[0] > -1e29f || tmax[1] > -1e29f) {
            #pragma unroll
            for (int j = 0; j < 2; j++) {
                float nm = fmaxf(m[j], tmax[j]);
                float scl = __expf(m[j] - nm);
                l[j] *= scl;
                #pragma unroll
                for (int d = 0; d < 16; d++) acc[j][d] *= scl;
                m[j] = nm;
            }
            for (int s = 0; s < 32; s++) {
                float2 pv = *(const float2*)&sc[s][qg * 2];
                float p0 = (pv.x > -1e29f) ? __expf(pv.x - m[0]) : 0.f;
                float p1 = (pv.y > -1e29f) ? __expf(pv.y - m[1]) : 0.f;
                l[0] += p0; l[1] += p1;
                float4 v0 = *(const float4*)&vs[s][db];
                float4 v1 = *(const float4*)&vs[s][db + 4];
                float4 v2 = *(const float4*)&vs[s][db + 8];
                float4 v3 = *(const float4*)&vs[s][db + 12];
                acc[0][0]  += p0*v0.x; acc[0][1]  += p0*v0.y; acc[0][2]  += p0*v0.z; acc[0][3]  += p0*v0.w;
                acc[0][4]  += p0*v1.x; acc[0][5]  += p0*v1.y; acc[0][6]  += p0*v1.z; acc[0][7]  += p0*v1.w;
                acc[0][8]  += p0*v2.x; acc[0][9]  += p0*v2.y; acc[0][10] += p0*v2.z; acc[0][11] += p0*v2.w;
                acc[0][12] += p0*v3.x; acc[0][13] += p0*v3.y; acc[0][14] += p0*v3.z; acc[0][15] += p0*v3.w;
                acc[1][0]  += p1*v0.x; acc[1][1]  += p1*v0.y; acc[1][2]  += p1*v0.z; acc[1][3]  += p1*v0.w;
                acc[1][4]  += p1*v1.x; acc[1][5]  += p1*v1.y; acc[1][6]  += p1*v1.z; acc[1][7]  += p1*v1.w;
                acc[1][8]  += p1*v2.x; acc[1][9]  += p1*v2.y; acc[1][10] += p1*v2.z; acc[1][11] += p1*v2.w;
                acc[1][12] += p1*v3.x; acc[1][13] += p1*v3.y; acc[1][14] += p1*v3.z; acc[1][15] += p1*v3.w;
            }
        }
        __syncthreads();
    }

    // appended global key (token 0, additive mask 0)
    {
        const float* k0p = &g_k[(size_t)nh * TT * DH + db];
        const float* v0p = &g_v[(size_t)nh * TT * DH + db];
        float4 k0 = *(const float4*)(k0p);
        float4 k1 = *(const float4*)(k0p + 4);
        float4 k2 = *(const float4*)(k0p + 8);
        float4 k3 = *(const float4*)(k0p + 12);
        float v0r[16];
        #pragma unroll
        for (int d = 0; d < 16; d++) v0r[d] = v0p[d];
        float p0 = dot16(qreg[0], k0, k1, k2, k3);
        float p1 = dot16(qreg[1], k0, k1, k2, k3);
        p0 += __shfl_xor_sync(0xffffffffu, p0, 1);
        p0 += __shfl_xor_sync(0xffffffffu, p0, 2);
        p1 += __shfl_xor_sync(0xffffffffu, p1, 1);
        p1 += __shfl_xor_sync(0xffffffffu, p1, 2);
        float pp[2] = {p0, p1};
        #pragma unroll
        for (int j = 0; j < 2; j++) {
            float s = pp[j] * 0.125f;
            float nm = fmaxf(m[j], s);
            float scl = __expf(m[j] - nm);
            float pe = __expf(s - nm);
            l[j] = l[j] * scl + pe;
            #pragma unroll
            for (int d = 0; d < 16; d++) acc[j][d] = acc[j][d] * scl + pe * v0r[d];
            m[j] = nm;
        }
    }

    // merge with global pass and write output
    #pragma unroll
    for (int j = 0; j < 2; j++) {
        float lsel = m[j] + __logf(l[j]);
        float lseg = g_lseg[nh * TT + qt + j];
        float pmix = 1.f / (1.f + __expf(lseg - lsel));
        float invl = 1.f / l[j];
        const float* cg = &g_ctxg[((size_t)nh * TT + qt + j) * DH + db];
        float* op = &out[((size_t)n * TT + qt + j) * HID + h * DH + db];
        #pragma unroll
        for (int d = 0; d < 16; d += 4) {
            float4 cgv = *(const float4*)(cg + d);
            float4 o;
            o.x = cgv.x + pmix * (acc[j][d]   * invl - cgv.x);
            o.y = cgv.y + pmix * (acc[j][d+1] * invl - cgv.y);
            o.z = cgv.z + pmix * (acc[j][d+2] * invl - cgv.z);
            o.w = cgv.w + pmix * (acc[j][d+3] * invl - cgv.w);
            *(float4*)(op + d) = o;
        }
    }
}

// ---------------------------------------------------------------------------
// BOS: token-0 query, full UNscaled attention over all 4096 keys + mask.
// ---------------------------------------------------------------------------
__global__ __launch_bounds__(512) void attn_bos(const float* __restrict__ mask,
                                                float* __restrict__ out)
{
    int h = blockIdx.x, n = blockIdx.y;
    int nh = n * NHD + h;
    __shared__ float sc[TT];
    __shared__ float q0s[DH];
    __shared__ float red[512];
    __shared__ float part[8][DH];
    int tid = threadIdx.x;
    if (tid < DH) q0s[tid] = g_q[(size_t)nh * TT * DH + tid];
    __syncthreads();

    float lmax = -1e30f;
    for (int t = tid; t < TT; t += 512) {
        const float* kp = &g_k[((size_t)nh * TT + t) * DH];
        float dot = 0.f;
        #pragma unroll
        for (int d = 0; d < DH; d += 4) {
            float4 kv = *(const float4*)&kp[d];
            dot += q0s[d]*kv.x + q0s[d+1]*kv.y + q0s[d+2]*kv.z + q0s[d+3]*kv.w;
        }
        float s = dot + mask[n * TT + t];
        sc[t] = s;
        lmax = fmaxf(lmax, s);
    }
    red[tid] = lmax; __syncthreads();
    for (int o = 256; o > 0; o >>= 1) {
        if (tid < o) red[tid] = fmaxf(red[tid], red[tid + o]);
        __syncthreads();
    }
    float mx = red[0]; __syncthreads();

    float ls = 0.f;
    for (int t = tid; t < TT; t += 512) {
        float p = expf(sc[t] - mx);
        sc[t] = p;
        ls += p;
    }
    red[tid] = ls; __syncthreads();
    for (int o = 256; o > 0; o >>= 1) {
        if (tid < o) red[tid] += red[tid + o];
        __syncthreads();
    }
    float inv = 1.f / red[0];
    __syncthreads();

    {
        int d = tid & 63, sl = tid >> 6;
        float a = 0.f;
        int tstart = sl * 512;
        for (int t = tstart; t < tstart + 512; t++)
            a += sc[t] * g_v[((size_t)nh * TT + t) * DH + d];
        part[sl][d] = a;
    }
    __syncthreads();
    if (tid < DH) {
        float a = 0.f;
        #pragma unroll
        for (int sl = 0; sl < 8; sl++) a += part[sl][tid];
        out[(size_t)n * TT * HID + h * DH + tid] = a * inv;
    }
}

// ---------------------------------------------------------------------------
extern "C" void kernel_launch(void* const* d_in, const int* in_sizes, int n_in,
                              void* d_out, int out_size)
{
    const float* hs   = (const float*)d_in[0];
    const float* mask = (const float*)d_in[1];
    const float* Wq   = (const float*)d_in[2];
    const float* bq   = (const float*)d_in[3];
    const float* Wk   = (const float*)d_in[4];
    const float* bk   = (const float*)d_in[5];
    const float* Wv   = (const float*)d_in[6];
    const float* bv   = (const float*)d_in[7];
    float* out = (float*)d_out;

    static int attr_done = 0;
    if (!attr_done) {
        cudaFuncSetAttribute(gemm_f16, cudaFuncAttributeMaxDynamicSharedMemorySize,
                             GEMM_SMEM);
        attr_done = 1;
    }

    // resolve device-global scratch addresses (host side)
    __half *ah, *al, *wh, *wl;
    cudaGetSymbolAddress((void**)&ah, g_ah);
    cudaGetSymbolAddress((void**)&al, g_al);
    cudaGetSymbolAddress((void**)&wh, g_wh);
    cudaGetSymbolAddress((void**)&wl, g_wl);

    const int nA4 = 8192 * 1024 / 4;     // 2097152
    const int nW4 = 1024 * 1024 / 4;     // 262144
    split_f16<<<(nA4 + 255) / 256, 256>>>(hs, ah, al, nA4);
    split_f16<<<(nW4 + 255) / 256, 256>>>(Wq, wh,            wl,            nW4);
    split_f16<<<(nW4 + 255) / 256, 256>>>(Wk, wh + 1048576,  wl + 1048576,  nW4);
    split_f16<<<(nW4 + 255) / 256, 256>>>(Wv, wh + 2097152,  wl + 2097152,  nW4);

    gemm_f16<<<dim3(8, 64, 3), 256, GEMM_SMEM>>>(bq, bk, bv);

    norm_kernel<<<(NB * NHD * TT + 255) / 256, 256>>>(bq, mask);
    select_kernel<<<NB * NHD * 64, 64>>>();
    attn_global<<<dim3(64, NHD, NB), 128>>>(mask);
    attn_local<<<dim3(32, NHD, NB), 256>>>(mask, out);
    attn_bos<<<dim3(NHD, NB), 512>>>(mask, out);
}

// round 13
// speedup vs baseline: 2.0812x; 1.0379x over previous
#include <cuda_runtime.h>
#include <cuda_fp16.h>
#include <math.h>
#include <stdint.h>

// Problem dims
#define NB   2
#define TT   4096
#define NHD  16      // heads
#define DH   64      // head dim
#define HID  1024
#define SELC 64
#define TOPK 16
#define LOCC 128

// Scratch (device globals: allocation-free rule)
__device__ float g_q[(size_t)NB*NHD*TT*DH];
__device__ float g_k[(size_t)NB*NHD*TT*DH];
__device__ float g_v[(size_t)NB*NHD*TT*DH];
__device__ float g_ctxl[(size_t)NB*NHD*TT*DH];   // local-pass context
__device__ float g_lsel[NB*NHD*TT];              // local-pass lse
__device__ int   g_gidx[NB*NHD*1024];
__device__ int   g_lidx[NB*NHD*3072];

// fp16 split scratch
__device__ __half g_ah[(size_t)8192*1024];
__device__ __half g_al[(size_t)8192*1024];
__device__ __half g_wh[(size_t)3*1024*1024];
__device__ __half g_wl[(size_t)3*1024*1024];

// ---------------------------------------------------------------------------
// PTX helpers (plain PTX only — valid on target sm_103)
// ---------------------------------------------------------------------------
#define MMA_F16(c, a, b0, b1) \
    asm volatile("mma.sync.aligned.m16n8k16.row.col.f32.f16.f16.f32 " \
        "{%0,%1,%2,%3}, {%4,%5,%6,%7}, {%8,%9}, {%0,%1,%2,%3};" \
        : "+f"((c)[0]), "+f"((c)[1]), "+f"((c)[2]), "+f"((c)[3]) \
        : "r"((a)[0]), "r"((a)[1]), "r"((a)[2]), "r"((a)[3]), "r"(b0), "r"(b1))

#define LDSM_X4(r, addr) \
    asm volatile("ldmatrix.sync.aligned.m8n8.x4.shared.b16 {%0,%1,%2,%3}, [%4];" \
        : "=r"((r)[0]), "=r"((r)[1]), "=r"((r)[2]), "=r"((r)[3]) : "r"(addr))

__device__ __forceinline__ void cp16(uint32_t dst, const void* src) {
    asm volatile("cp.async.cg.shared.global [%0], [%1], 16;" :: "r"(dst), "l"(src));
}
#define CP_COMMIT() asm volatile("cp.async.commit_group;" ::: "memory")
#define CP_WAIT2()  asm volatile("cp.async.wait_group 2;" ::: "memory")
#define CP_WAIT1()  asm volatile("cp.async.wait_group 1;" ::: "memory")
#define CP_WAIT0()  asm volatile("cp.async.wait_group 0;" ::: "memory")

// 4-partial tree dot of 16 dims against float4 quads
__device__ __forceinline__ float dot16(const float* q, float4 k0, float4 k1,
                                       float4 k2, float4 k3) {
    float d0 = q[0]*k0.x + q[1]*k0.y + q[2]*k0.z + q[3]*k0.w;
    float d1 = q[4]*k1.x + q[5]*k1.y + q[6]*k1.z + q[7]*k1.w;
    float d2 = q[8]*k2.x + q[9]*k2.y + q[10]*k2.z + q[11]*k2.w;
    float d3 = q[12]*k3.x + q[13]*k3.y + q[14]*k3.z + q[15]*k3.w;
    return (d0 + d1) + (d2 + d3);
}

// ---------------------------------------------------------------------------
// Fused fp32 -> (fp16 hi, fp16 lo) split for hidden + Wq + Wk + Wv (1 launch)
// ---------------------------------------------------------------------------
#define NA4 2097152                 // hidden float4 count
#define NW4 262144                  // per-W float4 count
__global__ void split_all(const float* __restrict__ hs,
                          const float* __restrict__ Wq,
                          const float* __restrict__ Wk,
                          const float* __restrict__ Wv)
{
    int i = blockIdx.x * 256 + threadIdx.x;
    const float4* src; uint2* hid; uint2* lod; int off;
    if (i < NA4) {
        src = (const float4*)hs; hid = (uint2*)g_ah; lod = (uint2*)g_al; off = i;
    } else {
        int r = i - NA4;
        int w = r >> 18;            // 0,1,2
        int j = r & (NW4 - 1);
        src = (const float4*)(w == 0 ? Wq : (w == 1 ? Wk : Wv));
        hid = (uint2*)g_wh + (size_t)w * NW4;
        lod = (uint2*)g_wl + (size_t)w * NW4;
        off = j;
    }
    float4 v = src[off];
    __half h[4], l[4];
    h[0] = __float2half_rn(v.x); l[0] = __float2half_rn(v.x - __half2float(h[0]));
    h[1] = __float2half_rn(v.y); l[1] = __float2half_rn(v.y - __half2float(h[1]));
    h[2] = __float2half_rn(v.z); l[2] = __float2half_rn(v.z - __half2float(h[2]));
    h[3] = __float2half_rn(v.w); l[3] = __float2half_rn(v.w - __half2float(h[3]));
    hid[off] = *(uint2*)h;
    lod[off] = *(uint2*)l;
}

// ---------------------------------------------------------------------------
// fp16 mma GEMM. K (z==1): split-3 (err ~2^-22, protects top-k selection).
// Q,V (z==0,2): single product Ahi.Whi (err ~3e-4, continuous paths only).
// CTA 128x128, BK=32, 8 warps, 4-stage cp.async, ldmatrix.x4.
// ---------------------------------------------------------------------------
#define STG_BYTES 20480
#define GEMM_SMEM (4 * STG_BYTES)

__global__ __launch_bounds__(256, 2) void gemm_f16(
    const float* __restrict__ bq, const float* __restrict__ bk,
    const float* __restrict__ bv)
{
    extern __shared__ char smc[];
    uint32_t sbase;
    asm("{ .reg .u64 t; cvta.to.shared.u64 t, %1; cvt.u32.u64 %0, t; }"
        : "=r"(sbase) : "l"(smc));

    const int z = blockIdx.z;
    float* out = (z == 0) ? g_q : (z == 1) ? g_k : g_v;
    const float* bias = (z == 0) ? bq : (z == 1) ? bk : bv;
    const __half* Whi = g_wh + (size_t)z * 1048576;
    const __half* Wlo = g_wl + (size_t)z * 1048576;
    const int nch = (z == 1) ? 96 : 32;

    const int tid = threadIdx.x;
    const int wid = tid >> 5, lane = tid & 31;
    const int gid = lane >> 2, tq = lane & 3;
    const int row0 = blockIdx.y * 128, col0 = blockIdx.x * 128;
    const int warpM = (wid & 3) * 32, warpN = (wid >> 2) * 64;

    float acc[2][8][4];
    #pragma unroll
    for (int i = 0; i < 2; i++)
        #pragma unroll
        for (int j = 0; j < 8; j++)
            #pragma unroll
            for (int r = 0; r < 4; r++) acc[i][j][r] = 0.f;

    const int crow = tid >> 1;
    const int h2 = tid & 1;

    const int lg = lane >> 3;
    const int lr = lane & 7;
    uint32_t aoff[2];
    #pragma unroll
    for (int mt = 0; mt < 2; mt++)
        aoff[mt] = (uint32_t)((warpM + mt * 16 + (lg & 1) * 8 + lr) * 80 + (lg >> 1) * 16);
    uint32_t boff[4];
    #pragma unroll
    for (int p = 0; p < 4; p++)
        boff[p] = (uint32_t)(10240 + (warpN + p * 16 + (lg >> 1) * 8 + lr) * 80 + (lg & 1) * 16);

    auto issue_copy = [&](int c, int stg) {
        int kv = c * 32;
        int ph = kv >> 10;
        int kl = kv & 1023;
        const __half* aS; const __half* bS;
        if (z == 1) { aS = (ph == 2) ? g_al : g_ah; bS = (ph == 1) ? Wlo : Whi; }
        else        { aS = g_ah; bS = Whi; }
        const __half* asrc = aS + (size_t)(row0 + crow) * 1024 + kl + h2 * 16;
        const __half* bsrc = bS + (size_t)(col0 + crow) * 1024 + kl + h2 * 16;
        uint32_t ad = sbase + stg * STG_BYTES + crow * 80 + h2 * 32;
        uint32_t bd = ad + 10240;
        cp16(ad, asrc);      cp16(ad + 16, asrc + 8);
        cp16(bd, bsrc);      cp16(bd + 16, bsrc + 8);
    };

    #pragma unroll
    for (int s = 0; s < 3; s++) { issue_copy(s, s); CP_COMMIT(); }

    for (int c = 0; c < nch; c++) {
        CP_WAIT2();
        __syncthreads();
        int cn = c + 3;
        if (cn < nch) issue_copy(cn, cn & 3);
        CP_COMMIT();

        const uint32_t sstage = sbase + (c & 3) * STG_BYTES;
        #pragma unroll
        for (int ks = 0; ks < 2; ks++) {
            const uint32_t ko = ks * 32;
            uint32_t a0[4], a1[4];
            LDSM_X4(a0, sstage + aoff[0] + ko);
            LDSM_X4(a1, sstage + aoff[1] + ko);
            #pragma unroll
            for (int p = 0; p < 4; p++) {
                uint32_t br[4];
                LDSM_X4(br, sstage + boff[p] + ko);
                MMA_F16(acc[0][2*p],   a0, br[0], br[1]);
                MMA_F16(acc[1][2*p],   a1, br[0], br[1]);
                MMA_F16(acc[0][2*p+1], a0, br[2], br[3]);
                MMA_F16(acc[1][2*p+1], a1, br[2], br[3]);
            }
        }
    }

    const int hcol = col0 + warpN;
    const int h = hcol >> 6;
    float2 bb[8];
    #pragma unroll
    for (int nt = 0; nt < 8; nt++) {
        int cc = hcol + nt * 8 + 2 * tq;
        bb[nt].x = bias[cc];
        bb[nt].y = bias[cc + 1];
    }
    #pragma unroll
    for (int mt = 0; mt < 2; mt++) {
        #pragma unroll
        for (int rr = 0; rr < 2; rr++) {
            int grow = row0 + warpM + mt * 16 + gid + rr * 8;
            int nn = grow >> 12, t = grow & 4095;
            float* p = out + (((size_t)(nn * NHD + h)) * TT + t) * DH;
            #pragma unroll
            for (int nt = 0; nt < 8; nt++) {
                float2 v;
                v.x = acc[mt][nt][rr * 2]     + bb[nt].x;
                v.y = acc[mt][nt][rr * 2 + 1] + bb[nt].y;
                *(float2*)(p + nt * 8 + 2 * tq) = v;
            }
        }
    }
}

// ---------------------------------------------------------------------------
// Fused norm + selection: block = (n,h,chunk); 64 threads.
// norm_i = ||k_i + bq_h||^2 * (mask==0); stable rank -> top-16 / bottom-48.
// ---------------------------------------------------------------------------
__global__ __launch_bounds__(64) void select_norm(const float* __restrict__ bq,
                                                  const float* __restrict__ mask)
{
    int b  = blockIdx.x;
    int c  = b & 63;
    int nh = b >> 6;
    int n  = nh >> 4, h = nh & 15;
    int i  = threadIdx.x;
    __shared__ float nrm[64];
    __shared__ float bqs[64];
    __shared__ int   sel[64];

    bqs[i] = bq[h * DH + i];
    __syncthreads();

    int t = c * SELC + i;
    const float* kp = &g_k[((size_t)nh * TT + t) * DH];
    float s = 0.f;
    #pragma unroll
    for (int d = 0; d < DH; d += 4) {
        float4 kv = *(const float4*)&kp[d];
        float x0 = kv.x + bqs[d+0];
        float x1 = kv.y + bqs[d+1];
        float x2 = kv.z + bqs[d+2];
        float x3 = kv.w + bqs[d+3];
        s += x0*x0 + x1*x1 + x2*x2 + x3*x3;
    }
    float valid = (mask[n * TT + t] == 0.0f) ? 1.0f : 0.0f;
    nrm[i] = s * valid;
    __syncthreads();

    float mine = nrm[i];
    int rank = 0;
    #pragma unroll 8
    for (int j = 0; j < 64; j++) {
        float oj = nrm[j];
        rank += (oj < mine) || (oj == mine && j < i);
    }
    sel[i] = (rank >= SELC - TOPK) ? 1 : 0;
    __syncthreads();
    int gcnt = 0;
    for (int j = 0; j < i; j++) gcnt += sel[j];
    if (sel[i]) g_gidx[nh * 1024 + c * TOPK + gcnt] = c * SELC + i;
    else        g_lidx[nh * 3072 + c * (SELC - TOPK) + (i - gcnt)] = c * SELC + i;
}

// ---------------------------------------------------------------------------
// Local pass (runs FIRST now): 128 queries/block; thread = (2q x 16d);
// 256 threads. All 288 token idx/masks prefetched; K/V tiles double-buffered
// via cp.async gather. Writes ctx_l (g_ctxl) and lse_l (g_lsel).
// Dynamic smem layout:
//   [0, 16384)      stage0: K 8KB | V 8KB
//   [16384, 32768)  stage1
//   [32768, 49152)  sc[32][128]
//   [49152, 50304)  toks[288]
//   [50304, 51456)  am[288]
// ---------------------------------------------------------------------------
#define AL_SMEM 51456

__global__ __launch_bounds__(256) void attn_local(const float* __restrict__ mask)
{
    extern __shared__ char smc[];
    uint32_t sbase;
    asm("{ .reg .u64 t; cvta.to.shared.u64 t, %1; cvt.u32.u64 %0, t; }"
        : "=r"(sbase) : "l"(smc));
    float* scp = (float*)(smc + 32768);
    int*   toks_s = (int*)(smc + 49152);
    float* am_s   = (float*)(smc + 50304);

    int qb = blockIdx.x;
    int h  = blockIdx.y, n = blockIdx.z;
    int nh = n * NHD + h;

    int tid = threadIdx.x;
    int qg = tid >> 2, dg = tid & 3;
    int qt = qb * LOCC + qg * 2;
    int db = dg * 16;

    // prologue: all 288 window token indices + masks
    int base = qb * 96 - 96;
    for (int idx = tid; idx < 288; idx += 256) {
        int gs = base + idx;
        int tok = (gs >= 0 && gs < 3072) ? g_lidx[nh * 3072 + gs] : -1;
        toks_s[idx] = tok;
        am_s[idx] = (tok >= 0) ? mask[n * TT + tok] : -1e30f;
    }

    float qreg[2][16];
    #pragma unroll
    for (int j = 0; j < 2; j++) {
        const float* qp = &g_q[((size_t)nh * TT + qt + j) * DH + db];
        #pragma unroll
        for (int d = 0; d < 16; d += 4) {
            float4 t4 = *(const float4*)(qp + d);
            qreg[j][d] = t4.x; qreg[j][d+1] = t4.y; qreg[j][d+2] = t4.z; qreg[j][d+3] = t4.w;
        }
    }
    __syncthreads();

    // cp.async gather of one 32-slot tile into a stage
    const int grow = tid >> 2;          // 0..63: 0-31 K rows, 32-63 V rows
    const int gslot = grow & 31;
    const int gisV = grow >> 5;
    const int gseg = (tid & 3) * 16;    // float offset within 256B row
    auto issue_tile = [&](int tile, int stg) {
        int tok = toks_s[tile * 32 + gslot];
        if (tok < 0) tok = 0;           // masked slots get weight 0 anyway
        const float* src = (gisV ? g_v : g_k) + ((size_t)nh * TT + tok) * DH + gseg;
        uint32_t dst = sbase + stg * 16384 + gisV * 8192 + gslot * 256 + gseg * 4;
        cp16(dst, src);          cp16(dst + 16, src + 4);
        cp16(dst + 32, src + 8); cp16(dst + 48, src + 12);
    };

    float acc[2][16];
    float m[2], l[2];
    #pragma unroll
    for (int j = 0; j < 2; j++) {
        m[j] = -1e30f; l[j] = 0.f;
        #pragma unroll
        for (int d = 0; d < 16; d++) acc[j][d] = 0.f;
    }

    issue_tile(0, 0); CP_COMMIT();

    for (int ti = 0; ti < 9; ti++) {
        if (ti + 1 < 9) { issue_tile(ti + 1, (ti + 1) & 1); CP_COMMIT(); CP_WAIT1(); }
        else            { CP_WAIT0(); }
        __syncthreads();

        const char* kb = smc + (ti & 1) * 16384;
        const char* vb = kb + 8192;
        const float* amt = am_s + ti * 32;

        float tmax[2] = {-1e30f, -1e30f};
        for (int s = 0; s < 32; s++) {
            const char* kr = kb + s * 256 + db * 4;
            float4 k0 = *(const float4*)(kr);
            float4 k1 = *(const float4*)(kr + 16);
            float4 k2 = *(const float4*)(kr + 32);
            float4 k3 = *(const float4*)(kr + 48);
            float p0 = dot16(qreg[0], k0, k1, k2, k3);
            float p1 = dot16(qreg[1], k0, k1, k2, k3);
            p0 += __shfl_xor_sync(0xffffffffu, p0, 1);
            p0 += __shfl_xor_sync(0xffffffffu, p0, 2);
            p1 += __shfl_xor_sync(0xffffffffu, p1, 1);
            p1 += __shfl_xor_sync(0xffffffffu, p1, 2);
            float a = amt[s];
            float v0 = (a > -1e29f) ? p0 * 0.125f + a : -1e30f;
            float v1 = (a > -1e29f) ? p1 * 0.125f + a : -1e30f;
            tmax[0] = fmaxf(tmax[0], v0);
            tmax[1] = fmaxf(tmax[1], v1);
            if (dg == 0) { float2 vv = {v0, v1}; *(float2*)&scp[s * 128 + qg * 2] = vv; }
        }
        __syncwarp();

        if (tmax[0] > -1e29f || tmax[1] > -1e29f) {
            #pragma unroll
            for (int j = 0; j < 2; j++) {
                float nm = fmaxf(m[j], tmax[j]);
                float scl = __expf(m[j] - nm);
                l[j] *= scl;
                #pragma unroll
                for (int d = 0; d < 16; d++) acc[j][d] *= scl;
                m[j] = nm;
            }
            for (int s = 0; s < 32; s++) {
                float2 pv = *(const float2*)&scp[s * 128 + qg * 2];
                float p0 = (pv.x > -1e29f) ? __expf(pv.x - m[0]) : 0.f;
                float p1 = (pv.y > -1e29f) ? __expf(pv.y - m[1]) : 0.f;
                l[0] += p0; l[1] += p1;
                const char* vr = vb + s * 256 + db * 4;
                float4 v0 = *(const float4*)(vr);
                float4 v1 = *(const float4*)(vr + 16);
                float4 v2 = *(const float4*)(vr + 32);
                float4 v3 = *(const float4*)(vr + 48);
                acc[0][0]  += p0*v0.x; acc[0][1]  += p0*v0.y; acc[0][2]  += p0*v0.z; acc[0][3]  += p0*v0.w;
                acc[0][4]  += p0*v1.x; acc[0][5]  += p0*v1.y; acc[0][6]  += p0*v1.z; acc[0][7]  += p0*v1.w;
                acc[0][8]  += p0*v2.x; acc[0][9]  += p0*v2.y; acc[0][10] += p0*v2.z; acc[0][11] += p0*v2.w;
                acc[0][12] += p0*v3.x; acc[0][13] += p0*v3.y; acc[0][14] += p0*v3.z; acc[0][15] += p0*v3.w;
                acc[1][0]  += p1*v0.x; acc[1][1]  += p1*v0.y; acc[1][2]  += p1*v0.z; acc[1][3]  += p1*v0.w;
                acc[1][4]  += p1*v1.x; acc[1][5]  += p1*v1.y; acc[1][6]  += p1*v1.z; acc[1][7]  += p1*v1.w;
                acc[1][8]  += p1*v2.x; acc[1][9]  += p1*v2.y; acc[1][10] += p1*v2.z; acc[1][11] += p1*v2.w;
                acc[1][12] += p1*v3.x; acc[1][13] += p1*v3.y; acc[1][14] += p1*v3.z; acc[1][15] += p1*v3.w;
            }
        }
        __syncthreads();
    }

    // appended global key (token 0, additive mask 0)
    {
        const float* k0p = &g_k[(size_t)nh * TT * DH + db];
        const float* v0p = &g_v[(size_t)nh * TT * DH + db];
        float4 k0 = *(const float4*)(k0p);
        float4 k1 = *(const float4*)(k0p + 4);
        float4 k2 = *(const float4*)(k0p + 8);
        float4 k3 = *(const float4*)(k0p + 12);
        float v0r[16];
        #pragma unroll
        for (int d = 0; d < 16; d++) v0r[d] = v0p[d];
        float p0 = dot16(qreg[0], k0, k1, k2, k3);
        float p1 = dot16(qreg[1], k0, k1, k2, k3);
        p0 += __shfl_xor_sync(0xffffffffu, p0, 1);
        p0 += __shfl_xor_sync(0xffffffffu, p0, 2);
        p1 += __shfl_xor_sync(0xffffffffu, p1, 1);
        p1 += __shfl_xor_sync(0xffffffffu, p1, 2);
        float pp[2] = {p0, p1};
        #pragma unroll
        for (int j = 0; j < 2; j++) {
            float s = pp[j] * 0.125f;
            float nm = fmaxf(m[j], s);
            float scl = __expf(m[j] - nm);
            float pe = __expf(s - nm);
            l[j] = l[j] * scl + pe;
            #pragma unroll
            for (int d = 0; d < 16; d++) acc[j][d] = acc[j][d] * scl + pe * v0r[d];
            m[j] = nm;
        }
    }

    // store local context + lse
    #pragma unroll
    for (int j = 0; j < 2; j++) {
        float invl = 1.f / l[j];
        float* cl = &g_ctxl[((size_t)nh * TT + qt + j) * DH + db];
        #pragma unroll
        for (int d = 0; d < 16; d += 4) {
            float4 o;
            o.x = acc[j][d] * invl; o.y = acc[j][d+1] * invl;
            o.z = acc[j][d+2] * invl; o.w = acc[j][d+3] * invl;
            *(float4*)(cl + d) = o;
        }
        if (dg == 0) g_lsel[nh * TT + qt + j] = m[j] + __logf(l[j]);
    }
}

// ---------------------------------------------------------------------------
// Global pass + MERGE (runs second): 64 queries/block; thread = (2q x 16d);
// 128 threads. Computes ctx_g/lse_g in-register, merges with (ctx_l, lse_l),
// writes final out.
// ---------------------------------------------------------------------------
__global__ __launch_bounds__(128) void attn_global(const float* __restrict__ mask,
                                                   float* __restrict__ out)
{
    int qb = blockIdx.x;
    int h  = blockIdx.y, n = blockIdx.z;
    int nh = n * NHD + h;
    __shared__ float ks[48][DH];
    __shared__ float vs[48][DH];
    __shared__ float am[48];
    __shared__ float sc[48][SELC];
    int tid = threadIdx.x;
    int qg = tid >> 2, dg = tid & 3;
    int qt = qb * SELC + qg * 2;
    int db = dg * 16;

    for (int idx = tid; idx < 48 * DH; idx += 128) {
        int s = idx >> 6, d = idx & 63;
        int gs = qb * 16 - 16 + s;
        if (gs >= 0 && gs < 1024) {
            int tok = g_gidx[nh * 1024 + gs];
            ks[s][d] = g_k[((size_t)nh * TT + tok) * DH + d];
            vs[s][d] = g_v[((size_t)nh * TT + tok) * DH + d];
            if (d == 0) am[s] = mask[n * TT + tok];
        } else {
            ks[s][d] = 0.f; vs[s][d] = 0.f;
            if (d == 0) am[s] = -1e30f;
        }
    }
    __syncthreads();

    float qreg[2][16];
    #pragma unroll
    for (int j = 0; j < 2; j++) {
        const float* qp = &g_q[((size_t)nh * TT + qt + j) * DH + db];
        #pragma unroll
        for (int d = 0; d < 16; d += 4) {
            float4 t4 = *(const float4*)(qp + d);
            qreg[j][d] = t4.x; qreg[j][d+1] = t4.y; qreg[j][d+2] = t4.z; qreg[j][d+3] = t4.w;
        }
    }

    float tmax[2] = {-1e30f, -1e30f};
    for (int s = 0; s < 48; s++) {
        float4 k0 = *(const float4*)&ks[s][db];
        float4 k1 = *(const float4*)&ks[s][db + 4];
        float4 k2 = *(const float4*)&ks[s][db + 8];
        float4 k3 = *(const float4*)&ks[s][db + 12];
        float p0 = dot16(qreg[0], k0, k1, k2, k3);
        float p1 = dot16(qreg[1], k0, k1, k2, k3);
        p0 += __shfl_xor_sync(0xffffffffu, p0, 1);
        p0 += __shfl_xor_sync(0xffffffffu, p0, 2);
        p1 += __shfl_xor_sync(0xffffffffu, p1, 1);
        p1 += __shfl_xor_sync(0xffffffffu, p1, 2);
        float a = am[s];
        float v0 = (a > -1e29f) ? p0 * 0.125f + a : -1e30f;
        float v1 = (a > -1e29f) ? p1 * 0.125f + a : -1e30f;
        tmax[0] = fmaxf(tmax[0], v0);
        tmax[1] = fmaxf(tmax[1], v1);
        if (dg == 0) { float2 vv = {v0, v1}; *(float2*)&sc[s][qg * 2] = vv; }
    }
    __syncwarp();

    float l[2] = {0.f, 0.f};
    float acc[2][16];
    #pragma unroll
    for (int j = 0; j < 2; j++)
        #pragma unroll
        for (int d = 0; d < 16; d++) acc[j][d] = 0.f;

    for (int s = 0; s < 48; s++) {
        float2 pv = *(const float2*)&sc[s][qg * 2];
        float p0 = (pv.x > -1e29f) ? __expf(pv.x - tmax[0]) : 0.f;
        float p1 = (pv.y > -1e29f) ? __expf(pv.y - tmax[1]) : 0.f;
        l[0] += p0; l[1] += p1;
        float4 v0 = *(const float4*)&vs[s][db];
        float4 v1 = *(const float4*)&vs[s][db + 4];
        float4 v2 = *(const float4*)&vs[s][db + 8];
        float4 v3 = *(const float4*)&vs[s][db + 12];
        acc[0][0]  += p0*v0.x; acc[0][1]  += p0*v0.y; acc[0][2]  += p0*v0.z; acc[0][3]  += p0*v0.w;
        acc[0][4]  += p0*v1.x; acc[0][5]  += p0*v1.y; acc[0][6]  += p0*v1.z; acc[0][7]  += p0*v1.w;
        acc[0][8]  += p0*v2.x; acc[0][9]  += p0*v2.y; acc[0][10] += p0*v2.z; acc[0][11] += p0*v2.w;
        acc[0][12] += p0*v3.x; acc[0][13] += p0*v3.y; acc[0][14] += p0*v3.z; acc[0][15] += p0*v3.w;
        acc[1][0]  += p1*v0.x; acc[1][1]  += p1*v0.y; acc[1][2]  += p1*v0.z; acc[1][3]  += p1*v0.w;
        acc[1][4]  += p1*v1.x; acc[1][5]  += p1*v1.y; acc[1][6]  += p1*v1.z; acc[1][7]  += p1*v1.w;
        acc[1][8]  += p1*v2.x; acc[1][9]  += p1*v2.y; acc[1][10] += p1*v2.z; acc[1][11] += p1*v2.w;
        acc[1][12] += p1*v3.x; acc[1][13] += p1*v3.y; acc[1][14] += p1*v3.z; acc[1][15] += p1*v3.w;
    }

    // merge with local pass, write final output
    #pragma unroll
    for (int j = 0; j < 2; j++) {
        float lseg = tmax[j] + __logf(l[j]);
        float lsel = g_lsel[nh * TT + qt + j];
        float pmix = 1.f / (1.f + __expf(lseg - lsel));
        float invg = 1.f / l[j];
        const float* cl = &g_ctxl[((size_t)nh * TT + qt + j) * DH + db];
        float* op = &out[((size_t)n * TT + qt + j) * HID + h * DH + db];
        #pragma unroll
        for (int d = 0; d < 16; d += 4) {
            float4 clv = *(const float4*)(cl + d);
            float4 o;
            float g0 = acc[j][d]   * invg;
            float g1 = acc[j][d+1] * invg;
            float g2 = acc[j][d+2] * invg;
            float g3 = acc[j][d+3] * invg;
            o.x = g0 + pmix * (clv.x - g0);
            o.y = g1 + pmix * (clv.y - g1);
            o.z = g2 + pmix * (clv.z - g2);
            o.w = g3 + pmix * (clv.w - g3);
            *(float4*)(op + d) = o;
        }
    }
}

// ---------------------------------------------------------------------------
// BOS: token-0 query, full UNscaled attention over all 4096 keys + mask.
// ---------------------------------------------------------------------------
__global__ __launch_bounds__(512) void attn_bos(const float* __restrict__ mask,
                                                float* __restrict__ out)
{
    int h = blockIdx.x, n = blockIdx.y;
    int nh = n * NHD + h;
    __shared__ float sc[TT];
    __shared__ float q0s[DH];
    __shared__ float red[512];
    __shared__ float part[8][DH];
    int tid = threadIdx.x;
    if (tid < DH) q0s[tid] = g_q[(size_t)nh * TT * DH + tid];
    __syncthreads();

    float lmax = -1e30f;
    for (int t = tid; t < TT; t += 512) {
        const float* kp = &g_k[((size_t)nh * TT + t) * DH];
        float dot = 0.f;
        #pragma unroll
        for (int d = 0; d < DH; d += 4) {
            float4 kv = *(const float4*)&kp[d];
            dot += q0s[d]*kv.x + q0s[d+1]*kv.y + q0s[d+2]*kv.z + q0s[d+3]*kv.w;
        }
        float s = dot + mask[n * TT + t];
        sc[t] = s;
        lmax = fmaxf(lmax, s);
    }
    red[tid] = lmax; __syncthreads();
    for (int o = 256; o > 0; o >>= 1) {
        if (tid < o) red[tid] = fmaxf(red[tid], red[tid + o]);
        __syncthreads();
    }
    float mx = red[0]; __syncthreads();

    float ls = 0.f;
    for (int t = tid; t < TT; t += 512) {
        float p = expf(sc[t] - mx);
        sc[t] = p;
        ls += p;
    }
    red[tid] = ls; __syncthreads();
    for (int o = 256; o > 0; o >>= 1) {
        if (tid < o) red[tid] += red[tid + o];
        __syncthreads();
    }
    float inv = 1.f / red[0];
    __syncthreads();

    {
        int d = tid & 63, sl = tid >> 6;
        float a = 0.f;
        int tstart = sl * 512;
        for (int t = tstart; t < tstart + 512; t++)
            a += sc[t] * g_v[((size_t)nh * TT + t) * DH + d];
        part[sl][d] = a;
    }
    __syncthreads();
    if (tid < DH) {
        float a = 0.f;
        #pragma unroll
        for (int sl = 0; sl < 8; sl++) a += part[sl][tid];
        out[(size_t)n * TT * HID + h * DH + tid] = a * inv;
    }
}

// ---------------------------------------------------------------------------
extern "C" void kernel_launch(void* const* d_in, const int* in_sizes, int n_in,
                              void* d_out, int out_size)
{
    const float* hs   = (const float*)d_in[0];
    const float* mask = (const float*)d_in[1];
    const float* Wq   = (const float*)d_in[2];
    const float* bq   = (const float*)d_in[3];
    const float* Wk   = (const float*)d_in[4];
    const float* bk   = (const float*)d_in[5];
    const float* Wv   = (const float*)d_in[6];
    const float* bv   = (const float*)d_in[7];
    float* out = (float*)d_out;

    static int attr_done = 0;
    if (!attr_done) {
        cudaFuncSetAttribute(gemm_f16, cudaFuncAttributeMaxDynamicSharedMemorySize,
                             GEMM_SMEM);
        cudaFuncSetAttribute(attn_local, cudaFuncAttributeMaxDynamicSharedMemorySize,
                             AL_SMEM);
        attr_done = 1;
    }

    // 1: fused split  2: gemm  3: select  4: attn_local (ncu target)
    // 5: attn_global+merge  6: bos
    split_all<<<(NA4 + 3 * NW4) / 256, 256>>>(hs, Wq, Wk, Wv);
    gemm_f16<<<dim3(8, 64, 3), 256, GEMM_SMEM>>>(bq, bk, bv);
    select_norm<<<NB * NHD * 64, 64>>>(bq, mask);
    attn_local<<<dim3(32, NHD, NB), 256, AL_SMEM>>>(mask);
    attn_global<<<dim3(64, NHD, NB), 128>>>(mask, out);
    attn_bos<<<dim3(NHD, NB), 512>>>(mask, out);
}

// round 14
// speedup vs baseline: 2.5383x; 1.2196x over previous
#include <cuda_runtime.h>
#include <cuda_fp16.h>
#include <math.h>
#include <stdint.h>

// Problem dims
#define NB   2
#define TT   4096
#define NHD  16      // heads
#define DH   64      // head dim
#define HID  1024
#define SELC 64
#define TOPK 16
#define LOCC 128

// Scratch (device globals: allocation-free rule)
__device__ float g_q[(size_t)NB*NHD*TT*DH];
__device__ float g_k[(size_t)NB*NHD*TT*DH];
__device__ float g_v[(size_t)NB*NHD*TT*DH];
__device__ float g_ctxl[(size_t)NB*NHD*TT*DH];   // local-pass context
__device__ float g_lsel[NB*NHD*TT];              // local-pass lse
__device__ int   g_gidx[NB*NHD*1024];
__device__ int   g_lidx[NB*NHD*3072];

// fp16 split scratch
__device__ __half g_ah[(size_t)8192*1024];
__device__ __half g_al[(size_t)8192*1024];
__device__ __half g_wh[(size_t)3*1024*1024];
__device__ __half g_wl[(size_t)3*1024*1024];

// ---------------------------------------------------------------------------
// PTX helpers (plain PTX only — valid on target sm_103)
// ---------------------------------------------------------------------------
#define MMA_F16(c, a, b0, b1) \
    asm volatile("mma.sync.aligned.m16n8k16.row.col.f32.f16.f16.f32 " \
        "{%0,%1,%2,%3}, {%4,%5,%6,%7}, {%8,%9}, {%0,%1,%2,%3};" \
        : "+f"((c)[0]), "+f"((c)[1]), "+f"((c)[2]), "+f"((c)[3]) \
        : "r"((a)[0]), "r"((a)[1]), "r"((a)[2]), "r"((a)[3]), "r"(b0), "r"(b1))

#define LDSM_X4(r, addr) \
    asm volatile("ldmatrix.sync.aligned.m8n8.x4.shared.b16 {%0,%1,%2,%3}, [%4];" \
        : "=r"((r)[0]), "=r"((r)[1]), "=r"((r)[2]), "=r"((r)[3]) : "r"(addr))

__device__ __forceinline__ void cp16(uint32_t dst, const void* src) {
    asm volatile("cp.async.cg.shared.global [%0], [%1], 16;" :: "r"(dst), "l"(src));
}
#define CP_COMMIT() asm volatile("cp.async.commit_group;" ::: "memory")
#define CP_WAIT2()  asm volatile("cp.async.wait_group 2;" ::: "memory")
#define CP_WAIT1()  asm volatile("cp.async.wait_group 1;" ::: "memory")
#define CP_WAIT0()  asm volatile("cp.async.wait_group 0;" ::: "memory")

// 4-partial tree dot of 16 dims against float4 quads
__device__ __forceinline__ float dot16(const float* q, float4 k0, float4 k1,
                                       float4 k2, float4 k3) {
    float d0 = q[0]*k0.x + q[1]*k0.y + q[2]*k0.z + q[3]*k0.w;
    float d1 = q[4]*k1.x + q[5]*k1.y + q[6]*k1.z + q[7]*k1.w;
    float d2 = q[8]*k2.x + q[9]*k2.y + q[10]*k2.z + q[11]*k2.w;
    float d3 = q[12]*k3.x + q[13]*k3.y + q[14]*k3.z + q[15]*k3.w;
    return (d0 + d1) + (d2 + d3);
}

// ---------------------------------------------------------------------------
// Fused fp32 -> (fp16 hi, fp16 lo) split for hidden + Wq + Wk + Wv (1 launch)
// ---------------------------------------------------------------------------
#define NA4 2097152                 // hidden float4 count
#define NW4 262144                  // per-W float4 count
__global__ void split_all(const float* __restrict__ hs,
                          const float* __restrict__ Wq,
                          const float* __restrict__ Wk,
                          const float* __restrict__ Wv)
{
    int i = blockIdx.x * 256 + threadIdx.x;
    const float4* src; uint2* hid; uint2* lod; int off;
    if (i < NA4) {
        src = (const float4*)hs; hid = (uint2*)g_ah; lod = (uint2*)g_al; off = i;
    } else {
        int r = i - NA4;
        int w = r >> 18;            // 0,1,2
        int j = r & (NW4 - 1);
        src = (const float4*)(w == 0 ? Wq : (w == 1 ? Wk : Wv));
        hid = (uint2*)g_wh + (size_t)w * NW4;
        lod = (uint2*)g_wl + (size_t)w * NW4;
        off = j;
    }
    float4 v = src[off];
    __half h[4], l[4];
    h[0] = __float2half_rn(v.x); l[0] = __float2half_rn(v.x - __half2float(h[0]));
    h[1] = __float2half_rn(v.y); l[1] = __float2half_rn(v.y - __half2float(h[1]));
    h[2] = __float2half_rn(v.z); l[2] = __float2half_rn(v.z - __half2float(h[2]));
    h[3] = __float2half_rn(v.w); l[3] = __float2half_rn(v.w - __half2float(h[3]));
    hid[off] = *(uint2*)h;
    lod[off] = *(uint2*)l;
}

// ---------------------------------------------------------------------------
// fp16 mma GEMM. K (z==1): split-3 (err ~2^-22, protects top-k selection).
// Q,V (z==0,2): single product Ahi.Whi (err ~3e-4, continuous paths only).
// CTA 128x128, BK=32, 8 warps, 4-stage cp.async, ldmatrix.x4.
// ---------------------------------------------------------------------------
#define STG_BYTES 20480
#define GEMM_SMEM (4 * STG_BYTES)

__global__ __launch_bounds__(256, 2) void gemm_f16(
    const float* __restrict__ bq, const float* __restrict__ bk,
    const float* __restrict__ bv)
{
    extern __shared__ char smc[];
    uint32_t sbase;
    asm("{ .reg .u64 t; cvta.to.shared.u64 t, %1; cvt.u32.u64 %0, t; }"
        : "=r"(sbase) : "l"(smc));

    const int z = blockIdx.z;
    float* out = (z == 0) ? g_q : (z == 1) ? g_k : g_v;
    const float* bias = (z == 0) ? bq : (z == 1) ? bk : bv;
    const __half* Whi = g_wh + (size_t)z * 1048576;
    const __half* Wlo = g_wl + (size_t)z * 1048576;
    const int nch = (z == 1) ? 96 : 32;

    const int tid = threadIdx.x;
    const int wid = tid >> 5, lane = tid & 31;
    const int gid = lane >> 2, tq = lane & 3;
    const int row0 = blockIdx.y * 128, col0 = blockIdx.x * 128;
    const int warpM = (wid & 3) * 32, warpN = (wid >> 2) * 64;

    float acc[2][8][4];
    #pragma unroll
    for (int i = 0; i < 2; i++)
        #pragma unroll
        for (int j = 0; j < 8; j++)
            #pragma unroll
            for (int r = 0; r < 4; r++) acc[i][j][r] = 0.f;

    const int crow = tid >> 1;
    const int h2 = tid & 1;

    const int lg = lane >> 3;
    const int lr = lane & 7;
    uint32_t aoff[2];
    #pragma unroll
    for (int mt = 0; mt < 2; mt++)
        aoff[mt] = (uint32_t)((warpM + mt * 16 + (lg & 1) * 8 + lr) * 80 + (lg >> 1) * 16);
    uint32_t boff[4];
    #pragma unroll
    for (int p = 0; p < 4; p++)
        boff[p] = (uint32_t)(10240 + (warpN + p * 16 + (lg >> 1) * 8 + lr) * 80 + (lg & 1) * 16);

    auto issue_copy = [&](int c, int stg) {
        int kv = c * 32;
        int ph = kv >> 10;
        int kl = kv & 1023;
        const __half* aS; const __half* bS;
        if (z == 1) { aS = (ph == 2) ? g_al : g_ah; bS = (ph == 1) ? Wlo : Whi; }
        else        { aS = g_ah; bS = Whi; }
        const __half* asrc = aS + (size_t)(row0 + crow) * 1024 + kl + h2 * 16;
        const __half* bsrc = bS + (size_t)(col0 + crow) * 1024 + kl + h2 * 16;
        uint32_t ad = sbase + stg * STG_BYTES + crow * 80 + h2 * 32;
        uint32_t bd = ad + 10240;
        cp16(ad, asrc);      cp16(ad + 16, asrc + 8);
        cp16(bd, bsrc);      cp16(bd + 16, bsrc + 8);
    };

    #pragma unroll
    for (int s = 0; s < 3; s++) { issue_copy(s, s); CP_COMMIT(); }

    for (int c = 0; c < nch; c++) {
        CP_WAIT2();
        __syncthreads();
        int cn = c + 3;
        if (cn < nch) issue_copy(cn, cn & 3);
        CP_COMMIT();

        const uint32_t sstage = sbase + (c & 3) * STG_BYTES;
        #pragma unroll
        for (int ks = 0; ks < 2; ks++) {
            const uint32_t ko = ks * 32;
            uint32_t a0[4], a1[4];
            LDSM_X4(a0, sstage + aoff[0] + ko);
            LDSM_X4(a1, sstage + aoff[1] + ko);
            #pragma unroll
            for (int p = 0; p < 4; p++) {
                uint32_t br[4];
                LDSM_X4(br, sstage + boff[p] + ko);
                MMA_F16(acc[0][2*p],   a0, br[0], br[1]);
                MMA_F16(acc[1][2*p],   a1, br[0], br[1]);
                MMA_F16(acc[0][2*p+1], a0, br[2], br[3]);
                MMA_F16(acc[1][2*p+1], a1, br[2], br[3]);
            }
        }
    }

    const int hcol = col0 + warpN;
    const int h = hcol >> 6;
    float2 bb[8];
    #pragma unroll
    for (int nt = 0; nt < 8; nt++) {
        int cc = hcol + nt * 8 + 2 * tq;
        bb[nt].x = bias[cc];
        bb[nt].y = bias[cc + 1];
    }
    #pragma unroll
    for (int mt = 0; mt < 2; mt++) {
        #pragma unroll
        for (int rr = 0; rr < 2; rr++) {
            int grow = row0 + warpM + mt * 16 + gid + rr * 8;
            int nn = grow >> 12, t = grow & 4095;
            float* p = out + (((size_t)(nn * NHD + h)) * TT + t) * DH;
            #pragma unroll
            for (int nt = 0; nt < 8; nt++) {
                float2 v;
                v.x = acc[mt][nt][rr * 2]     + bb[nt].x;
                v.y = acc[mt][nt][rr * 2 + 1] + bb[nt].y;
                *(float2*)(p + nt * 8 + 2 * tq) = v;
            }
        }
    }
}

// ---------------------------------------------------------------------------
// Fused norm + selection: block = (n,h,chunk); 64 threads.
// ---------------------------------------------------------------------------
__global__ __launch_bounds__(64) void select_norm(const float* __restrict__ bq,
                                                  const float* __restrict__ mask)
{
    int b  = blockIdx.x;
    int c  = b & 63;
    int nh = b >> 6;
    int n  = nh >> 4, h = nh & 15;
    int i  = threadIdx.x;
    __shared__ float nrm[64];
    __shared__ float bqs[64];
    __shared__ int   sel[64];

    bqs[i] = bq[h * DH + i];
    __syncthreads();

    int t = c * SELC + i;
    const float* kp = &g_k[((size_t)nh * TT + t) * DH];
    float s = 0.f;
    #pragma unroll
    for (int d = 0; d < DH; d += 4) {
        float4 kv = *(const float4*)&kp[d];
        float x0 = kv.x + bqs[d+0];
        float x1 = kv.y + bqs[d+1];
        float x2 = kv.z + bqs[d+2];
        float x3 = kv.w + bqs[d+3];
        s += x0*x0 + x1*x1 + x2*x2 + x3*x3;
    }
    float valid = (mask[n * TT + t] == 0.0f) ? 1.0f : 0.0f;
    nrm[i] = s * valid;
    __syncthreads();

    float mine = nrm[i];
    int rank = 0;
    #pragma unroll 8
    for (int j = 0; j < 64; j++) {
        float oj = nrm[j];
        rank += (oj < mine) || (oj == mine && j < i);
    }
    sel[i] = (rank >= SELC - TOPK) ? 1 : 0;
    __syncthreads();
    int gcnt = 0;
    for (int j = 0; j < i; j++) gcnt += sel[j];
    if (sel[i]) g_gidx[nh * 1024 + c * TOPK + gcnt] = c * SELC + i;
    else        g_lidx[nh * 3072 + c * (SELC - TOPK) + (i - gcnt)] = c * SELC + i;
}

// ---------------------------------------------------------------------------
// Local pass: 128 queries/block; thread = (4q x 16d); 128 threads.
// Double-buffered cp.async gather of K/V tiles. Writes ctx_l and lse_l.
// Dynamic smem:
//   [0, 16384)      stage0: K 8KB | V 8KB
//   [16384, 32768)  stage1
//   [32768, 49152)  sc[32][128]
//   [49152, 50304)  toks[288]
//   [50304, 51456)  am[288]
// ---------------------------------------------------------------------------
#define AL_SMEM 51456

__global__ __launch_bounds__(128) void attn_local(const float* __restrict__ mask)
{
    extern __shared__ char smc[];
    uint32_t sbase;
    asm("{ .reg .u64 t; cvta.to.shared.u64 t, %1; cvt.u32.u64 %0, t; }"
        : "=r"(sbase) : "l"(smc));
    float* scp = (float*)(smc + 32768);
    int*   toks_s = (int*)(smc + 49152);
    float* am_s   = (float*)(smc + 50304);

    int qb = blockIdx.x;
    int h  = blockIdx.y, n = blockIdx.z;
    int nh = n * NHD + h;

    int tid = threadIdx.x;
    int qg = tid >> 2, dg = tid & 3;        // 32 qg x 4 dg
    int qt = qb * LOCC + qg * 4;
    int db = dg * 16;

    // prologue: all 288 window token indices + masks
    int base = qb * 96 - 96;
    for (int idx = tid; idx < 288; idx += 128) {
        int gs = base + idx;
        int tok = (gs >= 0 && gs < 3072) ? g_lidx[nh * 3072 + gs] : -1;
        toks_s[idx] = tok;
        am_s[idx] = (tok >= 0) ? mask[n * TT + tok] : -1e30f;
    }

    float qreg[4][16];
    #pragma unroll
    for (int j = 0; j < 4; j++) {
        const float* qp = &g_q[((size_t)nh * TT + qt + j) * DH + db];
        #pragma unroll
        for (int d = 0; d < 16; d += 4) {
            float4 t4 = *(const float4*)(qp + d);
            qreg[j][d] = t4.x; qreg[j][d+1] = t4.y; qreg[j][d+2] = t4.z; qreg[j][d+3] = t4.w;
        }
    }
    __syncthreads();

    // cp.async gather: 128 threads x 128B = one 16KB tile
    const int grow = tid >> 1;          // 0..63: 0-31 K rows, 32-63 V rows
    const int gslot = grow & 31;
    const int gisV = grow >> 5;
    const int ghalf = tid & 1;          // which 128B half-row
    auto issue_tile = [&](int tile, int stg) {
        int tok = toks_s[tile * 32 + gslot];
        if (tok < 0) tok = 0;           // masked slots get weight 0 anyway
        const float* src = (gisV ? g_v : g_k) + ((size_t)nh * TT + tok) * DH + ghalf * 32;
        uint32_t dst = sbase + stg * 16384 + gisV * 8192 + gslot * 256 + ghalf * 128;
        #pragma unroll
        for (int kk = 0; kk < 8; kk++) cp16(dst + kk * 16, src + kk * 4);
    };

    float acc[4][16];
    float m[4], l[4];
    #pragma unroll
    for (int j = 0; j < 4; j++) {
        m[j] = -1e30f; l[j] = 0.f;
        #pragma unroll
        for (int d = 0; d < 16; d++) acc[j][d] = 0.f;
    }

    issue_tile(0, 0); CP_COMMIT();

    for (int ti = 0; ti < 9; ti++) {
        if (ti + 1 < 9) { issue_tile(ti + 1, (ti + 1) & 1); CP_COMMIT(); CP_WAIT1(); }
        else            { CP_WAIT0(); }
        __syncthreads();

        const char* kb = smc + (ti & 1) * 16384;
        const char* vb = kb + 8192;
        const float* amt = am_s + ti * 32;

        float tmax[4] = {-1e30f, -1e30f, -1e30f, -1e30f};
        for (int s = 0; s < 32; s++) {
            const char* kr = kb + s * 256 + db * 4;
            float4 k0 = *(const float4*)(kr);
            float4 k1 = *(const float4*)(kr + 16);
            float4 k2 = *(const float4*)(kr + 32);
            float4 k3 = *(const float4*)(kr + 48);
            float p[4];
            #pragma unroll
            for (int j = 0; j < 4; j++) p[j] = dot16(qreg[j], k0, k1, k2, k3);
            #pragma unroll
            for (int j = 0; j < 4; j++) {
                p[j] += __shfl_xor_sync(0xffffffffu, p[j], 1);
                p[j] += __shfl_xor_sync(0xffffffffu, p[j], 2);
            }
            float a = amt[s];
            float4 vv;
            #pragma unroll
            for (int j = 0; j < 4; j++) {
                float vj = (a > -1e29f) ? p[j] * 0.125f + a : -1e30f;
                (&vv.x)[j] = vj;
                tmax[j] = fmaxf(tmax[j], vj);
            }
            if (dg == 0) *(float4*)&scp[s * 128 + qg * 4] = vv;
        }
        __syncwarp();

        if (tmax[0] > -1e29f || tmax[1] > -1e29f) {
            #pragma unroll
            for (int j = 0; j < 4; j++) {
                float nm = fmaxf(m[j], tmax[j]);
                float scl = __expf(m[j] - nm);
                l[j] *= scl;
                #pragma unroll
                for (int d = 0; d < 16; d++) acc[j][d] *= scl;
                m[j] = nm;
            }
            for (int s = 0; s < 32; s++) {
                float4 pv = *(const float4*)&scp[s * 128 + qg * 4];
                float p[4];
                #pragma unroll
                for (int j = 0; j < 4; j++) {
                    float vj = (&pv.x)[j];
                    p[j] = (vj > -1e29f) ? __expf(vj - m[j]) : 0.f;
                    l[j] += p[j];
                }
                const char* vr = vb + s * 256 + db * 4;
                float4 v0 = *(const float4*)(vr);
                float4 v1 = *(const float4*)(vr + 16);
                float4 v2 = *(const float4*)(vr + 32);
                float4 v3 = *(const float4*)(vr + 48);
                #pragma unroll
                for (int j = 0; j < 4; j++) {
                    acc[j][0]  += p[j]*v0.x; acc[j][1]  += p[j]*v0.y; acc[j][2]  += p[j]*v0.z; acc[j][3]  += p[j]*v0.w;
                    acc[j][4]  += p[j]*v1.x; acc[j][5]  += p[j]*v1.y; acc[j][6]  += p[j]*v1.z; acc[j][7]  += p[j]*v1.w;
                    acc[j][8]  += p[j]*v2.x; acc[j][9]  += p[j]*v2.y; acc[j][10] += p[j]*v2.z; acc[j][11] += p[j]*v2.w;
                    acc[j][12] += p[j]*v3.x; acc[j][13] += p[j]*v3.y; acc[j][14] += p[j]*v3.z; acc[j][15] += p[j]*v3.w;
                }
            }
        }
        __syncthreads();
    }

    // appended global key (token 0, additive mask 0)
    {
        const float* k0p = &g_k[(size_t)nh * TT * DH + db];
        const float* v0p = &g_v[(size_t)nh * TT * DH + db];
        float4 k0 = *(const float4*)(k0p);
        float4 k1 = *(const float4*)(k0p + 4);
        float4 k2 = *(const float4*)(k0p + 8);
        float4 k3 = *(const float4*)(k0p + 12);
        float v0r[16];
        #pragma unroll
        for (int d = 0; d < 16; d++) v0r[d] = v0p[d];
        float p[4];
        #pragma unroll
        for (int j = 0; j < 4; j++) p[j] = dot16(qreg[j], k0, k1, k2, k3);
        #pragma unroll
        for (int j = 0; j < 4; j++) {
            p[j] += __shfl_xor_sync(0xffffffffu, p[j], 1);
            p[j] += __shfl_xor_sync(0xffffffffu, p[j], 2);
        }
        #pragma unroll
        for (int j = 0; j < 4; j++) {
            float s = p[j] * 0.125f;
            float nm = fmaxf(m[j], s);
            float scl = __expf(m[j] - nm);
            float pe = __expf(s - nm);
            l[j] = l[j] * scl + pe;
            #pragma unroll
            for (int d = 0; d < 16; d++) acc[j][d] = acc[j][d] * scl + pe * v0r[d];
            m[j] = nm;
        }
    }

    // store local context + lse
    #pragma unroll
    for (int j = 0; j < 4; j++) {
        float invl = 1.f / l[j];
        float* cl = &g_ctxl[((size_t)nh * TT + qt + j) * DH + db];
        #pragma unroll
        for (int d = 0; d < 16; d += 4) {
            float4 o;
            o.x = acc[j][d] * invl; o.y = acc[j][d+1] * invl;
            o.z = acc[j][d+2] * invl; o.w = acc[j][d+3] * invl;
            *(float4*)(cl + d) = o;
        }
        if (dg == 0) g_lsel[nh * TT + qt + j] = m[j] + __logf(l[j]);
    }
}

// ---------------------------------------------------------------------------
// Global pass + MERGE: 64 queries/block; thread = (4q x 16d); 64 threads.
// ---------------------------------------------------------------------------
__global__ __launch_bounds__(64) void attn_global(const float* __restrict__ mask,
                                                  float* __restrict__ out)
{
    int qb = blockIdx.x;
    int h  = blockIdx.y, n = blockIdx.z;
    int nh = n * NHD + h;
    __shared__ float ks[48][DH];
    __shared__ float vs[48][DH];
    __shared__ float am[48];
    __shared__ float sc[48][SELC];
    int tid = threadIdx.x;
    int qg = tid >> 2, dg = tid & 3;        // 16 qg x 4 dg
    int qt = qb * SELC + qg * 4;
    int db = dg * 16;

    for (int idx = tid; idx < 48 * DH; idx += 64) {
        int s = idx >> 6, d = idx & 63;
        int gs = qb * 16 - 16 + s;
        if (gs >= 0 && gs < 1024) {
            int tok = g_gidx[nh * 1024 + gs];
            ks[s][d] = g_k[((size_t)nh * TT + tok) * DH + d];
            vs[s][d] = g_v[((size_t)nh * TT + tok) * DH + d];
            if (d == 0) am[s] = mask[n * TT + tok];
        } else {
            ks[s][d] = 0.f; vs[s][d] = 0.f;
            if (d == 0) am[s] = -1e30f;
        }
    }
    __syncthreads();

    float qreg[4][16];
    #pragma unroll
    for (int j = 0; j < 4; j++) {
        const float* qp = &g_q[((size_t)nh * TT + qt + j) * DH + db];
        #pragma unroll
        for (int d = 0; d < 16; d += 4) {
            float4 t4 = *(const float4*)(qp + d);
            qreg[j][d] = t4.x; qreg[j][d+1] = t4.y; qreg[j][d+2] = t4.z; qreg[j][d+3] = t4.w;
        }
    }

    float tmax[4] = {-1e30f, -1e30f, -1e30f, -1e30f};
    for (int s = 0; s < 48; s++) {
        float4 k0 = *(const float4*)&ks[s][db];
        float4 k1 = *(const float4*)&ks[s][db + 4];
        float4 k2 = *(const float4*)&ks[s][db + 8];
        float4 k3 = *(const float4*)&ks[s][db + 12];
        float p[4];
        #pragma unroll
        for (int j = 0; j < 4; j++) p[j] = dot16(qreg[j], k0, k1, k2, k3);
        #pragma unroll
        for (int j = 0; j < 4; j++) {
            p[j] += __shfl_xor_sync(0xffffffffu, p[j], 1);
            p[j] += __shfl_xor_sync(0xffffffffu, p[j], 2);
        }
        float a = am[s];
        float4 vv;
        #pragma unroll
        for (int j = 0; j < 4; j++) {
            float vj = (a > -1e29f) ? p[j] * 0.125f + a : -1e30f;
            (&vv.x)[j] = vj;
            tmax[j] = fmaxf(tmax[j], vj);
        }
        if (dg == 0) *(float4*)&sc[s][qg * 4] = vv;
    }
    __syncwarp();

    float l[4] = {0.f, 0.f, 0.f, 0.f};
    float acc[4][16];
    #pragma unroll
    for (int j = 0; j < 4; j++)
        #pragma unroll
        for (int d = 0; d < 16; d++) acc[j][d] = 0.f;

    for (int s = 0; s < 48; s++) {
        float4 pv = *(const float4*)&sc[s][qg * 4];
        float p[4];
        #pragma unroll
        for (int j = 0; j < 4; j++) {
            float vj = (&pv.x)[j];
            p[j] = (vj > -1e29f) ? __expf(vj - tmax[j]) : 0.f;
            l[j] += p[j];
        }
        float4 v0 = *(const float4*)&vs[s][db];
        float4 v1 = *(const float4*)&vs[s][db + 4];
        float4 v2 = *(const float4*)&vs[s][db + 8];
        float4 v3 = *(const float4*)&vs[s][db + 12];
        #pragma unroll
        for (int j = 0; j < 4; j++) {
            acc[j][0]  += p[j]*v0.x; acc[j][1]  += p[j]*v0.y; acc[j][2]  += p[j]*v0.z; acc[j][3]  += p[j]*v0.w;
            acc[j][4]  += p[j]*v1.x; acc[j][5]  += p[j]*v1.y; acc[j][6]  += p[j]*v1.z; acc[j][7]  += p[j]*v1.w;
            acc[j][8]  += p[j]*v2.x; acc[j][9]  += p[j]*v2.y; acc[j][10] += p[j]*v2.z; acc[j][11] += p[j]*v2.w;
            acc[j][12] += p[j]*v3.x; acc[j][13] += p[j]*v3.y; acc[j][14] += p[j]*v3.z; acc[j][15] += p[j]*v3.w;
        }
    }

    // merge with local pass, write final output
    #pragma unroll
    for (int j = 0; j < 4; j++) {
        float lseg = tmax[j] + __logf(l[j]);
        float lsel = g_lsel[nh * TT + qt + j];
        float pmix = 1.f / (1.f + __expf(lseg - lsel));
        float invg = 1.f / l[j];
        const float* cl = &g_ctxl[((size_t)nh * TT + qt + j) * DH + db];
        float* op = &out[((size_t)n * TT + qt + j) * HID + h * DH + db];
        #pragma unroll
        for (int d = 0; d < 16; d += 4) {
            float4 clv = *(const float4*)(cl + d);
            float4 o;
            float g0 = acc[j][d]   * invg;
            float g1 = acc[j][d+1] * invg;
            float g2 = acc[j][d+2] * invg;
            float g3 = acc[j][d+3] * invg;
            o.x = g0 + pmix * (clv.x - g0);
            o.y = g1 + pmix * (clv.y - g1);
            o.z = g2 + pmix * (clv.z - g2);
            o.w = g3 + pmix * (clv.w - g3);
            *(float4*)(op + d) = o;
        }
    }
}

// ---------------------------------------------------------------------------
// BOS: token-0 query, full UNscaled attention over all 4096 keys + mask.
// ---------------------------------------------------------------------------
__global__ __launch_bounds__(512) void attn_bos(const float* __restrict__ mask,
                                                float* __restrict__ out)
{
    int h = blockIdx.x, n = blockIdx.y;
    int nh = n * NHD + h;
    __shared__ float sc[TT];
    __shared__ float q0s[DH];
    __shared__ float red[512];
    __shared__ float part[8][DH];
    int tid = threadIdx.x;
    if (tid < DH) q0s[tid] = g_q[(size_t)nh * TT * DH + tid];
    __syncthreads();

    float lmax = -1e30f;
    for (int t = tid; t < TT; t += 512) {
        const float* kp = &g_k[((size_t)nh * TT + t) * DH];
        float dot = 0.f;
        #pragma unroll
        for (int d = 0; d < DH; d += 4) {
            float4 kv = *(const float4*)&kp[d];
            dot += q0s[d]*kv.x + q0s[d+1]*kv.y + q0s[d+2]*kv.z + q0s[d+3]*kv.w;
        }
        float s = dot + mask[n * TT + t];
        sc[t] = s;
        lmax = fmaxf(lmax, s);
    }
    red[tid] = lmax; __syncthreads();
    for (int o = 256; o > 0; o >>= 1) {
        if (tid < o) red[tid] = fmaxf(red[tid], red[tid + o]);
        __syncthreads();
    }
    float mx = red[0]; __syncthreads();

    float ls = 0.f;
    for (int t = tid; t < TT; t += 512) {
        float p = expf(sc[t] - mx);
        sc[t] = p;
        ls += p;
    }
    red[tid] = ls; __syncthreads();
    for (int o = 256; o > 0; o >>= 1) {
        if (tid < o) red[tid] += red[tid + o];
        __syncthreads();
    }
    float inv = 1.f / red[0];
    __syncthreads();

    {
        int d = tid & 63, sl = tid >> 6;
        float a = 0.f;
        int tstart = sl * 512;
        for (int t = tstart; t < tstart + 512; t++)
            a += sc[t] * g_v[((size_t)nh * TT + t) * DH + d];
        part[sl][d] = a;
    }
    __syncthreads();
    if (tid < DH) {
        float a = 0.f;
        #pragma unroll
        for (int sl = 0; sl < 8; sl++) a += part[sl][tid];
        out[(size_t)n * TT * HID + h * DH + tid] = a * inv;
    }
}

// ---------------------------------------------------------------------------
extern "C" void kernel_launch(void* const* d_in, const int* in_sizes, int n_in,
                              void* d_out, int out_size)
{
    const float* hs   = (const float*)d_in[0];
    const float* mask = (const float*)d_in[1];
    const float* Wq   = (const float*)d_in[2];
    const float* bq   = (const float*)d_in[3];
    const float* Wk   = (const float*)d_in[4];
    const float* bk   = (const float*)d_in[5];
    const float* Wv   = (const float*)d_in[6];
    const float* bv   = (const float*)d_in[7];
    float* out = (float*)d_out;

    static int attr_done = 0;
    if (!attr_done) {
        cudaFuncSetAttribute(gemm_f16, cudaFuncAttributeMaxDynamicSharedMemorySize,
                             GEMM_SMEM);
        cudaFuncSetAttribute(attn_local, cudaFuncAttributeMaxDynamicSharedMemorySize,
                             AL_SMEM);
        attr_done = 1;
    }

    // 1: fused split  2: gemm  3: select  4: attn_local (ncu target)
    // 5: attn_global+merge  6: bos
    split_all<<<(NA4 + 3 * NW4) / 256, 256>>>(hs, Wq, Wk, Wv);
    gemm_f16<<<dim3(8, 64, 3), 256, GEMM_SMEM>>>(bq, bk, bv);
    select_norm<<<NB * NHD * 64, 64>>>(bq, mask);
    attn_local<<<dim3(32, NHD, NB), 128, AL_SMEM>>>(mask);
    attn_global<<<dim3(64, NHD, NB), 64>>>(mask, out);
    attn_bos<<<dim3(NHD, NB), 512>>>(mask, out);
}